// round 2
// baseline (speedup 1.0000x reference)
#include <cuda_runtime.h>
#include <cstdint>

#define B_       2
#define S_       2048
#define DM       1024
#define H_       16
#define HD       64
#define BH_      (B_ * H_)
#define MTOT     (B_ * S_)          // 4096
#define NEGV     (-1000000000.0f)
#define L2E      1.4426950408889634f
#define SCALE_   0.125f             // 1/sqrt(64)

// ---------------- scratch (device globals; no allocation at runtime) ----------------
__device__ __align__(128) float  g_q[MTOT * DM];
__device__ __align__(128) float  g_k[MTOT * DM];
__device__ __align__(128) float  g_v[MTOT * DM];
__device__ __align__(128) float  g_o[MTOT * DM];
__device__ __align__(128) float  g_s[(size_t)BH_ * S_ * S_];   // 536.9 MB masked scaled scores
__device__ __align__(128) float2 g_rc[BH_ * S_];               // {max*log2e, 1/sum}

// FMA-only exp2 of t (t expected <= 0 by construction; clamped for safety).
// Magic-number round-to-nearest + degree-5 Taylor of 2^f on [-0.5, 0.5].
__device__ __forceinline__ float fexp2(float t) {
    t = fmaxf(fminf(t, 0.0f), -126.0f);
    float z  = t + 12582912.0f;                 // 1.5 * 2^23
    float fi = z - 12582912.0f;
    float f  = t - fi;
    int   ei = __float_as_int(z) - 0x4b400000;  // integer part of t
    float p  = 0.0013333558f;
    p = fmaf(p, f, 0.0096181291f);
    p = fmaf(p, f, 0.0555041087f);
    p = fmaf(p, f, 0.2402265070f);
    p = fmaf(p, f, 0.6931471806f);
    p = fmaf(p, f, 1.0f);
    return p * __int_as_float((ei + 127) << 23);
}

// ---------------- dense GEMM: C = relu(A[M,K] @ B[K,N] + bias) ----------------
// BM=128, BN=128, BK=16, 256 threads, 8x8 strided thread tile.
__global__ __launch_bounds__(256)
void gemm_relu(const float* __restrict__ A, const float* __restrict__ Bm,
               const float* __restrict__ bias, float* __restrict__ C,
               int M, int N, int K) {
    __shared__ float As[16][132];   // transposed A tile, padded (16B-aligned rows)
    __shared__ float Bs[16][128];
    const int tid = threadIdx.x;
    const int tx = tid & 15, ty = tid >> 4;
    const int m0 = blockIdx.y * 128, n0 = blockIdx.x * 128;

    float c[8][8];
#pragma unroll
    for (int i = 0; i < 8; i++)
#pragma unroll
        for (int j = 0; j < 8; j++) c[i][j] = 0.0f;

    for (int k0 = 0; k0 < K; k0 += 16) {
#pragma unroll
        for (int p = 0; p < 2; p++) {               // A tile: 128x16 -> As[k][m]
            int id = tid + p * 256;
            int r = id >> 2, c4 = (id & 3) * 4;
            float4 va = *(const float4*)&A[(size_t)(m0 + r) * K + k0 + c4];
            As[c4 + 0][r] = va.x; As[c4 + 1][r] = va.y;
            As[c4 + 2][r] = va.z; As[c4 + 3][r] = va.w;
        }
#pragma unroll
        for (int p = 0; p < 2; p++) {               // B tile: 16x128
            int id = tid + p * 256;
            int r = id >> 5, c4 = (id & 31) * 4;
            *(float4*)&Bs[r][c4] = *(const float4*)&Bm[(size_t)(k0 + r) * N + n0 + c4];
        }
        __syncthreads();
#pragma unroll
        for (int kk = 0; kk < 16; kk++) {
            float a[8], b[8];
            *(float4*)&a[0] = *(float4*)&As[kk][ty * 4];
            *(float4*)&a[4] = *(float4*)&As[kk][64 + ty * 4];
            *(float4*)&b[0] = *(float4*)&Bs[kk][tx * 4];
            *(float4*)&b[4] = *(float4*)&Bs[kk][64 + tx * 4];
#pragma unroll
            for (int i = 0; i < 8; i++)
#pragma unroll
                for (int j = 0; j < 8; j++) c[i][j] = fmaf(a[i], b[j], c[i][j]);
        }
        __syncthreads();
    }
#pragma unroll
    for (int ih = 0; ih < 2; ih++)
#pragma unroll
        for (int i = 0; i < 4; i++) {
            int row = m0 + ih * 64 + ty * 4 + i;
            int ci = ih * 4 + i;
#pragma unroll
            for (int jh = 0; jh < 2; jh++) {
                int col = n0 + jh * 64 + tx * 4;
                float4 ov;
                ov.x = fmaxf(c[ci][jh * 4 + 0] + bias[col + 0], 0.0f);
                ov.y = fmaxf(c[ci][jh * 4 + 1] + bias[col + 1], 0.0f);
                ov.z = fmaxf(c[ci][jh * 4 + 2] + bias[col + 2], 0.0f);
                ov.w = fmaxf(c[ci][jh * 4 + 3] + bias[col + 3], 0.0f);
                *(float4*)&C[(size_t)row * N + col] = ov;
            }
        }
}

// ---------------- scores: S[bh][s][t] = mask ? scale*dot(q_s, k_t) : -1e9 ----------------
// 128x128 tile over (s,t), K=64 (head dim). Dynamic smem: 2 * 64 * 132 floats.
#define SCORES_SMEM (2 * 64 * 132 * 4)
__global__ __launch_bounds__(256)
void scores_kernel(const float* __restrict__ q, const float* __restrict__ k,
                   const int* __restrict__ mask, float* __restrict__ sc) {
    extern __shared__ float sm[];
    float (*Qs)[132] = (float(*)[132])sm;               // [64][132] : Qs[e][s_local]
    float (*Ks)[132] = (float(*)[132])(sm + 64 * 132);  // [64][132] : Ks[e][t_local]
    const int tid = threadIdx.x;
    const int tx = tid & 15, ty = tid >> 4;
    const int bh = blockIdx.z, b = bh >> 4, h = bh & 15;
    const int t0 = blockIdx.x * 128, s0 = blockIdx.y * 128;
    const float* qb = q + (size_t)b * S_ * DM + h * HD;
    const float* kb = k + (size_t)b * S_ * DM + h * HD;

#pragma unroll
    for (int p = 0; p < 8; p++) {
        int id = tid + p * 256;               // 2048 float4 per tile
        int r = id >> 4, c4 = (id & 15) * 4;
        float4 vq = *(const float4*)&qb[(size_t)(s0 + r) * DM + c4];
        Qs[c4 + 0][r] = vq.x; Qs[c4 + 1][r] = vq.y;
        Qs[c4 + 2][r] = vq.z; Qs[c4 + 3][r] = vq.w;
        float4 vk = *(const float4*)&kb[(size_t)(t0 + r) * DM + c4];
        Ks[c4 + 0][r] = vk.x; Ks[c4 + 1][r] = vk.y;
        Ks[c4 + 2][r] = vk.z; Ks[c4 + 3][r] = vk.w;
    }
    __syncthreads();

    float c[8][8];
#pragma unroll
    for (int i = 0; i < 8; i++)
#pragma unroll
        for (int j = 0; j < 8; j++) c[i][j] = 0.0f;

#pragma unroll 8
    for (int e = 0; e < 64; e++) {
        float a[8], bb[8];
        *(float4*)&a[0]  = *(float4*)&Qs[e][ty * 4];
        *(float4*)&a[4]  = *(float4*)&Qs[e][64 + ty * 4];
        *(float4*)&bb[0] = *(float4*)&Ks[e][tx * 4];
        *(float4*)&bb[4] = *(float4*)&Ks[e][64 + tx * 4];
#pragma unroll
        for (int i = 0; i < 8; i++)
#pragma unroll
            for (int j = 0; j < 8; j++) c[i][j] = fmaf(a[i], bb[j], c[i][j]);
    }

    const int* mb = mask + (size_t)b * S_ * S_;
    float* sb = sc + (size_t)bh * S_ * S_;
#pragma unroll
    for (int ih = 0; ih < 2; ih++)
#pragma unroll
        for (int i = 0; i < 4; i++) {
            int row = s0 + ih * 64 + ty * 4 + i;
            int ci = ih * 4 + i;
#pragma unroll
            for (int jh = 0; jh < 2; jh++) {
                int col = t0 + jh * 64 + tx * 4;
                int4 mm = *(const int4*)&mb[(size_t)row * S_ + col];
                float4 ov;
                ov.x = (mm.x == 1) ? c[ci][jh * 4 + 0] * SCALE_ : NEGV;
                ov.y = (mm.y == 1) ? c[ci][jh * 4 + 1] * SCALE_ : NEGV;
                ov.z = (mm.z == 1) ? c[ci][jh * 4 + 2] * SCALE_ : NEGV;
                ov.w = (mm.w == 1) ? c[ci][jh * 4 + 3] * SCALE_ : NEGV;
                *(float4*)&sb[(size_t)row * S_ + col] = ov;
            }
        }
}

// ---------------- row reduce: per row, max and 1/sum(exp) ----------------
__global__ __launch_bounds__(128)
void rowred_kernel(const float* __restrict__ sc, float2* __restrict__ rc) {
    const int row = blockIdx.x, bh = blockIdx.y;
    const float* p = sc + ((size_t)bh * S_ + row) * S_;
    const int tid = threadIdx.x;   // 128
    float4 vv[4];
    float mx = -3.0e38f;
#pragma unroll
    for (int i = 0; i < 4; i++) {
        vv[i] = *(const float4*)&p[(tid + i * 128) * 4];
        mx = fmaxf(mx, fmaxf(fmaxf(vv[i].x, vv[i].y), fmaxf(vv[i].z, vv[i].w)));
    }
#pragma unroll
    for (int off = 16; off > 0; off >>= 1)
        mx = fmaxf(mx, __shfl_xor_sync(0xffffffffu, mx, off));
    __shared__ float smx[4], ssum[4];
    if ((tid & 31) == 0) smx[tid >> 5] = mx;
    __syncthreads();
    mx = fmaxf(fmaxf(smx[0], smx[1]), fmaxf(smx[2], smx[3]));
    const float mx2 = mx * L2E;
    float s = 0.0f;
#pragma unroll
    for (int i = 0; i < 4; i++) {
        s += fexp2(fmaf(vv[i].x, L2E, -mx2));
        s += fexp2(fmaf(vv[i].y, L2E, -mx2));
        s += fexp2(fmaf(vv[i].z, L2E, -mx2));
        s += fexp2(fmaf(vv[i].w, L2E, -mx2));
    }
#pragma unroll
    for (int off = 16; off > 0; off >>= 1)
        s += __shfl_xor_sync(0xffffffffu, s, off);
    if ((tid & 31) == 0) ssum[tid >> 5] = s;
    __syncthreads();
    if (tid == 0) {
        float tot = ssum[0] + ssum[1] + ssum[2] + ssum[3];
        rc[(size_t)bh * S_ + row] = make_float2(mx2, 1.0f / tot);
    }
}

// ---------------- PV GEMM with fused softmax on A-load ----------------
// Per (bh, m-tile): O[128,64] = softmax(S[128,2048]) @ V[2048,64]
// BM=128, BN=64, BK=16, 128 threads, 8x8 strided thread tile.
__global__ __launch_bounds__(128)
void attnv_kernel(const float* __restrict__ sc, const float2* __restrict__ rc,
                  const float* __restrict__ v, float* __restrict__ o) {
    __shared__ float As[16][132];
    __shared__ float Bs[16][64];
    __shared__ float2 rcs[128];
    const int tid = threadIdx.x;   // 128
    const int tx = tid & 7, ty = tid >> 3;
    const int bh = blockIdx.z, b = bh >> 4, h = bh & 15;
    const int m0 = blockIdx.x * 128;
    const float* sb = sc + (size_t)bh * S_ * S_;
    const float* vb = v + (size_t)b * S_ * DM + h * HD;

    rcs[tid] = rc[(size_t)bh * S_ + m0 + tid];
    __syncthreads();

    float c[8][8];
#pragma unroll
    for (int i = 0; i < 8; i++)
#pragma unroll
        for (int j = 0; j < 8; j++) c[i][j] = 0.0f;

    for (int k0 = 0; k0 < S_; k0 += 16) {
#pragma unroll
        for (int p = 0; p < 4; p++) {            // A tile 128x16 with exp transform
            int id = tid + p * 128;
            int r = id >> 2, c4 = (id & 3) * 4;
            float4 sv = *(const float4*)&sb[(size_t)(m0 + r) * S_ + k0 + c4];
            float2 rr = rcs[r];
            As[c4 + 0][r] = fexp2(fmaf(sv.x, L2E, -rr.x)) * rr.y;
            As[c4 + 1][r] = fexp2(fmaf(sv.y, L2E, -rr.x)) * rr.y;
            As[c4 + 2][r] = fexp2(fmaf(sv.z, L2E, -rr.x)) * rr.y;
            As[c4 + 3][r] = fexp2(fmaf(sv.w, L2E, -rr.x)) * rr.y;
        }
#pragma unroll
        for (int p = 0; p < 2; p++) {            // V tile 16x64
            int id = tid + p * 128;
            int r = id >> 4, c4 = (id & 15) * 4;
            *(float4*)&Bs[r][c4] = *(const float4*)&vb[(size_t)(k0 + r) * DM + c4];
        }
        __syncthreads();
#pragma unroll
        for (int kk = 0; kk < 16; kk++) {
            float a[8], bb[8];
            *(float4*)&a[0]  = *(float4*)&As[kk][ty * 4];
            *(float4*)&a[4]  = *(float4*)&As[kk][64 + ty * 4];
            *(float4*)&bb[0] = *(float4*)&Bs[kk][tx * 4];
            *(float4*)&bb[4] = *(float4*)&Bs[kk][32 + tx * 4];
#pragma unroll
            for (int i = 0; i < 8; i++)
#pragma unroll
                for (int j = 0; j < 8; j++) c[i][j] = fmaf(a[i], bb[j], c[i][j]);
        }
        __syncthreads();
    }

    // o layout [B,H,S,64] contiguous == the reference's no-transpose reshape
#pragma unroll
    for (int ih = 0; ih < 2; ih++)
#pragma unroll
        for (int i = 0; i < 4; i++) {
            int row = m0 + ih * 64 + ty * 4 + i;
            int ci = ih * 4 + i;
            float* ob = o + ((size_t)bh * S_ + row) * HD;
            *(float4*)&ob[tx * 4]      = make_float4(c[ci][0], c[ci][1], c[ci][2], c[ci][3]);
            *(float4*)&ob[32 + tx * 4] = make_float4(c[ci][4], c[ci][5], c[ci][6], c[ci][7]);
        }
}

// ---------------- launch ----------------
extern "C" void kernel_launch(void* const* d_in, const int* in_sizes, int n_in,
                              void* d_out, int out_size) {
    (void)in_sizes; (void)n_in; (void)out_size;
    const float* x    = (const float*)d_in[0];
    const int*   mask = (const int*)d_in[1];
    const float* W0   = (const float*)d_in[2];
    const float* b0   = (const float*)d_in[3];
    const float* W1   = (const float*)d_in[4];
    const float* b1   = (const float*)d_in[5];
    const float* W2   = (const float*)d_in[6];
    const float* b2   = (const float*)d_in[7];
    const float* Wo   = (const float*)d_in[8];
    const float* bo   = (const float*)d_in[9];
    float* out = (float*)d_out;

    float *q, *k, *v, *o, *sc; float2* rc;
    cudaGetSymbolAddress((void**)&q,  g_q);
    cudaGetSymbolAddress((void**)&k,  g_k);
    cudaGetSymbolAddress((void**)&v,  g_v);
    cudaGetSymbolAddress((void**)&o,  g_o);
    cudaGetSymbolAddress((void**)&sc, g_s);
    cudaGetSymbolAddress((void**)&rc, g_rc);

    cudaFuncSetAttribute(scores_kernel,
                         cudaFuncAttributeMaxDynamicSharedMemorySize, SCORES_SMEM);

    gemm_relu<<<dim3(8, 32), 256>>>(x, W0, b0, q, MTOT, DM, DM);
    gemm_relu<<<dim3(8, 32), 256>>>(q, W1, b1, k, MTOT, DM, DM);
    gemm_relu<<<dim3(8, 32), 256>>>(q, W2, b2, v, MTOT, DM, DM);
    scores_kernel<<<dim3(16, 16, 32), 256, SCORES_SMEM>>>(q, k, mask, sc);
    rowred_kernel<<<dim3(2048, 32), 128>>>(sc, rc);
    attnv_kernel<<<dim3(16, 1, 32), 128>>>(sc, rc, v, o);
    gemm_relu<<<dim3(8, 32), 256>>>(o, Wo, bo, out, MTOT, DM, DM);
}

// round 4
// speedup vs baseline: 1.4445x; 1.4445x over previous
#include <cuda_runtime.h>
#include <cstdint>

#define B_       2
#define S_       2048
#define DM       1024
#define H_       16
#define HD       64
#define BH_      32
#define MTOT     4096
#define L2E      1.4426950408889634f
#define SCALE_   0.125f
#define KP       20                  // padded smem row length (floats)

// ---------------- scratch (device globals) ----------------
__device__ __align__(128) float g_q [MTOT * DM];
__device__ __align__(128) float g_k [MTOT * DM];
__device__ __align__(128) float g_vt[BH_ * HD * S_];            // V^T per head: [bh][e][t]
__device__ __align__(128) float g_o [MTOT * DM];                // attn out, [bh][t][e] == [4096][1024]
__device__ __align__(128) float g_wt[4][DM * DM];               // W^T: [n][k]
__device__ __align__(128) float g_e [(size_t)BH_ * S_ * S_];    // exp(masked logits)
__device__ __align__(128) float g_rs[BH_ * S_];                 // row sums of E

// ---------------- helpers ----------------
__device__ __forceinline__ uint32_t smem_u32(const void* p) {
    uint32_t r;
    asm("{ .reg .u64 t; cvta.to.shared.u64 t, %1; cvt.u32.u64 %0, t; }" : "=r"(r) : "l"(p));
    return r;
}
__device__ __forceinline__ uint32_t tf32r(float x) {           // round-to-nearest tf32
    uint32_t u; asm("cvt.rna.tf32.f32 %0, %1;" : "=r"(u) : "f"(x)); return u;
}
__device__ __forceinline__ void cp16(uint32_t d, const void* s) {
    asm volatile("cp.async.ca.shared.global [%0], [%1], 16;" :: "r"(d), "l"(s));
}
#define CPC()  asm volatile("cp.async.commit_group;")
#define CPW1() asm volatile("cp.async.wait_group 1;")
#define CPW0() asm volatile("cp.async.wait_group 0;")

__device__ __forceinline__ void mma_t(float* d, const uint32_t* a, const uint32_t* b) {
    asm volatile("mma.sync.aligned.m16n8k8.row.col.f32.tf32.tf32.f32 "
                 "{%0,%1,%2,%3},{%4,%5,%6,%7},{%8,%9},{%0,%1,%2,%3};"
                 : "+f"(d[0]), "+f"(d[1]), "+f"(d[2]), "+f"(d[3])
                 : "r"(a[0]), "r"(a[1]), "r"(a[2]), "r"(a[3]), "r"(b[0]), "r"(b[1]));
}

// FMA-only exp2; valid t in [-126, 80]
__device__ __forceinline__ float fexp2(float t) {
    t = fminf(fmaxf(t, -126.0f), 80.0f);
    float z  = t + 12582912.0f;
    float fi = z - 12582912.0f;
    float f  = t - fi;
    int   ei = __float_as_int(z) - 0x4b400000;
    float p  = 0.0013333558f;
    p = fmaf(p, f, 0.0096181291f);
    p = fmaf(p, f, 0.0555041087f);
    p = fmaf(p, f, 0.2402265070f);
    p = fmaf(p, f, 0.6931471806f);
    p = fmaf(p, f, 1.0f);
    return p * __int_as_float((ei + 127) << 23);
}

// Stage a [ROWS x 16] f32 tile (row-major, leading dim ld) into smem [ROWS][KP] via cp.async.
template<int ROWS>
__device__ __forceinline__ void stage(uint32_t sb, const float* __restrict__ g, int ld, int tid) {
#pragma unroll
    for (int p = 0; p < ROWS / 64; p++) {
        int id = tid + p * 256;
        int r = id >> 2, s = id & 3;
        cp16(sb + (uint32_t)(r * KP + s * 4) * 4u, g + (size_t)r * ld + s * 4);
    }
}

// One k8 step of a warp tile [MF*16 x 32] (NF=4). SPLIT=1: plain tf32; SPLIT=3: hi/lo split.
// ar0 = warp_m_base + (lane>>2); bn0 = warp_n_base + (lane>>2); c0 = k8base + (lane&3).
template<int SPLIT, int MF>
__device__ __forceinline__ void wstep(const float* __restrict__ As, const float* __restrict__ Bs,
                                      int ar0, int bn0, int c0, float (*acc)[4][4]) {
    uint32_t ah[MF][4], al[MF][4];
#pragma unroll
    for (int i = 0; i < MF; i++) {
        int r = ar0 + i * 16;
        float raw[4] = { As[r * KP + c0], As[(r + 8) * KP + c0],
                         As[r * KP + c0 + 4], As[(r + 8) * KP + c0 + 4] };
#pragma unroll
        for (int e = 0; e < 4; e++) {
            ah[i][e] = tf32r(raw[e]);
            if (SPLIT > 1) al[i][e] = tf32r(raw[e] - __uint_as_float(ah[i][e]));
        }
    }
#pragma unroll
    for (int j = 0; j < 4; j++) {
        int rn = bn0 + j * 8;
        float b0f = Bs[rn * KP + c0], b1f = Bs[rn * KP + c0 + 4];
        uint32_t bh2[2] = { tf32r(b0f), tf32r(b1f) };
        uint32_t bl2[2];
        if (SPLIT > 1) {
            bl2[0] = tf32r(b0f - __uint_as_float(bh2[0]));
            bl2[1] = tf32r(b1f - __uint_as_float(bh2[1]));
        }
#pragma unroll
        for (int i = 0; i < MF; i++) {
            if (SPLIT > 1) {
                mma_t(acc[i][j], al[i], bh2);
                mma_t(acc[i][j], ah[i], bl2);
            }
            mma_t(acc[i][j], ah[i], bh2);
        }
    }
}

// ---------------- dense: C = relu(A[M,1024] @ W + bias), 3xTF32, tile 128x128 ----------------
// MODE 0: C row-major [m][1024].  MODE 1: write V^T per head: vt[(b*16+h)*64+e][t].
template<int MODE>
__global__ __launch_bounds__(256)
void gemm_mma(const float* __restrict__ A, const float* __restrict__ Bt,
              const float* __restrict__ bias, float* __restrict__ C) {
    __shared__ float As[2][128 * KP], Bs[2][128 * KP];
    const int tid = threadIdx.x, lane = tid & 31, wid = tid >> 5;
    const int wm = wid & 1, wn = wid >> 1;
    const int m0 = blockIdx.y * 128, n0 = blockIdx.x * 128;
    const uint32_t sA[2] = { smem_u32(As[0]), smem_u32(As[1]) };
    const uint32_t sB[2] = { smem_u32(Bs[0]), smem_u32(Bs[1]) };
    float acc[4][4][4];
#pragma unroll
    for (int i = 0; i < 4; i++)
#pragma unroll
        for (int j = 0; j < 4; j++)
#pragma unroll
            for (int e = 0; e < 4; e++) acc[i][j][e] = 0.0f;

    const float* Ag = A  + (size_t)m0 * DM;
    const float* Bg = Bt + (size_t)n0 * DM;
    const int NT = DM / 16;   // 64
    stage<128>(sA[0], Ag, DM, tid); stage<128>(sB[0], Bg, DM, tid); CPC();
    stage<128>(sA[1], Ag + 16, DM, tid); stage<128>(sB[1], Bg + 16, DM, tid); CPC();

    const int ar0 = wm * 64 + (lane >> 2);
    const int bn0 = wn * 32 + (lane >> 2);
    const int c00 = lane & 3;
    for (int i = 0; i < NT; i++) {
        int s = i & 1;
        if (i >= NT - 2) { CPW0(); } else { CPW1(); }
        __syncthreads();
        wstep<3, 4>(As[s], Bs[s], ar0, bn0, c00, acc);
        wstep<3, 4>(As[s], Bs[s], ar0, bn0, c00 + 8, acc);
        __syncthreads();
        if (i + 2 < NT) {
            stage<128>(sA[s], Ag + (i + 2) * 16, DM, tid);
            stage<128>(sB[s], Bg + (i + 2) * 16, DM, tid);
            CPC();
        }
    }
#pragma unroll
    for (int i = 0; i < 4; i++)
#pragma unroll
        for (int j = 0; j < 4; j++) {
            int m = m0 + wm * 64 + i * 16 + (lane >> 2);
            int n = n0 + wn * 32 + j * 8 + (lane & 3) * 2;
            float bz0 = bias[n], bz1 = bias[n + 1];
            float v00 = fmaxf(acc[i][j][0] + bz0, 0.0f), v01 = fmaxf(acc[i][j][1] + bz1, 0.0f);
            float v10 = fmaxf(acc[i][j][2] + bz0, 0.0f), v11 = fmaxf(acc[i][j][3] + bz1, 0.0f);
            if (MODE == 0) {
                *(float2*)&C[(size_t)m * DM + n]       = make_float2(v00, v01);
                *(float2*)&C[(size_t)(m + 8) * DM + n] = make_float2(v10, v11);
            } else {
                int b = m >> 11, t = m & 2047, h = n >> 6, e = n & 63;
                size_t base = ((size_t)(b * 16 + h) * 64 + e) * S_;
                C[base + t]            = v00;
                C[base + S_ + t]       = v01;    // e+1
                C[base + t + 8]        = v10;
                C[base + S_ + t + 8]   = v11;
            }
        }
}

// ---------------- scores: E = mask ? exp(scale*q.k) : 0 ; rowsums via atomics ----------------
__global__ __launch_bounds__(256)
void scores_mma(const float* __restrict__ q, const float* __restrict__ kk,
                const int* __restrict__ mask, float* __restrict__ E, float* __restrict__ rs) {
    __shared__ float As[2][128 * KP], Bs[2][128 * KP];
    const int tid = threadIdx.x, lane = tid & 31, wid = tid >> 5;
    const int wm = wid & 1, wn = wid >> 1;
    const int bh = blockIdx.z, b = bh >> 4, h = bh & 15;
    const int t0 = blockIdx.x * 128, s0 = blockIdx.y * 128;
    const uint32_t sA[2] = { smem_u32(As[0]), smem_u32(As[1]) };
    const uint32_t sB[2] = { smem_u32(Bs[0]), smem_u32(Bs[1]) };
    float acc[4][4][4];
#pragma unroll
    for (int i = 0; i < 4; i++)
#pragma unroll
        for (int j = 0; j < 4; j++)
#pragma unroll
            for (int e = 0; e < 4; e++) acc[i][j][e] = 0.0f;

    const float* Ag = q  + ((size_t)b * S_ + s0) * DM + h * HD;
    const float* Bg = kk + ((size_t)b * S_ + t0) * DM + h * HD;
    const int NT = HD / 16;   // 4
    stage<128>(sA[0], Ag, DM, tid); stage<128>(sB[0], Bg, DM, tid); CPC();
    stage<128>(sA[1], Ag + 16, DM, tid); stage<128>(sB[1], Bg + 16, DM, tid); CPC();

    const int ar0 = wm * 64 + (lane >> 2);
    const int bn0 = wn * 32 + (lane >> 2);
    const int c00 = lane & 3;
    for (int i = 0; i < NT; i++) {
        int s = i & 1;
        if (i >= NT - 2) { CPW0(); } else { CPW1(); }
        __syncthreads();
        wstep<1, 4>(As[s], Bs[s], ar0, bn0, c00, acc);
        wstep<1, 4>(As[s], Bs[s], ar0, bn0, c00 + 8, acc);
        __syncthreads();
        if (i + 2 < NT) {
            stage<128>(sA[s], Ag + (i + 2) * 16, DM, tid);
            stage<128>(sB[s], Bg + (i + 2) * 16, DM, tid);
            CPC();
        }
    }
    const float cf = SCALE_ * L2E;
    float rowacc[8];
#pragma unroll
    for (int i = 0; i < 8; i++) rowacc[i] = 0.0f;
#pragma unroll
    for (int i = 0; i < 4; i++)
#pragma unroll
        for (int j = 0; j < 4; j++) {
            int mrow = s0 + wm * 64 + i * 16 + (lane >> 2);
            int tcol = t0 + wn * 32 + j * 8 + (lane & 3) * 2;
            int2 mk0 = *(const int2*)&mask[((size_t)b * S_ + mrow) * S_ + tcol];
            int2 mk1 = *(const int2*)&mask[((size_t)b * S_ + mrow + 8) * S_ + tcol];
            float e00 = (mk0.x == 1) ? fexp2(acc[i][j][0] * cf) : 0.0f;
            float e01 = (mk0.y == 1) ? fexp2(acc[i][j][1] * cf) : 0.0f;
            float e10 = (mk1.x == 1) ? fexp2(acc[i][j][2] * cf) : 0.0f;
            float e11 = (mk1.y == 1) ? fexp2(acc[i][j][3] * cf) : 0.0f;
            *(float2*)&E[((size_t)bh * S_ + mrow) * S_ + tcol]     = make_float2(e00, e01);
            *(float2*)&E[((size_t)bh * S_ + mrow + 8) * S_ + tcol] = make_float2(e10, e11);
            rowacc[i * 2 + 0] += e00 + e01;
            rowacc[i * 2 + 1] += e10 + e11;
        }
#pragma unroll
    for (int i = 0; i < 4; i++) {
        int mrow = s0 + wm * 64 + i * 16 + (lane >> 2);
        atomicAdd(&rs[bh * S_ + mrow],     rowacc[i * 2 + 0]);
        atomicAdd(&rs[bh * S_ + mrow + 8], rowacc[i * 2 + 1]);
    }
}

// ---------------- attnv: O[bh] = (E @ V^T_rows) / rowsum ----------------
__global__ __launch_bounds__(256)
void attnv_mma(const float* __restrict__ E, const float* __restrict__ vt,
               const float* __restrict__ rs, float* __restrict__ O) {
    __shared__ float As[2][128 * KP], Bs[2][64 * KP];
    const int tid = threadIdx.x, lane = tid & 31, wid = tid >> 5;
    const int wm = wid & 3, wn = wid >> 2;
    const int bh = blockIdx.y, m0 = blockIdx.x * 128;
    const uint32_t sA[2] = { smem_u32(As[0]), smem_u32(As[1]) };
    const uint32_t sB[2] = { smem_u32(Bs[0]), smem_u32(Bs[1]) };
    float acc[2][4][4];
#pragma unroll
    for (int i = 0; i < 2; i++)
#pragma unroll
        for (int j = 0; j < 4; j++)
#pragma unroll
            for (int e = 0; e < 4; e++) acc[i][j][e] = 0.0f;

    const float* Ag = E  + ((size_t)bh * S_ + m0) * S_;
    const float* Bg = vt + (size_t)bh * HD * S_;
    const int NT = S_ / 16;   // 128
    stage<128>(sA[0], Ag, S_, tid); stage<64>(sB[0], Bg, S_, tid); CPC();
    stage<128>(sA[1], Ag + 16, S_, tid); stage<64>(sB[1], Bg + 16, S_, tid); CPC();

    const int ar0 = wm * 32 + (lane >> 2);
    const int bn0 = wn * 32 + (lane >> 2);
    const int c00 = lane & 3;
    for (int i = 0; i < NT; i++) {
        int s = i & 1;
        if (i >= NT - 2) { CPW0(); } else { CPW1(); }
        __syncthreads();
        wstep<1, 2>(As[s], Bs[s], ar0, bn0, c00, acc);
        wstep<1, 2>(As[s], Bs[s], ar0, bn0, c00 + 8, acc);
        __syncthreads();
        if (i + 2 < NT) {
            stage<128>(sA[s], Ag + (i + 2) * 16, S_, tid);
            stage<64>(sB[s], Bg + (i + 2) * 16, S_, tid);
            CPC();
        }
    }
#pragma unroll
    for (int i = 0; i < 2; i++) {
        int row = m0 + wm * 32 + i * 16 + (lane >> 2);
        float inv0 = 1.0f / rs[bh * S_ + row];
        float inv1 = 1.0f / rs[bh * S_ + row + 8];
#pragma unroll
        for (int j = 0; j < 4; j++) {
            int col = wn * 32 + j * 8 + (lane & 3) * 2;
            *(float2*)&O[((size_t)bh * S_ + row) * HD + col] =
                make_float2(acc[i][j][0] * inv0, acc[i][j][1] * inv0);
            *(float2*)&O[((size_t)bh * S_ + row + 8) * HD + col] =
                make_float2(acc[i][j][2] * inv1, acc[i][j][3] * inv1);
        }
    }
}

// ---------------- small utility kernels ----------------
__global__ __launch_bounds__(256)
void zero_rs_kernel(float* rs) { rs[blockIdx.x * 256 + threadIdx.x] = 0.0f; }

__global__ __launch_bounds__(256)
void transpose_k(const float* __restrict__ W, float* __restrict__ Wt) {
    __shared__ float t[32][33];
    const int tx = threadIdx.x & 31, ty = threadIdx.x >> 5;
    const int bx = blockIdx.x * 32, by = blockIdx.y * 32;
#pragma unroll
    for (int j = 0; j < 32; j += 8) t[ty + j][tx] = W[(size_t)(by + ty + j) * DM + bx + tx];
    __syncthreads();
#pragma unroll
    for (int j = 0; j < 32; j += 8) Wt[(size_t)(bx + ty + j) * DM + by + tx] = t[tx][ty + j];
}

// ---------------- launch ----------------
extern "C" void kernel_launch(void* const* d_in, const int* in_sizes, int n_in,
                              void* d_out, int out_size) {
    (void)in_sizes; (void)n_in; (void)out_size;
    const float* x    = (const float*)d_in[0];
    const int*   mask = (const int*)d_in[1];
    const float* W0   = (const float*)d_in[2];
    const float* b0   = (const float*)d_in[3];
    const float* W1   = (const float*)d_in[4];
    const float* b1   = (const float*)d_in[5];
    const float* W2   = (const float*)d_in[6];
    const float* b2   = (const float*)d_in[7];
    const float* Wo   = (const float*)d_in[8];
    const float* bo   = (const float*)d_in[9];
    float* out = (float*)d_out;

    float *q, *k, *vt, *o, *e, *wt, *rs;
    cudaGetSymbolAddress((void**)&q,  g_q);
    cudaGetSymbolAddress((void**)&k,  g_k);
    cudaGetSymbolAddress((void**)&vt, g_vt);
    cudaGetSymbolAddress((void**)&o,  g_o);
    cudaGetSymbolAddress((void**)&e,  g_e);
    cudaGetSymbolAddress((void**)&wt, g_wt);
    cudaGetSymbolAddress((void**)&rs, g_rs);

    zero_rs_kernel<<<BH_ * S_ / 256, 256>>>(rs);
    transpose_k<<<dim3(32, 32), 256>>>(W0, wt + 0 * DM * DM);
    transpose_k<<<dim3(32, 32), 256>>>(W1, wt + 1 * DM * DM);
    transpose_k<<<dim3(32, 32), 256>>>(W2, wt + 2 * DM * DM);
    transpose_k<<<dim3(32, 32), 256>>>(Wo, wt + 3 * DM * DM);

    gemm_mma<0><<<dim3(8, 32), 256>>>(x, wt + 0 * DM * DM, b0, q);
    gemm_mma<0><<<dim3(8, 32), 256>>>(q, wt + 1 * DM * DM, b1, k);
    gemm_mma<1><<<dim3(8, 32), 256>>>(q, wt + 2 * DM * DM, b2, vt);
    scores_mma<<<dim3(16, 16, 32), 256>>>(q, k, mask, e, rs);
    attnv_mma<<<dim3(16, 32), 256>>>(e, vt, rs, o);
    gemm_mma<0><<<dim3(8, 32), 256>>>(o, wt + 3 * DM * DM, bo, out);
}

// round 5
// speedup vs baseline: 1.7298x; 1.1975x over previous
#include <cuda_runtime.h>
#include <cstdint>

#define B_       2
#define S_       2048
#define DM       1024
#define H_       16
#define HD       64
#define BH_      32
#define MTOT     4096
#define L2E      1.4426950408889634f
#define SCALE_   0.125f
#define KP       20                  // fp32 smem row pad (floats)
#define KP2      24                  // bf16 smem row pad (halves) -> conflict-free

// ---------------- scratch (device globals) ----------------
__device__ __align__(128) float    g_q [MTOT * DM];                 // q fp32 (for scores)
__device__ __align__(128) float    g_k [MTOT * DM];                 // k fp32
__device__ __align__(128) float    g_vt[BH_ * HD * S_];             // V^T per head [bh][e][t]
__device__ __align__(128) uint16_t g_xs[2][MTOT * DM];              // x  bf16 hi/lo planes
__device__ __align__(128) uint16_t g_qs[2][MTOT * DM];              // q  bf16 hi/lo planes
__device__ __align__(128) uint16_t g_os[2][MTOT * DM];              // attn-out bf16 hi/lo planes
__device__ __align__(128) uint16_t g_wtb[4][2][DM * DM];            // W^T bf16 hi/lo planes [n][k]
__device__ __align__(128) float    g_e [(size_t)BH_ * S_ * S_];     // exp(masked logits)
__device__ __align__(128) float    g_rs[BH_ * S_];                  // row sums of E

// ---------------- helpers ----------------
__device__ __forceinline__ uint32_t smem_u32(const void* p) {
    uint32_t r;
    asm("{ .reg .u64 t; cvta.to.shared.u64 t, %1; cvt.u32.u64 %0, t; }" : "=r"(r) : "l"(p));
    return r;
}
__device__ __forceinline__ uint32_t tf32r(float x) {
    uint32_t u; asm("cvt.rna.tf32.f32 %0, %1;" : "=r"(u) : "f"(x)); return u;
}
// bf16 round-to-nearest-even, result as fp32 bit pattern (low 16 bits zero)
__device__ __forceinline__ uint32_t bfhi(float x) {
    uint32_t u = __float_as_uint(x);
    return (u + 0x7fffu + ((u >> 16) & 1u)) & 0xffff0000u;
}
// pack two fp32 into bf16x2 (lo element -> low half)
__device__ __forceinline__ uint32_t pkbf(float lo, float hi) {
    return bfhi(hi) | (bfhi(lo) >> 16);
}
__device__ __forceinline__ void cp16(uint32_t d, const void* s) {
    asm volatile("cp.async.ca.shared.global [%0], [%1], 16;" :: "r"(d), "l"(s));
}
#define CPC()  asm volatile("cp.async.commit_group;")
#define CPW1() asm volatile("cp.async.wait_group 1;")
#define CPW0() asm volatile("cp.async.wait_group 0;")

__device__ __forceinline__ void mma_t(float* d, const uint32_t* a, const uint32_t* b) {
    asm volatile("mma.sync.aligned.m16n8k8.row.col.f32.tf32.tf32.f32 "
                 "{%0,%1,%2,%3},{%4,%5,%6,%7},{%8,%9},{%0,%1,%2,%3};"
                 : "+f"(d[0]), "+f"(d[1]), "+f"(d[2]), "+f"(d[3])
                 : "r"(a[0]), "r"(a[1]), "r"(a[2]), "r"(a[3]), "r"(b[0]), "r"(b[1]));
}
__device__ __forceinline__ void mma_bf(float* d, const uint32_t* a, const uint32_t* b) {
    asm volatile("mma.sync.aligned.m16n8k16.row.col.f32.bf16.bf16.f32 "
                 "{%0,%1,%2,%3},{%4,%5,%6,%7},{%8,%9},{%0,%1,%2,%3};"
                 : "+f"(d[0]), "+f"(d[1]), "+f"(d[2]), "+f"(d[3])
                 : "r"(a[0]), "r"(a[1]), "r"(a[2]), "r"(a[3]), "r"(b[0]), "r"(b[1]));
}

// FMA-only exp2; valid t in [-126, 80]
__device__ __forceinline__ float fexp2(float t) {
    t = fminf(fmaxf(t, -126.0f), 80.0f);
    float z  = t + 12582912.0f;
    float fi = z - 12582912.0f;
    float f  = t - fi;
    int   ei = __float_as_int(z) - 0x4b400000;
    float p  = 0.0013333558f;
    p = fmaf(p, f, 0.0096181291f);
    p = fmaf(p, f, 0.0555041087f);
    p = fmaf(p, f, 0.2402265070f);
    p = fmaf(p, f, 0.6931471806f);
    p = fmaf(p, f, 1.0f);
    return p * __int_as_float((ei + 127) << 23);
}

// Stage [ROWS x 16] fp32 tile (ld floats) into smem [ROWS][KP]
template<int ROWS>
__device__ __forceinline__ void stage(uint32_t sb, const float* __restrict__ g, int ld, int tid) {
#pragma unroll
    for (int p = 0; p < ROWS / 64; p++) {
        int id = tid + p * 256;
        int r = id >> 2, s = id & 3;
        cp16(sb + (uint32_t)(r * KP + s * 4) * 4u, g + (size_t)r * ld + s * 4);
    }
}
// Stage [128 x 16] bf16 tile (ld halves) into smem [128][KP2]  (256 threads, 1 chunk each)
__device__ __forceinline__ void stage_bf(uint32_t sb, const uint16_t* __restrict__ g, int ld, int tid) {
    int r = tid >> 1, s = tid & 1;
    cp16(sb + (uint32_t)(r * KP2 + s * 8) * 2u, g + (size_t)r * ld + s * 8);
}

// tf32 warp step (SPLIT=1 only used): [MF*16 x 32] over one k8
template<int MF>
__device__ __forceinline__ void wstep(const float* __restrict__ As, const float* __restrict__ Bs,
                                      int ar0, int bn0, int c0, float (*acc)[4][4]) {
    uint32_t a[MF][4];
#pragma unroll
    for (int i = 0; i < MF; i++) {
        int r = ar0 + i * 16;
        a[i][0] = tf32r(As[r * KP + c0]);
        a[i][1] = tf32r(As[(r + 8) * KP + c0]);
        a[i][2] = tf32r(As[r * KP + c0 + 4]);
        a[i][3] = tf32r(As[(r + 8) * KP + c0 + 4]);
    }
#pragma unroll
    for (int j = 0; j < 4; j++) {
        int rn = bn0 + j * 8;
        uint32_t b2[2] = { tf32r(Bs[rn * KP + c0]), tf32r(Bs[rn * KP + c0 + 4]) };
#pragma unroll
        for (int i = 0; i < MF; i++) mma_t(acc[i][j], a[i], b2);
    }
}

// bf16 3-term warp step: [64 x 32] over one k16 (MF=4, NF=4)
__device__ __forceinline__ void wstep_bf(const uint16_t* Ah, const uint16_t* Al,
                                         const uint16_t* Bh, const uint16_t* Bl,
                                         int ar0, int bn0, int c2, float (*acc)[4][4]) {
    uint32_t ah[4][4], al[4][4];
#pragma unroll
    for (int i = 0; i < 4; i++) {
        int r = ar0 + i * 16;
        ah[i][0] = *(const uint32_t*)&Ah[r * KP2 + c2];
        ah[i][1] = *(const uint32_t*)&Ah[(r + 8) * KP2 + c2];
        ah[i][2] = *(const uint32_t*)&Ah[r * KP2 + c2 + 8];
        ah[i][3] = *(const uint32_t*)&Ah[(r + 8) * KP2 + c2 + 8];
        al[i][0] = *(const uint32_t*)&Al[r * KP2 + c2];
        al[i][1] = *(const uint32_t*)&Al[(r + 8) * KP2 + c2];
        al[i][2] = *(const uint32_t*)&Al[r * KP2 + c2 + 8];
        al[i][3] = *(const uint32_t*)&Al[(r + 8) * KP2 + c2 + 8];
    }
#pragma unroll
    for (int j = 0; j < 4; j++) {
        int n = bn0 + j * 8;
        uint32_t bh2[2] = { *(const uint32_t*)&Bh[n * KP2 + c2], *(const uint32_t*)&Bh[n * KP2 + c2 + 8] };
        uint32_t bl2[2] = { *(const uint32_t*)&Bl[n * KP2 + c2], *(const uint32_t*)&Bl[n * KP2 + c2 + 8] };
#pragma unroll
        for (int i = 0; i < 4; i++) {
            mma_bf(acc[i][j], ah[i], bh2);
            mma_bf(acc[i][j], al[i], bh2);
            mma_bf(acc[i][j], ah[i], bl2);
        }
    }
}

// ---------------- dense (bf16 3-term): C = relu(A @ W + bias), tile 128x128 ----------------
// MODE 0: fp32 C only. MODE 1: V^T per head (fp32). MODE 2: fp32 C + bf16 planes Chi/Clo.
// MODE 3: bf16 planes only (unused). Planes laid out [m][1024] halves.
#define PL(s, p) (sm + (uint32_t)(((s) * 4 + (p)) * 128 * KP2))
#define DSMEM (8 * 128 * KP2 * 2)
template<int MODE>
__global__ __launch_bounds__(256)
void gemm_bf(const uint16_t* __restrict__ Ahg, const uint16_t* __restrict__ Alg,
             const uint16_t* __restrict__ Bhg, const uint16_t* __restrict__ Blg,
             const float* __restrict__ bias, float* __restrict__ C,
             uint16_t* __restrict__ Chi, uint16_t* __restrict__ Clo) {
    extern __shared__ uint16_t sm[];
    const int tid = threadIdx.x, lane = tid & 31, wid = tid >> 5;
    const int wm = wid & 1, wn = wid >> 1;
    const int m0 = blockIdx.y * 128, n0 = blockIdx.x * 128;
    const uint32_t sb = smem_u32(sm);
    float acc[4][4][4];
#pragma unroll
    for (int i = 0; i < 4; i++)
#pragma unroll
        for (int j = 0; j < 4; j++)
#pragma unroll
            for (int e = 0; e < 4; e++) acc[i][j][e] = 0.0f;

    const uint16_t* Ah = Ahg + (size_t)m0 * DM;
    const uint16_t* Al = Alg + (size_t)m0 * DM;
    const uint16_t* Bh = Bhg + (size_t)n0 * DM;
    const uint16_t* Bl = Blg + (size_t)n0 * DM;
    const int NT = DM / 16;   // 64

#pragma unroll
    for (int s = 0; s < 2; s++) {
        stage_bf(sb + (uint32_t)((s * 4 + 0) * 128 * KP2) * 2u, Ah + s * 16, DM, tid);
        stage_bf(sb + (uint32_t)((s * 4 + 1) * 128 * KP2) * 2u, Al + s * 16, DM, tid);
        stage_bf(sb + (uint32_t)((s * 4 + 2) * 128 * KP2) * 2u, Bh + s * 16, DM, tid);
        stage_bf(sb + (uint32_t)((s * 4 + 3) * 128 * KP2) * 2u, Bl + s * 16, DM, tid);
        CPC();
    }
    const int ar0 = wm * 64 + (lane >> 2);
    const int bn0 = wn * 32 + (lane >> 2);
    const int c2 = (lane & 3) * 2;
    for (int i = 0; i < NT; i++) {
        int s = i & 1;
        if (i >= NT - 2) { CPW0(); } else { CPW1(); }
        __syncthreads();
        wstep_bf(sm + (s * 4 + 0) * 128 * KP2, sm + (s * 4 + 1) * 128 * KP2,
                 sm + (s * 4 + 2) * 128 * KP2, sm + (s * 4 + 3) * 128 * KP2,
                 ar0, bn0, c2, acc);
        __syncthreads();
        if (i + 2 < NT) {
            stage_bf(sb + (uint32_t)((s * 4 + 0) * 128 * KP2) * 2u, Ah + (i + 2) * 16, DM, tid);
            stage_bf(sb + (uint32_t)((s * 4 + 1) * 128 * KP2) * 2u, Al + (i + 2) * 16, DM, tid);
            stage_bf(sb + (uint32_t)((s * 4 + 2) * 128 * KP2) * 2u, Bh + (i + 2) * 16, DM, tid);
            stage_bf(sb + (uint32_t)((s * 4 + 3) * 128 * KP2) * 2u, Bl + (i + 2) * 16, DM, tid);
            CPC();
        }
    }
#pragma unroll
    for (int i = 0; i < 4; i++)
#pragma unroll
        for (int j = 0; j < 4; j++) {
            int m = m0 + wm * 64 + i * 16 + (lane >> 2);
            int n = n0 + wn * 32 + j * 8 + (lane & 3) * 2;
            float bz0 = bias[n], bz1 = bias[n + 1];
            float v00 = fmaxf(acc[i][j][0] + bz0, 0.0f), v01 = fmaxf(acc[i][j][1] + bz1, 0.0f);
            float v10 = fmaxf(acc[i][j][2] + bz0, 0.0f), v11 = fmaxf(acc[i][j][3] + bz1, 0.0f);
            if (MODE == 0 || MODE == 2) {
                *(float2*)&C[(size_t)m * DM + n]       = make_float2(v00, v01);
                *(float2*)&C[(size_t)(m + 8) * DM + n] = make_float2(v10, v11);
            }
            if (MODE == 2 || MODE == 3) {
                size_t p0 = ((size_t)m * DM + n) >> 1, p1 = ((size_t)(m + 8) * DM + n) >> 1;
                ((uint32_t*)Chi)[p0] = pkbf(v00, v01);
                ((uint32_t*)Chi)[p1] = pkbf(v10, v11);
                float r00 = v00 - __uint_as_float(bfhi(v00));
                float r01 = v01 - __uint_as_float(bfhi(v01));
                float r10 = v10 - __uint_as_float(bfhi(v10));
                float r11 = v11 - __uint_as_float(bfhi(v11));
                ((uint32_t*)Clo)[p0] = pkbf(r00, r01);
                ((uint32_t*)Clo)[p1] = pkbf(r10, r11);
            }
            if (MODE == 1) {
                int b = m >> 11, t = m & 2047, h = n >> 6, e = n & 63;
                size_t base = ((size_t)(b * 16 + h) * 64 + e) * S_;
                C[base + t]          = v00;
                C[base + S_ + t]     = v01;
                C[base + t + 8]      = v10;
                C[base + S_ + t + 8] = v11;
            }
        }
}

// ---------------- scores: E = mask ? exp(scale*q.k) : 0 ; rowsums via atomics ----------------
__global__ __launch_bounds__(256)
void scores_mma(const float* __restrict__ q, const float* __restrict__ kk,
                const int* __restrict__ mask, float* __restrict__ E, float* __restrict__ rs) {
    __shared__ float As[2][128 * KP], Bs[2][128 * KP];
    const int tid = threadIdx.x, lane = tid & 31, wid = tid >> 5;
    const int wm = wid & 1, wn = wid >> 1;
    const int bh = blockIdx.z, b = bh >> 4, h = bh & 15;
    const int t0 = blockIdx.x * 128, s0 = blockIdx.y * 128;
    const uint32_t sA[2] = { smem_u32(As[0]), smem_u32(As[1]) };
    const uint32_t sB[2] = { smem_u32(Bs[0]), smem_u32(Bs[1]) };
    float acc[4][4][4];
#pragma unroll
    for (int i = 0; i < 4; i++)
#pragma unroll
        for (int j = 0; j < 4; j++)
#pragma unroll
            for (int e = 0; e < 4; e++) acc[i][j][e] = 0.0f;

    const float* Ag = q  + ((size_t)b * S_ + s0) * DM + h * HD;
    const float* Bg = kk + ((size_t)b * S_ + t0) * DM + h * HD;
    const int NT = HD / 16;   // 4
    stage<128>(sA[0], Ag, DM, tid); stage<128>(sB[0], Bg, DM, tid); CPC();
    stage<128>(sA[1], Ag + 16, DM, tid); stage<128>(sB[1], Bg + 16, DM, tid); CPC();

    const int ar0 = wm * 64 + (lane >> 2);
    const int bn0 = wn * 32 + (lane >> 2);
    const int c00 = lane & 3;
    for (int i = 0; i < NT; i++) {
        int s = i & 1;
        if (i >= NT - 2) { CPW0(); } else { CPW1(); }
        __syncthreads();
        wstep<4>(As[s], Bs[s], ar0, bn0, c00, acc);
        wstep<4>(As[s], Bs[s], ar0, bn0, c00 + 8, acc);
        __syncthreads();
        if (i + 2 < NT) {
            stage<128>(sA[s], Ag + (i + 2) * 16, DM, tid);
            stage<128>(sB[s], Bg + (i + 2) * 16, DM, tid);
            CPC();
        }
    }
    const float cf = SCALE_ * L2E;
    float rowacc[8];
#pragma unroll
    for (int i = 0; i < 8; i++) rowacc[i] = 0.0f;
#pragma unroll
    for (int i = 0; i < 4; i++)
#pragma unroll
        for (int j = 0; j < 4; j++) {
            int mrow = s0 + wm * 64 + i * 16 + (lane >> 2);
            int tcol = t0 + wn * 32 + j * 8 + (lane & 3) * 2;
            int2 mk0 = *(const int2*)&mask[((size_t)b * S_ + mrow) * S_ + tcol];
            int2 mk1 = *(const int2*)&mask[((size_t)b * S_ + mrow + 8) * S_ + tcol];
            float e00 = (mk0.x == 1) ? fexp2(acc[i][j][0] * cf) : 0.0f;
            float e01 = (mk0.y == 1) ? fexp2(acc[i][j][1] * cf) : 0.0f;
            float e10 = (mk1.x == 1) ? fexp2(acc[i][j][2] * cf) : 0.0f;
            float e11 = (mk1.y == 1) ? fexp2(acc[i][j][3] * cf) : 0.0f;
            *(float2*)&E[((size_t)bh * S_ + mrow) * S_ + tcol]     = make_float2(e00, e01);
            *(float2*)&E[((size_t)bh * S_ + mrow + 8) * S_ + tcol] = make_float2(e10, e11);
            rowacc[i * 2 + 0] += e00 + e01;
            rowacc[i * 2 + 1] += e10 + e11;
        }
#pragma unroll
    for (int i = 0; i < 4; i++) {
        int mrow = s0 + wm * 64 + i * 16 + (lane >> 2);
        atomicAdd(&rs[bh * S_ + mrow],     rowacc[i * 2 + 0]);
        atomicAdd(&rs[bh * S_ + mrow + 8], rowacc[i * 2 + 1]);
    }
}

// ---------------- attnv: O = (E @ V^T) / rowsum ; writes bf16 hi/lo planes ----------------
__global__ __launch_bounds__(256)
void attnv_mma(const float* __restrict__ E, const float* __restrict__ vt,
               const float* __restrict__ rs, uint16_t* __restrict__ Ohi, uint16_t* __restrict__ Olo) {
    __shared__ float As[2][128 * KP], Bs[2][64 * KP];
    const int tid = threadIdx.x, lane = tid & 31, wid = tid >> 5;
    const int wm = wid & 3, wn = wid >> 2;
    const int bh = blockIdx.y, m0 = blockIdx.x * 128;
    const uint32_t sA[2] = { smem_u32(As[0]), smem_u32(As[1]) };
    const uint32_t sB[2] = { smem_u32(Bs[0]), smem_u32(Bs[1]) };
    float acc[2][4][4];
#pragma unroll
    for (int i = 0; i < 2; i++)
#pragma unroll
        for (int j = 0; j < 4; j++)
#pragma unroll
            for (int e = 0; e < 4; e++) acc[i][j][e] = 0.0f;

    const float* Ag = E  + ((size_t)bh * S_ + m0) * S_;
    const float* Bg = vt + (size_t)bh * HD * S_;
    const int NT = S_ / 16;   // 128
    stage<128>(sA[0], Ag, S_, tid); stage<64>(sB[0], Bg, S_, tid); CPC();
    stage<128>(sA[1], Ag + 16, S_, tid); stage<64>(sB[1], Bg + 16, S_, tid); CPC();

    const int ar0 = wm * 32 + (lane >> 2);
    const int bn0 = wn * 32 + (lane >> 2);
    const int c00 = lane & 3;
    for (int i = 0; i < NT; i++) {
        int s = i & 1;
        if (i >= NT - 2) { CPW0(); } else { CPW1(); }
        __syncthreads();
        wstep<2>(As[s], Bs[s], ar0, bn0, c00, acc);
        wstep<2>(As[s], Bs[s], ar0, bn0, c00 + 8, acc);
        __syncthreads();
        if (i + 2 < NT) {
            stage<128>(sA[s], Ag + (i + 2) * 16, S_, tid);
            stage<64>(sB[s], Bg + (i + 2) * 16, S_, tid);
            CPC();
        }
    }
#pragma unroll
    for (int i = 0; i < 2; i++) {
        int row = m0 + wm * 32 + i * 16 + (lane >> 2);
        float inv0 = 1.0f / rs[bh * S_ + row];
        float inv1 = 1.0f / rs[bh * S_ + row + 8];
#pragma unroll
        for (int j = 0; j < 4; j++) {
            int col = wn * 32 + j * 8 + (lane & 3) * 2;
            float v00 = acc[i][j][0] * inv0, v01 = acc[i][j][1] * inv0;
            float v10 = acc[i][j][2] * inv1, v11 = acc[i][j][3] * inv1;
            size_t p0 = (((size_t)bh * S_ + row) * HD + col) >> 1;
            size_t p1 = (((size_t)bh * S_ + row + 8) * HD + col) >> 1;
            ((uint32_t*)Ohi)[p0] = pkbf(v00, v01);
            ((uint32_t*)Ohi)[p1] = pkbf(v10, v11);
            float r00 = v00 - __uint_as_float(bfhi(v00));
            float r01 = v01 - __uint_as_float(bfhi(v01));
            float r10 = v10 - __uint_as_float(bfhi(v10));
            float r11 = v11 - __uint_as_float(bfhi(v11));
            ((uint32_t*)Olo)[p0] = pkbf(r00, r01);
            ((uint32_t*)Olo)[p1] = pkbf(r10, r11);
        }
    }
}

// ---------------- small utility kernels ----------------
__global__ __launch_bounds__(256)
void zero_rs_kernel(float* rs) { rs[blockIdx.x * 256 + threadIdx.x] = 0.0f; }

// split fp32 -> bf16 hi/lo planes (element pairs)
__global__ __launch_bounds__(256)
void split_kernel(const float* __restrict__ X, uint16_t* __restrict__ Xhi, uint16_t* __restrict__ Xlo) {
    size_t i = (size_t)blockIdx.x * 256 + threadIdx.x;   // over MTOT*DM/2
    float2 v = ((const float2*)X)[i];
    ((uint32_t*)Xhi)[i] = pkbf(v.x, v.y);
    float rx = v.x - __uint_as_float(bfhi(v.x));
    float ry = v.y - __uint_as_float(bfhi(v.y));
    ((uint32_t*)Xlo)[i] = pkbf(rx, ry);
}

// transpose + split: Wt planes [n][k] = split(W[k][n])
__global__ __launch_bounds__(256)
void transpose_split(const float* __restrict__ W, uint16_t* __restrict__ Whi, uint16_t* __restrict__ Wlo) {
    __shared__ float t[32][33];
    const int tx = threadIdx.x & 31, ty = threadIdx.x >> 5;
    const int bx = blockIdx.x * 32, by = blockIdx.y * 32;
#pragma unroll
    for (int j = 0; j < 32; j += 8) t[ty + j][tx] = W[(size_t)(by + ty + j) * DM + bx + tx];
    __syncthreads();
#pragma unroll
    for (int j = 0; j < 32; j += 8) {
        float v = t[tx][ty + j];
        size_t idx = (size_t)(bx + ty + j) * DM + by + tx;
        Whi[idx] = (uint16_t)(bfhi(v) >> 16);
        float rr = v - __uint_as_float(bfhi(v));
        Wlo[idx] = (uint16_t)(bfhi(rr) >> 16);
    }
}

// ---------------- launch ----------------
extern "C" void kernel_launch(void* const* d_in, const int* in_sizes, int n_in,
                              void* d_out, int out_size) {
    (void)in_sizes; (void)n_in; (void)out_size;
    const float* x    = (const float*)d_in[0];
    const int*   mask = (const int*)d_in[1];
    const float* W0   = (const float*)d_in[2];
    const float* b0   = (const float*)d_in[3];
    const float* W1   = (const float*)d_in[4];
    const float* b1   = (const float*)d_in[5];
    const float* W2   = (const float*)d_in[6];
    const float* b2   = (const float*)d_in[7];
    const float* Wo   = (const float*)d_in[8];
    const float* bo   = (const float*)d_in[9];
    float* out = (float*)d_out;

    float *q, *k, *vt, *e, *rs;
    uint16_t *xs, *qs, *os, *wtb;
    cudaGetSymbolAddress((void**)&q,   g_q);
    cudaGetSymbolAddress((void**)&k,   g_k);
    cudaGetSymbolAddress((void**)&vt,  g_vt);
    cudaGetSymbolAddress((void**)&e,   g_e);
    cudaGetSymbolAddress((void**)&rs,  g_rs);
    cudaGetSymbolAddress((void**)&xs,  g_xs);
    cudaGetSymbolAddress((void**)&qs,  g_qs);
    cudaGetSymbolAddress((void**)&os,  g_os);
    cudaGetSymbolAddress((void**)&wtb, g_wtb);
    const size_t PLN = (size_t)MTOT * DM;   // plane elements
    const size_t WP  = (size_t)DM * DM;

    cudaFuncSetAttribute(gemm_bf<0>, cudaFuncAttributeMaxDynamicSharedMemorySize, DSMEM);
    cudaFuncSetAttribute(gemm_bf<1>, cudaFuncAttributeMaxDynamicSharedMemorySize, DSMEM);
    cudaFuncSetAttribute(gemm_bf<2>, cudaFuncAttributeMaxDynamicSharedMemorySize, DSMEM);

    zero_rs_kernel<<<BH_ * S_ / 256, 256>>>(rs);
    split_kernel<<<MTOT * DM / 512, 256>>>(x, xs, xs + PLN);
    transpose_split<<<dim3(32, 32), 256>>>(W0, wtb + 0 * 2 * WP, wtb + 0 * 2 * WP + WP);
    transpose_split<<<dim3(32, 32), 256>>>(W1, wtb + 1 * 2 * WP, wtb + 1 * 2 * WP + WP);
    transpose_split<<<dim3(32, 32), 256>>>(W2, wtb + 2 * 2 * WP, wtb + 2 * 2 * WP + WP);
    transpose_split<<<dim3(32, 32), 256>>>(Wo, wtb + 3 * 2 * WP, wtb + 3 * 2 * WP + WP);

    gemm_bf<2><<<dim3(8, 32), 256, DSMEM>>>(xs, xs + PLN, wtb + 0 * 2 * WP, wtb + 0 * 2 * WP + WP,
                                            b0, q, qs, qs + PLN);
    gemm_bf<0><<<dim3(8, 32), 256, DSMEM>>>(qs, qs + PLN, wtb + 1 * 2 * WP, wtb + 1 * 2 * WP + WP,
                                            b1, k, nullptr, nullptr);
    gemm_bf<1><<<dim3(8, 32), 256, DSMEM>>>(qs, qs + PLN, wtb + 2 * 2 * WP, wtb + 2 * 2 * WP + WP,
                                            b2, vt, nullptr, nullptr);
    scores_mma<<<dim3(16, 16, 32), 256>>>(q, k, mask, e, rs);
    attnv_mma<<<dim3(16, 32), 256>>>(e, vt, rs, os, os + PLN);
    gemm_bf<0><<<dim3(8, 32), 256, DSMEM>>>(os, os + PLN, wtb + 3 * 2 * WP, wtb + 3 * 2 * WP + WP,
                                            bo, out, nullptr, nullptr);
}

// round 7
// speedup vs baseline: 1.8584x; 1.0743x over previous
#include <cuda_runtime.h>
#include <cstdint>

#define B_       2
#define S_       2048
#define DM       1024
#define H_       16
#define HD       64
#define BH_      32
#define MTOT     4096
#define L2E      1.4426950408889634f
#define SCALE_   0.125f
#define KP2      24                  // bf16 smem row pad (halves), dense GEMM
#define KPQ      68                  // q/k smem row pad (floats), flash
#define KPV      136                 // v smem row pad (halves), flash

// ---------------- scratch (device globals) ----------------
__device__ __align__(128) float    g_q [MTOT * DM];            // q fp32 (QK tf32 operand)
__device__ __align__(128) float    g_k [MTOT * DM];            // k fp32
__device__ __align__(128) uint16_t g_vt[BH_ * HD * S_];        // V^T bf16 per head [bh][e][t]
__device__ __align__(128) uint16_t g_xs[2][MTOT * DM];         // x  bf16 hi/lo planes
__device__ __align__(128) uint16_t g_qs[2][MTOT * DM];         // q  bf16 hi/lo planes
__device__ __align__(128) uint16_t g_os[2][MTOT * DM];         // attn-out bf16 hi/lo planes
__device__ __align__(128) uint16_t g_wtb[4][2][DM * DM];       // W^T bf16 hi/lo planes [n][k]

// single extern shared array (one type everywhere)
extern __shared__ char smraw[];

// ---------------- helpers ----------------
__device__ __forceinline__ uint32_t smem_u32(const void* p) {
    uint32_t r;
    asm("{ .reg .u64 t; cvta.to.shared.u64 t, %1; cvt.u32.u64 %0, t; }" : "=r"(r) : "l"(p));
    return r;
}
__device__ __forceinline__ uint32_t tf32r(float x) {
    uint32_t u; asm("cvt.rna.tf32.f32 %0, %1;" : "=r"(u) : "f"(x)); return u;
}
__device__ __forceinline__ uint32_t bfhi(float x) {   // bf16 RNE, as fp32 bits (low16=0)
    uint32_t u = __float_as_uint(x);
    return (u + 0x7fffu + ((u >> 16) & 1u)) & 0xffff0000u;
}
__device__ __forceinline__ uint32_t pkbf(float lo, float hi) {
    return bfhi(hi) | (bfhi(lo) >> 16);
}
__device__ __forceinline__ void cp16(uint32_t d, const void* s) {
    asm volatile("cp.async.ca.shared.global [%0], [%1], 16;" :: "r"(d), "l"(s));
}
#define CPC()  asm volatile("cp.async.commit_group;")
#define CPW1() asm volatile("cp.async.wait_group 1;")
#define CPW0() asm volatile("cp.async.wait_group 0;")

__device__ __forceinline__ void mma_t(float* d, const uint32_t* a, const uint32_t* b) {
    asm volatile("mma.sync.aligned.m16n8k8.row.col.f32.tf32.tf32.f32 "
                 "{%0,%1,%2,%3},{%4,%5,%6,%7},{%8,%9},{%0,%1,%2,%3};"
                 : "+f"(d[0]), "+f"(d[1]), "+f"(d[2]), "+f"(d[3])
                 : "r"(a[0]), "r"(a[1]), "r"(a[2]), "r"(a[3]), "r"(b[0]), "r"(b[1]));
}
__device__ __forceinline__ void mma_bf(float* d, const uint32_t* a, const uint32_t* b) {
    asm volatile("mma.sync.aligned.m16n8k16.row.col.f32.bf16.bf16.f32 "
                 "{%0,%1,%2,%3},{%4,%5,%6,%7},{%8,%9},{%0,%1,%2,%3};"
                 : "+f"(d[0]), "+f"(d[1]), "+f"(d[2]), "+f"(d[3])
                 : "r"(a[0]), "r"(a[1]), "r"(a[2]), "r"(a[3]), "r"(b[0]), "r"(b[1]));
}

// FMA-only exp2; valid t in [-126, 80]
__device__ __forceinline__ float fexp2(float t) {
    t = fminf(fmaxf(t, -126.0f), 80.0f);
    float z  = t + 12582912.0f;
    float fi = z - 12582912.0f;
    float f  = t - fi;
    int   ei = __float_as_int(z) - 0x4b400000;
    float p  = 0.0013333558f;
    p = fmaf(p, f, 0.0096181291f);
    p = fmaf(p, f, 0.0555041087f);
    p = fmaf(p, f, 0.2402265070f);
    p = fmaf(p, f, 0.6931471806f);
    p = fmaf(p, f, 1.0f);
    return p * __int_as_float((ei + 127) << 23);
}

// Stage [128 x 16] bf16 tile (ld halves) into smem [128][KP2]
__device__ __forceinline__ void stage_bf(uint32_t sb, const uint16_t* __restrict__ g, int ld, int tid) {
    int r = tid >> 1, s = tid & 1;
    cp16(sb + (uint32_t)(r * KP2 + s * 8) * 2u, g + (size_t)r * ld + s * 8);
}

// bf16 3-term warp step: [64 x 32] over one k16 (MF=4, NF=4)
__device__ __forceinline__ void wstep_bf(const uint16_t* Ah, const uint16_t* Al,
                                         const uint16_t* Bh, const uint16_t* Bl,
                                         int ar0, int bn0, int c2, float (*acc)[4][4]) {
    uint32_t ah[4][4], al[4][4];
#pragma unroll
    for (int i = 0; i < 4; i++) {
        int r = ar0 + i * 16;
        ah[i][0] = *(const uint32_t*)&Ah[r * KP2 + c2];
        ah[i][1] = *(const uint32_t*)&Ah[(r + 8) * KP2 + c2];
        ah[i][2] = *(const uint32_t*)&Ah[r * KP2 + c2 + 8];
        ah[i][3] = *(const uint32_t*)&Ah[(r + 8) * KP2 + c2 + 8];
        al[i][0] = *(const uint32_t*)&Al[r * KP2 + c2];
        al[i][1] = *(const uint32_t*)&Al[(r + 8) * KP2 + c2];
        al[i][2] = *(const uint32_t*)&Al[r * KP2 + c2 + 8];
        al[i][3] = *(const uint32_t*)&Al[(r + 8) * KP2 + c2 + 8];
    }
#pragma unroll
    for (int j = 0; j < 4; j++) {
        int n = bn0 + j * 8;
        uint32_t bh2[2] = { *(const uint32_t*)&Bh[n * KP2 + c2], *(const uint32_t*)&Bh[n * KP2 + c2 + 8] };
        uint32_t bl2[2] = { *(const uint32_t*)&Bl[n * KP2 + c2], *(const uint32_t*)&Bl[n * KP2 + c2 + 8] };
#pragma unroll
        for (int i = 0; i < 4; i++) {
            mma_bf(acc[i][j], ah[i], bh2);
            mma_bf(acc[i][j], al[i], bh2);
            mma_bf(acc[i][j], ah[i], bl2);
        }
    }
}

// ---------------- dense (bf16 3-term): C = relu(A @ W + bias), tile 128x128 ----------------
// MODE 0: fp32 C.  MODE 1: bf16 V^T per head into Chi.  MODE 2: fp32 C + bf16 planes.
#define DSMEM (8 * 128 * KP2 * 2)
template<int MODE>
__global__ __launch_bounds__(256)
void gemm_bf(const uint16_t* __restrict__ Ahg, const uint16_t* __restrict__ Alg,
             const uint16_t* __restrict__ Bhg, const uint16_t* __restrict__ Blg,
             const float* __restrict__ bias, float* __restrict__ C,
             uint16_t* __restrict__ Chi, uint16_t* __restrict__ Clo) {
    uint16_t* sm = (uint16_t*)smraw;
    const int tid = threadIdx.x, lane = tid & 31, wid = tid >> 5;
    const int wm = wid & 1, wn = wid >> 1;
    const int m0 = blockIdx.y * 128, n0 = blockIdx.x * 128;
    const uint32_t sb = smem_u32(sm);
    float acc[4][4][4];
#pragma unroll
    for (int i = 0; i < 4; i++)
#pragma unroll
        for (int j = 0; j < 4; j++)
#pragma unroll
            for (int e = 0; e < 4; e++) acc[i][j][e] = 0.0f;

    const uint16_t* Ah = Ahg + (size_t)m0 * DM;
    const uint16_t* Al = Alg + (size_t)m0 * DM;
    const uint16_t* Bh = Bhg + (size_t)n0 * DM;
    const uint16_t* Bl = Blg + (size_t)n0 * DM;
    const int NT = DM / 16;   // 64

#pragma unroll
    for (int s = 0; s < 2; s++) {
        stage_bf(sb + (uint32_t)((s * 4 + 0) * 128 * KP2) * 2u, Ah + s * 16, DM, tid);
        stage_bf(sb + (uint32_t)((s * 4 + 1) * 128 * KP2) * 2u, Al + s * 16, DM, tid);
        stage_bf(sb + (uint32_t)((s * 4 + 2) * 128 * KP2) * 2u, Bh + s * 16, DM, tid);
        stage_bf(sb + (uint32_t)((s * 4 + 3) * 128 * KP2) * 2u, Bl + s * 16, DM, tid);
        CPC();
    }
    const int ar0 = wm * 64 + (lane >> 2);
    const int bn0 = wn * 32 + (lane >> 2);
    const int c2 = (lane & 3) * 2;
    for (int i = 0; i < NT; i++) {
        int s = i & 1;
        if (i >= NT - 2) { CPW0(); } else { CPW1(); }
        __syncthreads();
        wstep_bf(sm + (s * 4 + 0) * 128 * KP2, sm + (s * 4 + 1) * 128 * KP2,
                 sm + (s * 4 + 2) * 128 * KP2, sm + (s * 4 + 3) * 128 * KP2,
                 ar0, bn0, c2, acc);
        __syncthreads();
        if (i + 2 < NT) {
            stage_bf(sb + (uint32_t)((s * 4 + 0) * 128 * KP2) * 2u, Ah + (i + 2) * 16, DM, tid);
            stage_bf(sb + (uint32_t)((s * 4 + 1) * 128 * KP2) * 2u, Al + (i + 2) * 16, DM, tid);
            stage_bf(sb + (uint32_t)((s * 4 + 2) * 128 * KP2) * 2u, Bh + (i + 2) * 16, DM, tid);
            stage_bf(sb + (uint32_t)((s * 4 + 3) * 128 * KP2) * 2u, Bl + (i + 2) * 16, DM, tid);
            CPC();
        }
    }
#pragma unroll
    for (int i = 0; i < 4; i++)
#pragma unroll
        for (int j = 0; j < 4; j++) {
            int m = m0 + wm * 64 + i * 16 + (lane >> 2);
            int n = n0 + wn * 32 + j * 8 + (lane & 3) * 2;
            float bz0 = bias[n], bz1 = bias[n + 1];
            float v00 = fmaxf(acc[i][j][0] + bz0, 0.0f), v01 = fmaxf(acc[i][j][1] + bz1, 0.0f);
            float v10 = fmaxf(acc[i][j][2] + bz0, 0.0f), v11 = fmaxf(acc[i][j][3] + bz1, 0.0f);
            if (MODE == 0 || MODE == 2) {
                *(float2*)&C[(size_t)m * DM + n]       = make_float2(v00, v01);
                *(float2*)&C[(size_t)(m + 8) * DM + n] = make_float2(v10, v11);
            }
            if (MODE == 2) {
                size_t p0 = ((size_t)m * DM + n) >> 1, p1 = ((size_t)(m + 8) * DM + n) >> 1;
                ((uint32_t*)Chi)[p0] = pkbf(v00, v01);
                ((uint32_t*)Chi)[p1] = pkbf(v10, v11);
                float r00 = v00 - __uint_as_float(bfhi(v00));
                float r01 = v01 - __uint_as_float(bfhi(v01));
                float r10 = v10 - __uint_as_float(bfhi(v10));
                float r11 = v11 - __uint_as_float(bfhi(v11));
                ((uint32_t*)Clo)[p0] = pkbf(r00, r01);
                ((uint32_t*)Clo)[p1] = pkbf(r10, r11);
            }
            if (MODE == 1) {
                int bb = m >> 11, t = m & 2047, hh = n >> 6, e = n & 63;
                size_t base = ((size_t)(bb * 16 + hh) * 64 + e) * S_;
                Chi[base + t]          = (uint16_t)(bfhi(v00) >> 16);
                Chi[base + S_ + t]     = (uint16_t)(bfhi(v01) >> 16);
                Chi[base + t + 8]      = (uint16_t)(bfhi(v10) >> 16);
                Chi[base + S_ + t + 8] = (uint16_t)(bfhi(v11) >> 16);
            }
        }
}

// ---------------- fused flash attention ----------------
// Per (s-tile 128, bh): loop 16 t-tiles: QK(tf32) -> mask+exp2 (regs) -> PV(bf16).
// smem: q[128][KPQ] f32 | k x2 [128][KPQ] f32 | v x2 [64][KPV] bf16 | srow[128] f32
#define QOFF   0
#define KOFF0  34816
#define KOFF1  69632
#define VOFF0  104448
#define VOFF1  121856
#define SROWO  139264
#define FSMEM  139776
__global__ __launch_bounds__(256, 1)
void flash_attn(const float* __restrict__ q, const float* __restrict__ k,
                const uint16_t* __restrict__ vtb, const int* __restrict__ mask,
                uint16_t* __restrict__ Ohi, uint16_t* __restrict__ Olo) {
    char* sm = smraw;
    const int tid = threadIdx.x, lane = tid & 31, wid = tid >> 5;
    const int wn = wid & 1, wm = wid >> 1;          // 2 t-col warps x 4 m-row warps
    const int bh = blockIdx.y, b = bh >> 4, h = bh & 15;
    const int s0 = blockIdx.x * 128;
    const uint32_t sb = smem_u32(sm);
    float* srow = (float*)(sm + SROWO);
    if (tid < 128) srow[tid] = 0.0f;

    const float* qg = q + ((size_t)b * S_ + s0) * DM + h * HD;
    const float* kg = k + (size_t)b * S_ * DM + h * HD;
    const uint16_t* vg = vtb + (size_t)bh * HD * S_;

    // stage q once: [128][64] f32 -> [128][KPQ]
#pragma unroll
    for (int p = 0; p < 8; p++) {
        int id = tid + p * 256, r = id >> 4, s = id & 15;
        cp16(sb + QOFF + (uint32_t)(r * KPQ + s * 4) * 4u, qg + (size_t)r * DM + s * 4);
    }
    auto stage_k = [&](uint32_t koff, int t0) {
        const float* src = kg + (size_t)t0 * DM;
#pragma unroll
        for (int p = 0; p < 8; p++) {
            int id = tid + p * 256, r = id >> 4, c = id & 15;
            cp16(sb + koff + (uint32_t)(r * KPQ + c * 4) * 4u, src + (size_t)r * DM + c * 4);
        }
    };
    auto stage_v = [&](uint32_t voff, int t0) {
#pragma unroll
        for (int p = 0; p < 4; p++) {
            int id = tid + p * 256, e = id >> 4, c = id & 15;
            cp16(sb + voff + (uint32_t)(e * KPV + c * 8) * 2u, vg + (size_t)e * S_ + t0 + c * 8);
        }
    };
    stage_k(KOFF0, 0);   stage_v(VOFF0, 0);   CPC();
    stage_k(KOFF1, 128); stage_v(VOFF1, 128); CPC();

    float acc2[2][8][4];
#pragma unroll
    for (int i = 0; i < 2; i++)
#pragma unroll
        for (int j = 0; j < 8; j++)
#pragma unroll
            for (int e = 0; e < 4; e++) acc2[i][j][e] = 0.0f;
    float rs4[4] = {0.f, 0.f, 0.f, 0.f};

    const float* Qs = (const float*)(sm + QOFF);
    const int ar0 = wm * 32 + (lane >> 2);
    const int bn0 = wn * 64 + (lane >> 2);
    const float cf = SCALE_ * L2E;

    for (int it = 0; it < 16; it++) {
        const int s = it & 1;
        if (it >= 14) { CPW0(); } else { CPW1(); }
        __syncthreads();
        const float*    Ks = (const float*)(sm + (s ? KOFF1 : KOFF0));
        const uint16_t* Vs = (const uint16_t*)(sm + (s ? VOFF1 : VOFF0));

        // ---- QK: warp tile [32 m x 64 t], tf32 ----
        float acc[2][8][4];
#pragma unroll
        for (int i = 0; i < 2; i++)
#pragma unroll
            for (int j = 0; j < 8; j++)
#pragma unroll
                for (int e = 0; e < 4; e++) acc[i][j][e] = 0.0f;
#pragma unroll
        for (int kc = 0; kc < 8; kc++) {
            int c0 = kc * 8 + (lane & 3);
            uint32_t a[2][4];
#pragma unroll
            for (int i = 0; i < 2; i++) {
                int r = ar0 + i * 16;
                a[i][0] = tf32r(Qs[r * KPQ + c0]);
                a[i][1] = tf32r(Qs[(r + 8) * KPQ + c0]);
                a[i][2] = tf32r(Qs[r * KPQ + c0 + 4]);
                a[i][3] = tf32r(Qs[(r + 8) * KPQ + c0 + 4]);
            }
#pragma unroll
            for (int j = 0; j < 8; j++) {
                int rn = bn0 + j * 8;
                uint32_t b2[2] = { tf32r(Ks[rn * KPQ + c0]), tf32r(Ks[rn * KPQ + c0 + 4]) };
                mma_t(acc[0][j], a[0], b2);
                mma_t(acc[1][j], a[1], b2);
            }
        }

        // ---- mask + exp2 + pack -> PV (per k16 step) ----
        const int t0g = it * 128;
#pragma unroll
        for (int st = 0; st < 4; st++) {
            uint32_t af0[4], af1[4];
#pragma unroll
            for (int i = 0; i < 2; i++) {
                uint32_t* af = i ? af1 : af0;
                int row = s0 + wm * 32 + i * 16 + (lane >> 2);
#pragma unroll
                for (int jj = 0; jj < 2; jj++) {
                    int j = st * 2 + jj;
                    const int* mp = mask + ((size_t)b * S_ + row) * S_ + t0g + wn * 64 + j * 8 + (lane & 3) * 2;
                    int2 m0v = *(const int2*)mp;
                    int2 m1v = *(const int2*)(mp + 8 * (size_t)S_);
                    uint32_t u00 = (m0v.x == 1) ? bfhi(fexp2(acc[i][j][0] * cf)) : 0u;
                    uint32_t u01 = (m0v.y == 1) ? bfhi(fexp2(acc[i][j][1] * cf)) : 0u;
                    uint32_t u10 = (m1v.x == 1) ? bfhi(fexp2(acc[i][j][2] * cf)) : 0u;
                    uint32_t u11 = (m1v.y == 1) ? bfhi(fexp2(acc[i][j][3] * cf)) : 0u;
                    rs4[i * 2 + 0] += __uint_as_float(u00) + __uint_as_float(u01);
                    rs4[i * 2 + 1] += __uint_as_float(u10) + __uint_as_float(u11);
                    af[jj * 2 + 0] = u01 | (u00 >> 16);
                    af[jj * 2 + 1] = u11 | (u10 >> 16);
                }
            }
            const int tb = wn * 64 + st * 16 + (lane & 3) * 2;
#pragma unroll
            for (int je = 0; je < 8; je++) {
                int e = je * 8 + (lane >> 2);
                uint32_t b2[2] = { *(const uint32_t*)&Vs[e * KPV + tb],
                                   *(const uint32_t*)&Vs[e * KPV + tb + 8] };
                mma_bf(acc2[0][je], af0, b2);
                mma_bf(acc2[1][je], af1, b2);
            }
        }
        __syncthreads();
        if (it + 2 < 16) {
            stage_k(s ? KOFF1 : KOFF0, (it + 2) * 128);
            stage_v(s ? VOFF1 : VOFF0, (it + 2) * 128);
            CPC();
        }
    }

    // ---- row sums: lane-reduce then atomic into smem ----
#pragma unroll
    for (int i = 0; i < 4; i++) {
        rs4[i] += __shfl_xor_sync(0xffffffffu, rs4[i], 1);
        rs4[i] += __shfl_xor_sync(0xffffffffu, rs4[i], 2);
    }
    if ((lane & 3) == 0) {
#pragma unroll
        for (int i = 0; i < 2; i++) {
            int r = wm * 32 + i * 16 + (lane >> 2);
            atomicAdd(&srow[r],     rs4[i * 2 + 0]);
            atomicAdd(&srow[r + 8], rs4[i * 2 + 1]);
        }
    }
    __syncthreads();

    // ---- cross-warp PV reduce (wn=1 -> smem, wn=0 adds) ----
    float* red = (float*)(sm + KOFF0);   // reuse k buffers: 4 * 32*64 f32 = 32KB
    if (wn == 1) {
#pragma unroll
        for (int i = 0; i < 2; i++)
#pragma unroll
            for (int je = 0; je < 8; je++) {
                int rl = wm * 32 + i * 16 + (lane >> 2);
                int cl = je * 8 + (lane & 3) * 2;
                *(float2*)&red[(size_t)rl * 64 + cl]       = make_float2(acc2[i][je][0], acc2[i][je][1]);
                *(float2*)&red[(size_t)(rl + 8) * 64 + cl] = make_float2(acc2[i][je][2], acc2[i][je][3]);
            }
    }
    __syncthreads();
    if (wn == 0) {
#pragma unroll
        for (int i = 0; i < 2; i++) {
            int rl0 = wm * 32 + i * 16 + (lane >> 2);
            float inv0 = 1.0f / srow[rl0];
            float inv1 = 1.0f / srow[rl0 + 8];
            int row = s0 + rl0;
#pragma unroll
            for (int je = 0; je < 8; je++) {
                int cl = je * 8 + (lane & 3) * 2;
                float2 o0 = *(float2*)&red[(size_t)rl0 * 64 + cl];
                float2 o1 = *(float2*)&red[(size_t)(rl0 + 8) * 64 + cl];
                float v00 = (acc2[i][je][0] + o0.x) * inv0;
                float v01 = (acc2[i][je][1] + o0.y) * inv0;
                float v10 = (acc2[i][je][2] + o1.x) * inv1;
                float v11 = (acc2[i][je][3] + o1.y) * inv1;
                size_t p0 = (((size_t)bh * S_ + row) * HD + cl) >> 1;
                size_t p1 = (((size_t)bh * S_ + row + 8) * HD + cl) >> 1;
                ((uint32_t*)Ohi)[p0] = pkbf(v00, v01);
                ((uint32_t*)Ohi)[p1] = pkbf(v10, v11);
                float r00 = v00 - __uint_as_float(bfhi(v00));
                float r01 = v01 - __uint_as_float(bfhi(v01));
                float r10 = v10 - __uint_as_float(bfhi(v10));
                float r11 = v11 - __uint_as_float(bfhi(v11));
                ((uint32_t*)Olo)[p0] = pkbf(r00, r01);
                ((uint32_t*)Olo)[p1] = pkbf(r10, r11);
            }
        }
    }
}

// ---------------- small utility kernels ----------------
__global__ __launch_bounds__(256)
void split_kernel(const float* __restrict__ X, uint16_t* __restrict__ Xhi, uint16_t* __restrict__ Xlo) {
    size_t i = (size_t)blockIdx.x * 256 + threadIdx.x;
    float2 v = ((const float2*)X)[i];
    ((uint32_t*)Xhi)[i] = pkbf(v.x, v.y);
    float rx = v.x - __uint_as_float(bfhi(v.x));
    float ry = v.y - __uint_as_float(bfhi(v.y));
    ((uint32_t*)Xlo)[i] = pkbf(rx, ry);
}

__global__ __launch_bounds__(256)
void transpose_split(const float* __restrict__ W, uint16_t* __restrict__ Whi, uint16_t* __restrict__ Wlo) {
    __shared__ float t[32][33];
    const int tx = threadIdx.x & 31, ty = threadIdx.x >> 5;
    const int bx = blockIdx.x * 32, by = blockIdx.y * 32;
#pragma unroll
    for (int j = 0; j < 32; j += 8) t[ty + j][tx] = W[(size_t)(by + ty + j) * DM + bx + tx];
    __syncthreads();
#pragma unroll
    for (int j = 0; j < 32; j += 8) {
        float v = t[tx][ty + j];
        size_t idx = (size_t)(bx + ty + j) * DM + by + tx;
        Whi[idx] = (uint16_t)(bfhi(v) >> 16);
        float rr = v - __uint_as_float(bfhi(v));
        Wlo[idx] = (uint16_t)(bfhi(rr) >> 16);
    }
}

// ---------------- launch ----------------
extern "C" void kernel_launch(void* const* d_in, const int* in_sizes, int n_in,
                              void* d_out, int out_size) {
    (void)in_sizes; (void)n_in; (void)out_size;
    const float* x    = (const float*)d_in[0];
    const int*   mask = (const int*)d_in[1];
    const float* W0   = (const float*)d_in[2];
    const float* b0   = (const float*)d_in[3];
    const float* W1   = (const float*)d_in[4];
    const float* b1   = (const float*)d_in[5];
    const float* W2   = (const float*)d_in[6];
    const float* b2   = (const float*)d_in[7];
    const float* Wo   = (const float*)d_in[8];
    const float* bo   = (const float*)d_in[9];
    float* out = (float*)d_out;

    float *q, *k;
    uint16_t *vt, *xs, *qs, *os, *wtb;
    cudaGetSymbolAddress((void**)&q,   g_q);
    cudaGetSymbolAddress((void**)&k,   g_k);
    cudaGetSymbolAddress((void**)&vt,  g_vt);
    cudaGetSymbolAddress((void**)&xs,  g_xs);
    cudaGetSymbolAddress((void**)&qs,  g_qs);
    cudaGetSymbolAddress((void**)&os,  g_os);
    cudaGetSymbolAddress((void**)&wtb, g_wtb);
    const size_t PLN = (size_t)MTOT * DM;
    const size_t WP  = (size_t)DM * DM;

    cudaFuncSetAttribute(gemm_bf<0>, cudaFuncAttributeMaxDynamicSharedMemorySize, DSMEM);
    cudaFuncSetAttribute(gemm_bf<1>, cudaFuncAttributeMaxDynamicSharedMemorySize, DSMEM);
    cudaFuncSetAttribute(gemm_bf<2>, cudaFuncAttributeMaxDynamicSharedMemorySize, DSMEM);
    cudaFuncSetAttribute(flash_attn, cudaFuncAttributeMaxDynamicSharedMemorySize, FSMEM);

    split_kernel<<<MTOT * DM / 512, 256>>>(x, xs, xs + PLN);
    transpose_split<<<dim3(32, 32), 256>>>(W0, wtb + 0 * 2 * WP, wtb + 0 * 2 * WP + WP);
    transpose_split<<<dim3(32, 32), 256>>>(W1, wtb + 1 * 2 * WP, wtb + 1 * 2 * WP + WP);
    transpose_split<<<dim3(32, 32), 256>>>(W2, wtb + 2 * 2 * WP, wtb + 2 * 2 * WP + WP);
    transpose_split<<<dim3(32, 32), 256>>>(Wo, wtb + 3 * 2 * WP, wtb + 3 * 2 * WP + WP);

    gemm_bf<2><<<dim3(8, 32), 256, DSMEM>>>(xs, xs + PLN, wtb + 0 * 2 * WP, wtb + 0 * 2 * WP + WP,
                                            b0, q, qs, qs + PLN);
    gemm_bf<0><<<dim3(8, 32), 256, DSMEM>>>(qs, qs + PLN, wtb + 1 * 2 * WP, wtb + 1 * 2 * WP + WP,
                                            b1, k, nullptr, nullptr);
    gemm_bf<1><<<dim3(8, 32), 256, DSMEM>>>(qs, qs + PLN, wtb + 2 * 2 * WP, wtb + 2 * 2 * WP + WP,
                                            b2, nullptr, vt, nullptr);
    flash_attn<<<dim3(16, 32), 256, FSMEM>>>(q, k, vt, mask, os, os + PLN);
    gemm_bf<0><<<dim3(8, 32), 256, DSMEM>>>(os, os + PLN, wtb + 3 * 2 * WP, wtb + 3 * 2 * WP + WP,
                                            bo, out, nullptr, nullptr);
}

// round 8
// speedup vs baseline: 2.2743x; 1.2238x over previous
#include <cuda_runtime.h>
#include <cstdint>

#define B_       2
#define S_       2048
#define DM       1024
#define H_       16
#define HD       64
#define BH_      32
#define MTOT     4096
#define L2E      1.4426950408889634f
#define SCALE_   0.125f
#define KP2      24                  // bf16 smem row pad (halves), dense GEMM
#define KPQ      68                  // q/k smem row pad (floats), flash
#define KPV2     72                  // v smem row pad (halves), flash

// ---------------- scratch (device globals) ----------------
__device__ __align__(128) float    g_q [MTOT * DM];            // q fp32 (tf32-prerounded)
__device__ __align__(128) float    g_k [MTOT * DM];            // k fp32 (tf32-prerounded)
__device__ __align__(128) uint16_t g_vt[BH_ * HD * S_];        // V^T bf16 per head [bh][e][t]
__device__ __align__(128) uint16_t g_xs[2][MTOT * DM];         // x  bf16 hi/lo planes
__device__ __align__(128) uint16_t g_qs[2][MTOT * DM];         // q  bf16 hi/lo planes
__device__ __align__(128) uint16_t g_os[2][MTOT * DM];         // attn-out bf16 hi/lo planes
__device__ __align__(128) uint16_t g_wtb[4][2][DM * DM];       // W^T bf16 hi/lo planes [n][k]

// single extern shared array (one type everywhere)
extern __shared__ char smraw[];

// ---------------- helpers ----------------
__device__ __forceinline__ uint32_t smem_u32(const void* p) {
    uint32_t r;
    asm("{ .reg .u64 t; cvta.to.shared.u64 t, %1; cvt.u32.u64 %0, t; }" : "=r"(r) : "l"(p));
    return r;
}
__device__ __forceinline__ uint32_t tf32r(float x) {
    uint32_t u; asm("cvt.rna.tf32.f32 %0, %1;" : "=r"(u) : "f"(x)); return u;
}
__device__ __forceinline__ uint32_t bfhi(float x) {   // bf16 RNE, as fp32 bits (low16=0)
    uint32_t u = __float_as_uint(x);
    return (u + 0x7fffu + ((u >> 16) & 1u)) & 0xffff0000u;
}
__device__ __forceinline__ uint32_t pkbf(float lo, float hi) {
    return bfhi(hi) | (bfhi(lo) >> 16);
}
__device__ __forceinline__ float ex2a(float x) {       // MUFU exp2
    float r; asm("ex2.approx.ftz.f32 %0, %1;" : "=f"(r) : "f"(x)); return r;
}
__device__ __forceinline__ uint32_t cvtbf2(float lo, float hi) {  // 1-instr bf16x2 pack
    uint32_t r; asm("cvt.rn.bf16x2.f32 %0, %1, %2;" : "=r"(r) : "f"(hi), "f"(lo)); return r;
}
__device__ __forceinline__ void cp16(uint32_t d, const void* s) {
    asm volatile("cp.async.ca.shared.global [%0], [%1], 16;" :: "r"(d), "l"(s));
}
#define CPC()  asm volatile("cp.async.commit_group;")
#define CPW1() asm volatile("cp.async.wait_group 1;")
#define CPW0() asm volatile("cp.async.wait_group 0;")

__device__ __forceinline__ void mma_t(float* d, const uint32_t* a, const uint32_t* b) {
    asm volatile("mma.sync.aligned.m16n8k8.row.col.f32.tf32.tf32.f32 "
                 "{%0,%1,%2,%3},{%4,%5,%6,%7},{%8,%9},{%0,%1,%2,%3};"
                 : "+f"(d[0]), "+f"(d[1]), "+f"(d[2]), "+f"(d[3])
                 : "r"(a[0]), "r"(a[1]), "r"(a[2]), "r"(a[3]), "r"(b[0]), "r"(b[1]));
}
__device__ __forceinline__ void mma_bf(float* d, const uint32_t* a, const uint32_t* b) {
    asm volatile("mma.sync.aligned.m16n8k16.row.col.f32.bf16.bf16.f32 "
                 "{%0,%1,%2,%3},{%4,%5,%6,%7},{%8,%9},{%0,%1,%2,%3};"
                 : "+f"(d[0]), "+f"(d[1]), "+f"(d[2]), "+f"(d[3])
                 : "r"(a[0]), "r"(a[1]), "r"(a[2]), "r"(a[3]), "r"(b[0]), "r"(b[1]));
}

// Stage [128 x 16] bf16 tile (ld halves) into smem [128][KP2]
__device__ __forceinline__ void stage_bf(uint32_t sb, const uint16_t* __restrict__ g, int ld, int tid) {
    int r = tid >> 1, s = tid & 1;
    cp16(sb + (uint32_t)(r * KP2 + s * 8) * 2u, g + (size_t)r * ld + s * 8);
}

// bf16 3-term warp step: [64 x 32] over one k16 (MF=4, NF=4)
__device__ __forceinline__ void wstep_bf(const uint16_t* Ah, const uint16_t* Al,
                                         const uint16_t* Bh, const uint16_t* Bl,
                                         int ar0, int bn0, int c2, float (*acc)[4][4]) {
    uint32_t ah[4][4], al[4][4];
#pragma unroll
    for (int i = 0; i < 4; i++) {
        int r = ar0 + i * 16;
        ah[i][0] = *(const uint32_t*)&Ah[r * KP2 + c2];
        ah[i][1] = *(const uint32_t*)&Ah[(r + 8) * KP2 + c2];
        ah[i][2] = *(const uint32_t*)&Ah[r * KP2 + c2 + 8];
        ah[i][3] = *(const uint32_t*)&Ah[(r + 8) * KP2 + c2 + 8];
        al[i][0] = *(const uint32_t*)&Al[r * KP2 + c2];
        al[i][1] = *(const uint32_t*)&Al[(r + 8) * KP2 + c2];
        al[i][2] = *(const uint32_t*)&Al[r * KP2 + c2 + 8];
        al[i][3] = *(const uint32_t*)&Al[(r + 8) * KP2 + c2 + 8];
    }
#pragma unroll
    for (int j = 0; j < 4; j++) {
        int n = bn0 + j * 8;
        uint32_t bh2[2] = { *(const uint32_t*)&Bh[n * KP2 + c2], *(const uint32_t*)&Bh[n * KP2 + c2 + 8] };
        uint32_t bl2[2] = { *(const uint32_t*)&Bl[n * KP2 + c2], *(const uint32_t*)&Bl[n * KP2 + c2 + 8] };
#pragma unroll
        for (int i = 0; i < 4; i++) {
            mma_bf(acc[i][j], ah[i], bh2);
            mma_bf(acc[i][j], al[i], bh2);
            mma_bf(acc[i][j], ah[i], bl2);
        }
    }
}

// ---------------- dense (bf16 3-term): C = relu(A @ W + bias), tile 128x128 ----------------
// MODE 0: fp32 C.  MODE 1: bf16 V^T per head into Chi.
// MODE 2: tf32-rounded fp32 C + exact bf16 planes.  MODE 3: tf32-rounded fp32 C only.
#define DSMEM (8 * 128 * KP2 * 2)
template<int MODE>
__global__ __launch_bounds__(256)
void gemm_bf(const uint16_t* __restrict__ Ahg, const uint16_t* __restrict__ Alg,
             const uint16_t* __restrict__ Bhg, const uint16_t* __restrict__ Blg,
             const float* __restrict__ bias, float* __restrict__ C,
             uint16_t* __restrict__ Chi, uint16_t* __restrict__ Clo) {
    uint16_t* sm = (uint16_t*)smraw;
    const int tid = threadIdx.x, lane = tid & 31, wid = tid >> 5;
    const int wm = wid & 1, wn = wid >> 1;
    const int m0 = blockIdx.y * 128, n0 = blockIdx.x * 128;
    const uint32_t sb = smem_u32(sm);
    float acc[4][4][4];
#pragma unroll
    for (int i = 0; i < 4; i++)
#pragma unroll
        for (int j = 0; j < 4; j++)
#pragma unroll
            for (int e = 0; e < 4; e++) acc[i][j][e] = 0.0f;

    const uint16_t* Ah = Ahg + (size_t)m0 * DM;
    const uint16_t* Al = Alg + (size_t)m0 * DM;
    const uint16_t* Bh = Bhg + (size_t)n0 * DM;
    const uint16_t* Bl = Blg + (size_t)n0 * DM;
    const int NT = DM / 16;   // 64

#pragma unroll
    for (int s = 0; s < 2; s++) {
        stage_bf(sb + (uint32_t)((s * 4 + 0) * 128 * KP2) * 2u, Ah + s * 16, DM, tid);
        stage_bf(sb + (uint32_t)((s * 4 + 1) * 128 * KP2) * 2u, Al + s * 16, DM, tid);
        stage_bf(sb + (uint32_t)((s * 4 + 2) * 128 * KP2) * 2u, Bh + s * 16, DM, tid);
        stage_bf(sb + (uint32_t)((s * 4 + 3) * 128 * KP2) * 2u, Bl + s * 16, DM, tid);
        CPC();
    }
    const int ar0 = wm * 64 + (lane >> 2);
    const int bn0 = wn * 32 + (lane >> 2);
    const int c2 = (lane & 3) * 2;
    for (int i = 0; i < NT; i++) {
        int s = i & 1;
        if (i >= NT - 2) { CPW0(); } else { CPW1(); }
        __syncthreads();
        wstep_bf(sm + (s * 4 + 0) * 128 * KP2, sm + (s * 4 + 1) * 128 * KP2,
                 sm + (s * 4 + 2) * 128 * KP2, sm + (s * 4 + 3) * 128 * KP2,
                 ar0, bn0, c2, acc);
        __syncthreads();
        if (i + 2 < NT) {
            stage_bf(sb + (uint32_t)((s * 4 + 0) * 128 * KP2) * 2u, Ah + (i + 2) * 16, DM, tid);
            stage_bf(sb + (uint32_t)((s * 4 + 1) * 128 * KP2) * 2u, Al + (i + 2) * 16, DM, tid);
            stage_bf(sb + (uint32_t)((s * 4 + 2) * 128 * KP2) * 2u, Bh + (i + 2) * 16, DM, tid);
            stage_bf(sb + (uint32_t)((s * 4 + 3) * 128 * KP2) * 2u, Bl + (i + 2) * 16, DM, tid);
            CPC();
        }
    }
#pragma unroll
    for (int i = 0; i < 4; i++)
#pragma unroll
        for (int j = 0; j < 4; j++) {
            int m = m0 + wm * 64 + i * 16 + (lane >> 2);
            int n = n0 + wn * 32 + j * 8 + (lane & 3) * 2;
            float bz0 = bias[n], bz1 = bias[n + 1];
            float v00 = fmaxf(acc[i][j][0] + bz0, 0.0f), v01 = fmaxf(acc[i][j][1] + bz1, 0.0f);
            float v10 = fmaxf(acc[i][j][2] + bz0, 0.0f), v11 = fmaxf(acc[i][j][3] + bz1, 0.0f);
            if (MODE == 0) {
                *(float2*)&C[(size_t)m * DM + n]       = make_float2(v00, v01);
                *(float2*)&C[(size_t)(m + 8) * DM + n] = make_float2(v10, v11);
            }
            if (MODE == 2 || MODE == 3) {   // tf32-preround for the flash QK consumers
                *(float2*)&C[(size_t)m * DM + n] =
                    make_float2(__uint_as_float(tf32r(v00)), __uint_as_float(tf32r(v01)));
                *(float2*)&C[(size_t)(m + 8) * DM + n] =
                    make_float2(__uint_as_float(tf32r(v10)), __uint_as_float(tf32r(v11)));
            }
            if (MODE == 2) {                // exact planes for downstream dense GEMMs
                size_t p0 = ((size_t)m * DM + n) >> 1, p1 = ((size_t)(m + 8) * DM + n) >> 1;
                ((uint32_t*)Chi)[p0] = pkbf(v00, v01);
                ((uint32_t*)Chi)[p1] = pkbf(v10, v11);
                float r00 = v00 - __uint_as_float(bfhi(v00));
                float r01 = v01 - __uint_as_float(bfhi(v01));
                float r10 = v10 - __uint_as_float(bfhi(v10));
                float r11 = v11 - __uint_as_float(bfhi(v11));
                ((uint32_t*)Clo)[p0] = pkbf(r00, r01);
                ((uint32_t*)Clo)[p1] = pkbf(r10, r11);
            }
            if (MODE == 1) {
                int bb = m >> 11, t = m & 2047, hh = n >> 6, e = n & 63;
                size_t base = ((size_t)(bb * 16 + hh) * 64 + e) * S_;
                Chi[base + t]          = (uint16_t)(bfhi(v00) >> 16);
                Chi[base + S_ + t]     = (uint16_t)(bfhi(v01) >> 16);
                Chi[base + t + 8]      = (uint16_t)(bfhi(v10) >> 16);
                Chi[base + S_ + t + 8] = (uint16_t)(bfhi(v11) >> 16);
            }
        }
}

// ---------------- fused flash attention (64-row s-tile, 64-col t-iters, 2 CTAs/SM) ----------
// smem: q[64][KPQ] f32 | k x2 [64][KPQ] f32 | v x2 [64][KPV2] bf16 | srow[64] f32
#define QOFF   0
#define KOFF0  17408
#define KOFF1  34816
#define VOFF0  52224
#define VOFF1  61440
#define SROWO  70656
#define FSMEM  70912
#define TT     64
#define ITERS  (S_ / TT)   // 32
__global__ __launch_bounds__(256, 2)
void flash_attn(const float* __restrict__ q, const float* __restrict__ k,
                const uint16_t* __restrict__ vtb, const int* __restrict__ mask,
                uint16_t* __restrict__ Ohi, uint16_t* __restrict__ Olo) {
    char* sm = smraw;
    const int tid = threadIdx.x, lane = tid & 31, wid = tid >> 5;
    const int wn = wid & 1, wm = wid >> 1;          // 2 t-col warps x 4 m-row warps
    const int bh = blockIdx.y, b = bh >> 4, h = bh & 15;
    const int s0 = blockIdx.x * 64;
    const uint32_t sb = smem_u32(sm);
    float* srow = (float*)(sm + SROWO);
    if (tid < 64) srow[tid] = 0.0f;

    const float* qg = q + ((size_t)b * S_ + s0) * DM + h * HD;
    const float* kg = k + (size_t)b * S_ * DM + h * HD;
    const uint16_t* vg = vtb + (size_t)bh * HD * S_;

    // stage q once: [64][64] f32
#pragma unroll
    for (int p = 0; p < 4; p++) {
        int id = tid + p * 256, r = id >> 4, c = id & 15;
        cp16(sb + QOFF + (uint32_t)(r * KPQ + c * 4) * 4u, qg + (size_t)r * DM + c * 4);
    }
    auto stage_k = [&](uint32_t koff, int t0) {
        const float* src = kg + (size_t)t0 * DM;
#pragma unroll
        for (int p = 0; p < 4; p++) {
            int id = tid + p * 256, r = id >> 4, c = id & 15;
            cp16(sb + koff + (uint32_t)(r * KPQ + c * 4) * 4u, src + (size_t)r * DM + c * 4);
        }
    };
    auto stage_v = [&](uint32_t voff, int t0) {
#pragma unroll
        for (int p = 0; p < 2; p++) {
            int id = tid + p * 256, e = id >> 3, c = id & 7;
            cp16(sb + voff + (uint32_t)(e * KPV2 + c * 8) * 2u, vg + (size_t)e * S_ + t0 + c * 8);
        }
    };
    stage_k(KOFF0, 0);  stage_v(VOFF0, 0);  CPC();
    stage_k(KOFF1, TT); stage_v(VOFF1, TT); CPC();

    float acc2[8][4];
#pragma unroll
    for (int j = 0; j < 8; j++)
#pragma unroll
        for (int e = 0; e < 4; e++) acc2[j][e] = 0.0f;
    float rs2[2] = {0.f, 0.f};

    const float* Qs = (const float*)(sm + QOFF);
    const int ar0 = wm * 16 + (lane >> 2);
    const int bn0 = wn * 32 + (lane >> 2);
    const int row = s0 + wm * 16 + (lane >> 2);
    const float cf = SCALE_ * L2E;

    for (int it = 0; it < ITERS; it++) {
        const int s = it & 1;
        if (it >= ITERS - 2) { CPW0(); } else { CPW1(); }
        __syncthreads();
        const float*    Ks = (const float*)(sm + (s ? KOFF1 : KOFF0));
        const uint16_t* Vs = (const uint16_t*)(sm + (s ? VOFF1 : VOFF0));

        // ---- QK: warp tile [16 m x 32 t], tf32 (operands pre-rounded) ----
        float acc[4][4];
#pragma unroll
        for (int j = 0; j < 4; j++)
#pragma unroll
            for (int e = 0; e < 4; e++) acc[j][e] = 0.0f;
#pragma unroll
        for (int kc = 0; kc < 8; kc++) {
            int c0 = kc * 8 + (lane & 3);
            uint32_t a[4];
            a[0] = __float_as_uint(Qs[ar0 * KPQ + c0]);
            a[1] = __float_as_uint(Qs[(ar0 + 8) * KPQ + c0]);
            a[2] = __float_as_uint(Qs[ar0 * KPQ + c0 + 4]);
            a[3] = __float_as_uint(Qs[(ar0 + 8) * KPQ + c0 + 4]);
#pragma unroll
            for (int j = 0; j < 4; j++) {
                int rn = bn0 + j * 8;
                uint32_t b2[2] = { __float_as_uint(Ks[rn * KPQ + c0]),
                                   __float_as_uint(Ks[rn * KPQ + c0 + 4]) };
                mma_t(acc[j], a, b2);
            }
        }

        // ---- mask + MUFU exp2 + 1-instr pack -> PV (per k16 step) ----
        const int t0g = it * TT;
#pragma unroll
        for (int st = 0; st < 2; st++) {
            uint32_t af[4];
#pragma unroll
            for (int jj = 0; jj < 2; jj++) {
                int j = st * 2 + jj;
                const int* mp = mask + ((size_t)b * S_ + row) * S_ + t0g + wn * 32 + j * 8 + (lane & 3) * 2;
                int2 m0v = *(const int2*)mp;
                int2 m1v = *(const int2*)(mp + 8 * (size_t)S_);
                float e00 = ex2a((m0v.x == 1) ? acc[j][0] * cf : -12000.0f);
                float e01 = ex2a((m0v.y == 1) ? acc[j][1] * cf : -12000.0f);
                float e10 = ex2a((m1v.x == 1) ? acc[j][2] * cf : -12000.0f);
                float e11 = ex2a((m1v.y == 1) ? acc[j][3] * cf : -12000.0f);
                rs2[0] += e00 + e01;
                rs2[1] += e10 + e11;
                af[jj * 2 + 0] = cvtbf2(e00, e01);
                af[jj * 2 + 1] = cvtbf2(e10, e11);
            }
            const int tb = wn * 32 + st * 16 + (lane & 3) * 2;
#pragma unroll
            for (int je = 0; je < 8; je++) {
                int e = je * 8 + (lane >> 2);
                uint32_t b2[2] = { *(const uint32_t*)&Vs[e * KPV2 + tb],
                                   *(const uint32_t*)&Vs[e * KPV2 + tb + 8] };
                mma_bf(acc2[je], af, b2);
            }
        }
        __syncthreads();
        if (it + 2 < ITERS) {
            stage_k(s ? KOFF1 : KOFF0, (it + 2) * TT);
            stage_v(s ? VOFF1 : VOFF0, (it + 2) * TT);
            CPC();
        }
    }

    // ---- row sums: lane-quad reduce then atomic into smem ----
#pragma unroll
    for (int i = 0; i < 2; i++) {
        rs2[i] += __shfl_xor_sync(0xffffffffu, rs2[i], 1);
        rs2[i] += __shfl_xor_sync(0xffffffffu, rs2[i], 2);
    }
    if ((lane & 3) == 0) {
        atomicAdd(&srow[wm * 16 + (lane >> 2)],     rs2[0]);
        atomicAdd(&srow[wm * 16 + (lane >> 2) + 8], rs2[1]);
    }
    __syncthreads();

    // ---- cross-warp PV reduce (wn=1 -> smem, wn=0 adds + writes) ----
    float* red = (float*)(sm + KOFF0);   // 64x64 f32 = 16KB, reuse k buffer
    if (wn == 1) {
#pragma unroll
        for (int je = 0; je < 8; je++) {
            int rl = wm * 16 + (lane >> 2);
            int cl = je * 8 + (lane & 3) * 2;
            *(float2*)&red[(size_t)rl * 64 + cl]       = make_float2(acc2[je][0], acc2[je][1]);
            *(float2*)&red[(size_t)(rl + 8) * 64 + cl] = make_float2(acc2[je][2], acc2[je][3]);
        }
    }
    __syncthreads();
    if (wn == 0) {
        int rl0 = wm * 16 + (lane >> 2);
        float inv0 = 1.0f / srow[rl0];
        float inv1 = 1.0f / srow[rl0 + 8];
        int rowg = s0 + rl0;
#pragma unroll
        for (int je = 0; je < 8; je++) {
            int cl = je * 8 + (lane & 3) * 2;
            float2 o0 = *(float2*)&red[(size_t)rl0 * 64 + cl];
            float2 o1 = *(float2*)&red[(size_t)(rl0 + 8) * 64 + cl];
            float v00 = (acc2[je][0] + o0.x) * inv0;
            float v01 = (acc2[je][1] + o0.y) * inv0;
            float v10 = (acc2[je][2] + o1.x) * inv1;
            float v11 = (acc2[je][3] + o1.y) * inv1;
            size_t p0 = (((size_t)bh * S_ + rowg) * HD + cl) >> 1;
            size_t p1 = (((size_t)bh * S_ + rowg + 8) * HD + cl) >> 1;
            ((uint32_t*)Ohi)[p0] = pkbf(v00, v01);
            ((uint32_t*)Ohi)[p1] = pkbf(v10, v11);
            float r00 = v00 - __uint_as_float(bfhi(v00));
            float r01 = v01 - __uint_as_float(bfhi(v01));
            float r10 = v10 - __uint_as_float(bfhi(v10));
            float r11 = v11 - __uint_as_float(bfhi(v11));
            ((uint32_t*)Olo)[p0] = pkbf(r00, r01);
            ((uint32_t*)Olo)[p1] = pkbf(r10, r11);
        }
    }
}

// ---------------- small utility kernels ----------------
__global__ __launch_bounds__(256)
void split_kernel(const float* __restrict__ X, uint16_t* __restrict__ Xhi, uint16_t* __restrict__ Xlo) {
    size_t i = (size_t)blockIdx.x * 256 + threadIdx.x;
    float2 v = ((const float2*)X)[i];
    ((uint32_t*)Xhi)[i] = pkbf(v.x, v.y);
    float rx = v.x - __uint_as_float(bfhi(v.x));
    float ry = v.y - __uint_as_float(bfhi(v.y));
    ((uint32_t*)Xlo)[i] = pkbf(rx, ry);
}

__global__ __launch_bounds__(256)
void transpose_split(const float* __restrict__ W, uint16_t* __restrict__ Whi, uint16_t* __restrict__ Wlo) {
    __shared__ float t[32][33];
    const int tx = threadIdx.x & 31, ty = threadIdx.x >> 5;
    const int bx = blockIdx.x * 32, by = blockIdx.y * 32;
#pragma unroll
    for (int j = 0; j < 32; j += 8) t[ty + j][tx] = W[(size_t)(by + ty + j) * DM + bx + tx];
    __syncthreads();
#pragma unroll
    for (int j = 0; j < 32; j += 8) {
        float v = t[tx][ty + j];
        size_t idx = (size_t)(bx + ty + j) * DM + by + tx;
        Whi[idx] = (uint16_t)(bfhi(v) >> 16);
        float rr = v - __uint_as_float(bfhi(v));
        Wlo[idx] = (uint16_t)(bfhi(rr) >> 16);
    }
}

// ---------------- launch ----------------
extern "C" void kernel_launch(void* const* d_in, const int* in_sizes, int n_in,
                              void* d_out, int out_size) {
    (void)in_sizes; (void)n_in; (void)out_size;
    const float* x    = (const float*)d_in[0];
    const int*   mask = (const int*)d_in[1];
    const float* W0   = (const float*)d_in[2];
    const float* b0   = (const float*)d_in[3];
    const float* W1   = (const float*)d_in[4];
    const float* b1   = (const float*)d_in[5];
    const float* W2   = (const float*)d_in[6];
    const float* b2   = (const float*)d_in[7];
    const float* Wo   = (const float*)d_in[8];
    const float* bo   = (const float*)d_in[9];
    float* out = (float*)d_out;

    float *q, *k;
    uint16_t *vt, *xs, *qs, *os, *wtb;
    cudaGetSymbolAddress((void**)&q,   g_q);
    cudaGetSymbolAddress((void**)&k,   g_k);
    cudaGetSymbolAddress((void**)&vt,  g_vt);
    cudaGetSymbolAddress((void**)&xs,  g_xs);
    cudaGetSymbolAddress((void**)&qs,  g_qs);
    cudaGetSymbolAddress((void**)&os,  g_os);
    cudaGetSymbolAddress((void**)&wtb, g_wtb);
    const size_t PLN = (size_t)MTOT * DM;
    const size_t WP  = (size_t)DM * DM;

    cudaFuncSetAttribute(gemm_bf<0>, cudaFuncAttributeMaxDynamicSharedMemorySize, DSMEM);
    cudaFuncSetAttribute(gemm_bf<1>, cudaFuncAttributeMaxDynamicSharedMemorySize, DSMEM);
    cudaFuncSetAttribute(gemm_bf<2>, cudaFuncAttributeMaxDynamicSharedMemorySize, DSMEM);
    cudaFuncSetAttribute(gemm_bf<3>, cudaFuncAttributeMaxDynamicSharedMemorySize, DSMEM);
    cudaFuncSetAttribute(flash_attn, cudaFuncAttributeMaxDynamicSharedMemorySize, FSMEM);

    split_kernel<<<MTOT * DM / 512, 256>>>(x, xs, xs + PLN);
    transpose_split<<<dim3(32, 32), 256>>>(W0, wtb + 0 * 2 * WP, wtb + 0 * 2 * WP + WP);
    transpose_split<<<dim3(32, 32), 256>>>(W1, wtb + 1 * 2 * WP, wtb + 1 * 2 * WP + WP);
    transpose_split<<<dim3(32, 32), 256>>>(W2, wtb + 2 * 2 * WP, wtb + 2 * 2 * WP + WP);
    transpose_split<<<dim3(32, 32), 256>>>(Wo, wtb + 3 * 2 * WP, wtb + 3 * 2 * WP + WP);

    gemm_bf<2><<<dim3(8, 32), 256, DSMEM>>>(xs, xs + PLN, wtb + 0 * 2 * WP, wtb + 0 * 2 * WP + WP,
                                            b0, q, qs, qs + PLN);
    gemm_bf<3><<<dim3(8, 32), 256, DSMEM>>>(qs, qs + PLN, wtb + 1 * 2 * WP, wtb + 1 * 2 * WP + WP,
                                            b1, k, nullptr, nullptr);
    gemm_bf<1><<<dim3(8, 32), 256, DSMEM>>>(qs, qs + PLN, wtb + 2 * 2 * WP, wtb + 2 * 2 * WP + WP,
                                            b2, nullptr, vt, nullptr);
    flash_attn<<<dim3(32, 32), 256, FSMEM>>>(q, k, vt, mask, os, os + PLN);
    gemm_bf<0><<<dim3(8, 32), 256, DSMEM>>>(os, os + PLN, wtb + 3 * 2 * WP, wtb + 3 * 2 * WP + WP,
                                            bo, out, nullptr, nullptr);
}

// round 9
// speedup vs baseline: 2.9325x; 1.2894x over previous
#include <cuda_runtime.h>
#include <cstdint>

#define B_       2
#define S_       2048
#define DM       1024
#define H_       16
#define HD       64
#define BH_      32
#define MTOT     4096
#define L2E      1.4426950408889634f
#define SCALE_   0.125f
#define KP2      24                  // bf16 smem row pad (halves), dense GEMM
#define KPQ      68                  // q/k smem row pad (floats), flash
#define KPV2     72                  // v smem row pad (halves), flash

// ---------------- scratch (device globals) ----------------
__device__ __align__(128) float    g_q [MTOT * DM];            // q fp32 (tf32-prerounded)
__device__ __align__(128) float    g_k [MTOT * DM];            // k fp32 (tf32-prerounded)
__device__ __align__(128) uint16_t g_vt[BH_ * HD * S_];        // V^T bf16 per head [bh][e][t]
__device__ __align__(128) uint16_t g_xs[2][MTOT * DM];         // x  bf16 hi/lo planes
__device__ __align__(128) uint16_t g_qs[2][MTOT * DM];         // q  bf16 hi/lo planes
__device__ __align__(128) uint16_t g_os[2][MTOT * DM];         // attn-out bf16 hi/lo planes
__device__ __align__(128) uint16_t g_wtb[4][2][DM * DM];       // W^T bf16 hi/lo planes [n][k]
__device__ __align__(128) uint32_t g_mp[B_ * S_ * (S_ / 32)];  // packed mask bits, 1MB

// single extern shared array (one type everywhere)
extern __shared__ char smraw[];

// ---------------- helpers ----------------
__device__ __forceinline__ uint32_t smem_u32(const void* p) {
    uint32_t r;
    asm("{ .reg .u64 t; cvta.to.shared.u64 t, %1; cvt.u32.u64 %0, t; }" : "=r"(r) : "l"(p));
    return r;
}
__device__ __forceinline__ uint32_t tf32r(float x) {
    uint32_t u; asm("cvt.rna.tf32.f32 %0, %1;" : "=r"(u) : "f"(x)); return u;
}
__device__ __forceinline__ uint32_t bfhi(float x) {   // bf16 RNE, as fp32 bits (low16=0)
    uint32_t u = __float_as_uint(x);
    return (u + 0x7fffu + ((u >> 16) & 1u)) & 0xffff0000u;
}
__device__ __forceinline__ uint32_t pkbf(float lo, float hi) {
    return bfhi(hi) | (bfhi(lo) >> 16);
}
__device__ __forceinline__ float ex2a(float x) {       // MUFU exp2
    float r; asm("ex2.approx.ftz.f32 %0, %1;" : "=f"(r) : "f"(x)); return r;
}
__device__ __forceinline__ uint32_t cvtbf2(float lo, float hi) {  // 1-instr bf16x2 pack
    uint32_t r; asm("cvt.rn.bf16x2.f32 %0, %1, %2;" : "=r"(r) : "f"(hi), "f"(lo)); return r;
}
__device__ __forceinline__ void cp16(uint32_t d, const void* s) {
    asm volatile("cp.async.ca.shared.global [%0], [%1], 16;" :: "r"(d), "l"(s));
}
#define CPC()  asm volatile("cp.async.commit_group;")
#define CPW2() asm volatile("cp.async.wait_group 2;")
#define CPW1() asm volatile("cp.async.wait_group 1;")
#define CPW0() asm volatile("cp.async.wait_group 0;")

#define LDSM4(r, addr) \
    asm volatile("ldmatrix.sync.aligned.m8n8.x4.shared.b16 {%0,%1,%2,%3}, [%4];" \
                 : "=r"((r)[0]), "=r"((r)[1]), "=r"((r)[2]), "=r"((r)[3]) : "r"(addr))

__device__ __forceinline__ void mma_t(float* d, const uint32_t* a, const uint32_t* b) {
    asm volatile("mma.sync.aligned.m16n8k8.row.col.f32.tf32.tf32.f32 "
                 "{%0,%1,%2,%3},{%4,%5,%6,%7},{%8,%9},{%0,%1,%2,%3};"
                 : "+f"(d[0]), "+f"(d[1]), "+f"(d[2]), "+f"(d[3])
                 : "r"(a[0]), "r"(a[1]), "r"(a[2]), "r"(a[3]), "r"(b[0]), "r"(b[1]));
}
__device__ __forceinline__ void mma_bf(float* d, const uint32_t* a, const uint32_t* b) {
    asm volatile("mma.sync.aligned.m16n8k16.row.col.f32.bf16.bf16.f32 "
                 "{%0,%1,%2,%3},{%4,%5,%6,%7},{%8,%9},{%0,%1,%2,%3};"
                 : "+f"(d[0]), "+f"(d[1]), "+f"(d[2]), "+f"(d[3])
                 : "r"(a[0]), "r"(a[1]), "r"(a[2]), "r"(a[3]), "r"(b[0]), "r"(b[1]));
}

// Stage [128 x 16] bf16 tile (ld halves) into smem [128][KP2]
__device__ __forceinline__ void stage_bf(uint32_t sb, const uint16_t* __restrict__ g, int ld, int tid) {
    int r = tid >> 1, s = tid & 1;
    cp16(sb + (uint32_t)(r * KP2 + s * 8) * 2u, g + (size_t)r * ld + s * 8);
}

// ---------------- dense (bf16 3-term, ldmatrix): C = relu(A @ W + bias), 128x128 ----------
// MODE 0: fp32 C.  MODE 1: bf16 V^T per head into Chi.
// MODE 2: tf32-rounded fp32 C + exact bf16 planes.  MODE 3: tf32-rounded fp32 C only.
#define PLSZ   (128 * KP2 * 2)        // 6144 B per plane
#define STSZ   (4 * PLSZ)             // 24576 B per stage
#define DSMEM  (2 * STSZ)
template<int MODE>
__global__ __launch_bounds__(256)
void gemm_bf(const uint16_t* __restrict__ Ahg, const uint16_t* __restrict__ Alg,
             const uint16_t* __restrict__ Bhg, const uint16_t* __restrict__ Blg,
             const float* __restrict__ bias, float* __restrict__ C,
             uint16_t* __restrict__ Chi, uint16_t* __restrict__ Clo) {
    const int tid = threadIdx.x, lane = tid & 31, wid = tid >> 5;
    const int wm = wid & 1, wn = wid >> 1;
    const int m0 = blockIdx.y * 128, n0 = blockIdx.x * 128;
    const uint32_t sb = smem_u32(smraw);
    float acc[4][4][4];
#pragma unroll
    for (int i = 0; i < 4; i++)
#pragma unroll
        for (int j = 0; j < 4; j++)
#pragma unroll
            for (int e = 0; e < 4; e++) acc[i][j][e] = 0.0f;

    const uint16_t* Ah = Ahg + (size_t)m0 * DM;
    const uint16_t* Al = Alg + (size_t)m0 * DM;
    const uint16_t* Bh = Bhg + (size_t)n0 * DM;
    const uint16_t* Bl = Blg + (size_t)n0 * DM;
    const int NT = DM / 16;   // 64

#pragma unroll
    for (int s = 0; s < 2; s++) {
        stage_bf(sb + s * STSZ + 0 * PLSZ, Ah + s * 16, DM, tid);
        stage_bf(sb + s * STSZ + 1 * PLSZ, Al + s * 16, DM, tid);
        stage_bf(sb + s * STSZ + 2 * PLSZ, Bh + s * 16, DM, tid);
        stage_bf(sb + s * STSZ + 3 * PLSZ, Bl + s * 16, DM, tid);
        CPC();
    }
    // ldmatrix base addresses (stage 0)
    const uint32_t aH0 = sb + (uint32_t)(((wm * 64 + (lane & 15)) * KP2 + ((lane >> 4) & 1) * 8) * 2);
    const uint32_t bH0 = sb + 2 * PLSZ +
        (uint32_t)(((wn * 32 + ((lane >> 4) & 1) * 8 + (lane & 7)) * KP2 + ((lane >> 3) & 1) * 8) * 2);

    for (int i = 0; i < NT; i++) {
        int s = i & 1;
        if (i >= NT - 2) { CPW0(); } else { CPW1(); }
        __syncthreads();
        const uint32_t aH = aH0 + s * STSZ, aL = aH + PLSZ;
        const uint32_t bHa = bH0 + s * STSZ, bLa = bHa + PLSZ;
        uint32_t bhf[2][4], blf[2][4];
        LDSM4(bhf[0], bHa); LDSM4(bhf[1], bHa + 768);
        LDSM4(blf[0], bLa); LDSM4(blf[1], bLa + 768);
#pragma unroll
        for (int ii = 0; ii < 4; ii++) {
            uint32_t ahf[4], alf[4];
            LDSM4(ahf, aH + ii * 768);
            LDSM4(alf, aL + ii * 768);
#pragma unroll
            for (int j = 0; j < 4; j++) {
                int p = j >> 1, o = (j & 1) * 2;
                uint32_t b2h[2] = { bhf[p][o], bhf[p][o + 1] };
                uint32_t b2l[2] = { blf[p][o], blf[p][o + 1] };
                mma_bf(acc[ii][j], ahf, b2h);
                mma_bf(acc[ii][j], alf, b2h);
                mma_bf(acc[ii][j], ahf, b2l);
            }
        }
        __syncthreads();
        if (i + 2 < NT) {
            stage_bf(sb + s * STSZ + 0 * PLSZ, Ah + (i + 2) * 16, DM, tid);
            stage_bf(sb + s * STSZ + 1 * PLSZ, Al + (i + 2) * 16, DM, tid);
            stage_bf(sb + s * STSZ + 2 * PLSZ, Bh + (i + 2) * 16, DM, tid);
            stage_bf(sb + s * STSZ + 3 * PLSZ, Bl + (i + 2) * 16, DM, tid);
            CPC();
        }
    }
#pragma unroll
    for (int i = 0; i < 4; i++)
#pragma unroll
        for (int j = 0; j < 4; j++) {
            int m = m0 + wm * 64 + i * 16 + (lane >> 2);
            int n = n0 + wn * 32 + j * 8 + (lane & 3) * 2;
            float bz0 = bias[n], bz1 = bias[n + 1];
            float v00 = fmaxf(acc[i][j][0] + bz0, 0.0f), v01 = fmaxf(acc[i][j][1] + bz1, 0.0f);
            float v10 = fmaxf(acc[i][j][2] + bz0, 0.0f), v11 = fmaxf(acc[i][j][3] + bz1, 0.0f);
            if (MODE == 0) {
                *(float2*)&C[(size_t)m * DM + n]       = make_float2(v00, v01);
                *(float2*)&C[(size_t)(m + 8) * DM + n] = make_float2(v10, v11);
            }
            if (MODE == 2 || MODE == 3) {
                *(float2*)&C[(size_t)m * DM + n] =
                    make_float2(__uint_as_float(tf32r(v00)), __uint_as_float(tf32r(v01)));
                *(float2*)&C[(size_t)(m + 8) * DM + n] =
                    make_float2(__uint_as_float(tf32r(v10)), __uint_as_float(tf32r(v11)));
            }
            if (MODE == 2) {
                size_t p0 = ((size_t)m * DM + n) >> 1, p1 = ((size_t)(m + 8) * DM + n) >> 1;
                ((uint32_t*)Chi)[p0] = pkbf(v00, v01);
                ((uint32_t*)Chi)[p1] = pkbf(v10, v11);
                float r00 = v00 - __uint_as_float(bfhi(v00));
                float r01 = v01 - __uint_as_float(bfhi(v01));
                float r10 = v10 - __uint_as_float(bfhi(v10));
                float r11 = v11 - __uint_as_float(bfhi(v11));
                ((uint32_t*)Clo)[p0] = pkbf(r00, r01);
                ((uint32_t*)Clo)[p1] = pkbf(r10, r11);
            }
            if (MODE == 1) {
                int bb = m >> 11, t = m & 2047, hh = n >> 6, e = n & 63;
                size_t base = ((size_t)(bb * 16 + hh) * 64 + e) * S_;
                Chi[base + t]          = (uint16_t)(bfhi(v00) >> 16);
                Chi[base + S_ + t]     = (uint16_t)(bfhi(v01) >> 16);
                Chi[base + t + 8]      = (uint16_t)(bfhi(v10) >> 16);
                Chi[base + S_ + t + 8] = (uint16_t)(bfhi(v11) >> 16);
            }
        }
}

// ---------------- fused flash attention (64-row s-tile, 2 CTAs/SM) ----------
// smem: q[64][KPQ] f32 | k x2 [64][KPQ] f32 | v x2 [64][KPV2] bf16 | srow[64] f32
#define QOFF   0
#define KOFF0  17408
#define KOFF1  34816
#define VOFF0  52224
#define VOFF1  61440
#define SROWO  70656
#define FSMEM  70912
#define TT     64
#define ITERS  (S_ / TT)   // 32
__global__ __launch_bounds__(256, 2)
void flash_attn(const float* __restrict__ q, const float* __restrict__ k,
                const uint16_t* __restrict__ vtb, const uint32_t* __restrict__ mp,
                uint16_t* __restrict__ Ohi, uint16_t* __restrict__ Olo) {
    char* sm = smraw;
    const int tid = threadIdx.x, lane = tid & 31, wid = tid >> 5;
    const int wn = wid & 1, wm = wid >> 1;          // 2 t-col warps x 4 m-row warps
    const int bh = blockIdx.y, b = bh >> 4, h = bh & 15;
    const int s0 = blockIdx.x * 64;
    const uint32_t sb = smem_u32(sm);
    float* srow = (float*)(sm + SROWO);
    if (tid < 64) srow[tid] = 0.0f;

    const float* qg = q + ((size_t)b * S_ + s0) * DM + h * HD;
    const float* kg = k + (size_t)b * S_ * DM + h * HD;
    const uint16_t* vg = vtb + (size_t)bh * HD * S_;

    // stage q (own group), then k0/v0, k1/v1
#pragma unroll
    for (int p = 0; p < 4; p++) {
        int id = tid + p * 256, r = id >> 4, c = id & 15;
        cp16(sb + QOFF + (uint32_t)(r * KPQ + c * 4) * 4u, qg + (size_t)r * DM + c * 4);
    }
    CPC();
    auto stage_k = [&](uint32_t koff, int t0) {
        const float* src = kg + (size_t)t0 * DM;
#pragma unroll
        for (int p = 0; p < 4; p++) {
            int id = tid + p * 256, r = id >> 4, c = id & 15;
            cp16(sb + koff + (uint32_t)(r * KPQ + c * 4) * 4u, src + (size_t)r * DM + c * 4);
        }
    };
    auto stage_v = [&](uint32_t voff, int t0) {
#pragma unroll
        for (int p = 0; p < 2; p++) {
            int id = tid + p * 256, e = id >> 3, c = id & 7;
            cp16(sb + voff + (uint32_t)(e * KPV2 + c * 8) * 2u, vg + (size_t)e * S_ + t0 + c * 8);
        }
    };
    stage_k(KOFF0, 0);  stage_v(VOFF0, 0);  CPC();
    stage_k(KOFF1, TT); stage_v(VOFF1, TT); CPC();

    const int ar0 = wm * 16 + (lane >> 2);
    const int row = s0 + wm * 16 + (lane >> 2);
    const int bpl = (lane & 3) * 2;

    // hoist Q fragments (loop-invariant): 32 regs
    CPW2();
    __syncthreads();
    const float* Qs = (const float*)(sm + QOFF);
    uint32_t Qf[8][4];
#pragma unroll
    for (int kc = 0; kc < 8; kc++) {
        int c0 = kc * 8 + (lane & 3);
        Qf[kc][0] = __float_as_uint(Qs[ar0 * KPQ + c0]);
        Qf[kc][1] = __float_as_uint(Qs[(ar0 + 8) * KPQ + c0]);
        Qf[kc][2] = __float_as_uint(Qs[ar0 * KPQ + c0 + 4]);
        Qf[kc][3] = __float_as_uint(Qs[(ar0 + 8) * KPQ + c0 + 4]);
    }

    float acc2[8][4];
#pragma unroll
    for (int j = 0; j < 8; j++)
#pragma unroll
        for (int e = 0; e < 4; e++) acc2[j][e] = 0.0f;
    float rs2[2] = {0.f, 0.f};

    const int bn0 = wn * 32 + (lane >> 2);
    const float cf = SCALE_ * L2E;
    const uint32_t* mpr0 = mp + ((size_t)(b * S_ + row) << 6) + wn;
    const uint32_t* mpr1 = mpr0 + (8 << 6);
    // V ldmatrix lane base (stage-独立 part)
    const uint32_t vln = (uint32_t)(((((lane >> 4) & 1) * 8 + (lane & 7)) * KPV2 + ((lane >> 3) & 1) * 8) * 2);

    for (int it = 0; it < ITERS; it++) {
        const int s = it & 1;
        if (it >= ITERS - 2) { CPW0(); } else { CPW1(); }
        __syncthreads();
        const float* Ks = (const float*)(sm + (s ? KOFF1 : KOFF0));
        const uint32_t vbase = sb + (s ? VOFF1 : VOFF0) + vln;

        // ---- QK: warp tile [16 m x 32 t], tf32, Q frags hoisted ----
        float acc[4][4];
#pragma unroll
        for (int j = 0; j < 4; j++)
#pragma unroll
            for (int e = 0; e < 4; e++) acc[j][e] = 0.0f;
#pragma unroll
        for (int kc = 0; kc < 8; kc++) {
            int c0 = kc * 8 + (lane & 3);
#pragma unroll
            for (int j = 0; j < 4; j++) {
                int rn = bn0 + j * 8;
                uint32_t b2[2] = { __float_as_uint(Ks[rn * KPQ + c0]),
                                   __float_as_uint(Ks[rn * KPQ + c0 + 4]) };
                mma_t(acc[j], Qf[kc], b2);
            }
        }

        // ---- packed-mask + MUFU exp2 -> PV (ldmatrix V) ----
        const uint32_t w0 = mpr0[it * 2], w1 = mpr1[it * 2];
#pragma unroll
        for (int st = 0; st < 2; st++) {
            uint32_t af[4];
#pragma unroll
            for (int jj = 0; jj < 2; jj++) {
                int j = st * 2 + jj;
                int bp = j * 8 + bpl;
                float e00 = ex2a(((w0 >> bp) & 1u)       ? acc[j][0] * cf : -12000.0f);
                float e01 = ex2a(((w0 >> (bp + 1)) & 1u) ? acc[j][1] * cf : -12000.0f);
                float e10 = ex2a(((w1 >> bp) & 1u)       ? acc[j][2] * cf : -12000.0f);
                float e11 = ex2a(((w1 >> (bp + 1)) & 1u) ? acc[j][3] * cf : -12000.0f);
                rs2[0] += e00 + e01;
                rs2[1] += e10 + e11;
                af[jj * 2 + 0] = cvtbf2(e00, e01);
                af[jj * 2 + 1] = cvtbf2(e10, e11);
            }
            const uint32_t va = vbase + (uint32_t)((wn * 32 + st * 16) * 2);
#pragma unroll
            for (int p = 0; p < 4; p++) {
                uint32_t vf[4];
                LDSM4(vf, va + p * (16 * KPV2 * 2));
                uint32_t b2a[2] = { vf[0], vf[1] }, b2b[2] = { vf[2], vf[3] };
                mma_bf(acc2[p * 2 + 0], af, b2a);
                mma_bf(acc2[p * 2 + 1], af, b2b);
            }
        }
        __syncthreads();
        if (it + 2 < ITERS) {
            stage_k(s ? KOFF1 : KOFF0, (it + 2) * TT);
            stage_v(s ? VOFF1 : VOFF0, (it + 2) * TT);
            CPC();
        }
    }

    // ---- row sums: lane-quad reduce then atomic into smem ----
#pragma unroll
    for (int i = 0; i < 2; i++) {
        rs2[i] += __shfl_xor_sync(0xffffffffu, rs2[i], 1);
        rs2[i] += __shfl_xor_sync(0xffffffffu, rs2[i], 2);
    }
    if ((lane & 3) == 0) {
        atomicAdd(&srow[wm * 16 + (lane >> 2)],     rs2[0]);
        atomicAdd(&srow[wm * 16 + (lane >> 2) + 8], rs2[1]);
    }
    __syncthreads();

    // ---- cross-warp PV reduce (wn=1 -> smem, wn=0 adds + writes) ----
    float* red = (float*)(sm + KOFF0);   // 64x64 f32 = 16KB, reuse k buffer
    if (wn == 1) {
#pragma unroll
        for (int je = 0; je < 8; je++) {
            int rl = wm * 16 + (lane >> 2);
            int cl = je * 8 + (lane & 3) * 2;
            *(float2*)&red[(size_t)rl * 64 + cl]       = make_float2(acc2[je][0], acc2[je][1]);
            *(float2*)&red[(size_t)(rl + 8) * 64 + cl] = make_float2(acc2[je][2], acc2[je][3]);
        }
    }
    __syncthreads();
    if (wn == 0) {
        int rl0 = wm * 16 + (lane >> 2);
        float inv0 = 1.0f / srow[rl0];
        float inv1 = 1.0f / srow[rl0 + 8];
        int rowg = s0 + rl0;
#pragma unroll
        for (int je = 0; je < 8; je++) {
            int cl = je * 8 + (lane & 3) * 2;
            float2 o0 = *(float2*)&red[(size_t)rl0 * 64 + cl];
            float2 o1 = *(float2*)&red[(size_t)(rl0 + 8) * 64 + cl];
            float v00 = (acc2[je][0] + o0.x) * inv0;
            float v01 = (acc2[je][1] + o0.y) * inv0;
            float v10 = (acc2[je][2] + o1.x) * inv1;
            float v11 = (acc2[je][3] + o1.y) * inv1;
            size_t p0 = (((size_t)bh * S_ + rowg) * HD + cl) >> 1;
            size_t p1 = (((size_t)bh * S_ + rowg + 8) * HD + cl) >> 1;
            ((uint32_t*)Ohi)[p0] = pkbf(v00, v01);
            ((uint32_t*)Ohi)[p1] = pkbf(v10, v11);
            float r00 = v00 - __uint_as_float(bfhi(v00));
            float r01 = v01 - __uint_as_float(bfhi(v01));
            float r10 = v10 - __uint_as_float(bfhi(v10));
            float r11 = v11 - __uint_as_float(bfhi(v11));
            ((uint32_t*)Olo)[p0] = pkbf(r00, r01);
            ((uint32_t*)Olo)[p1] = pkbf(r10, r11);
        }
    }
}

// ---------------- small utility kernels ----------------
__global__ __launch_bounds__(256)
void split_kernel(const float* __restrict__ X, uint16_t* __restrict__ Xhi, uint16_t* __restrict__ Xlo) {
    size_t i = (size_t)blockIdx.x * 256 + threadIdx.x;
    float2 v = ((const float2*)X)[i];
    ((uint32_t*)Xhi)[i] = pkbf(v.x, v.y);
    float rx = v.x - __uint_as_float(bfhi(v.x));
    float ry = v.y - __uint_as_float(bfhi(v.y));
    ((uint32_t*)Xlo)[i] = pkbf(rx, ry);
}

__global__ __launch_bounds__(256)
void maskpack(const int* __restrict__ mask, uint32_t* __restrict__ mp) {
    int w = blockIdx.x * 256 + threadIdx.x;      // 262144 words
    const int4* src = (const int4*)mask + (size_t)w * 8;
    uint32_t bits = 0;
#pragma unroll
    for (int i = 0; i < 8; i++) {
        int4 v = src[i];
        bits |= (uint32_t)(v.x == 1) << (i * 4 + 0);
        bits |= (uint32_t)(v.y == 1) << (i * 4 + 1);
        bits |= (uint32_t)(v.z == 1) << (i * 4 + 2);
        bits |= (uint32_t)(v.w == 1) << (i * 4 + 3);
    }
    mp[w] = bits;
}

__global__ __launch_bounds__(256)
void transpose_split(const float* __restrict__ W, uint16_t* __restrict__ Whi, uint16_t* __restrict__ Wlo) {
    __shared__ float t[32][33];
    const int tx = threadIdx.x & 31, ty = threadIdx.x >> 5;
    const int bx = blockIdx.x * 32, by = blockIdx.y * 32;
#pragma unroll
    for (int j = 0; j < 32; j += 8) t[ty + j][tx] = W[(size_t)(by + ty + j) * DM + bx + tx];
    __syncthreads();
#pragma unroll
    for (int j = 0; j < 32; j += 8) {
        float v = t[tx][ty + j];
        size_t idx = (size_t)(bx + ty + j) * DM + by + tx;
        Whi[idx] = (uint16_t)(bfhi(v) >> 16);
        float rr = v - __uint_as_float(bfhi(v));
        Wlo[idx] = (uint16_t)(bfhi(rr) >> 16);
    }
}

// ---------------- launch ----------------
extern "C" void kernel_launch(void* const* d_in, const int* in_sizes, int n_in,
                              void* d_out, int out_size) {
    (void)in_sizes; (void)n_in; (void)out_size;
    const float* x    = (const float*)d_in[0];
    const int*   mask = (const int*)d_in[1];
    const float* W0   = (const float*)d_in[2];
    const float* b0   = (const float*)d_in[3];
    const float* W1   = (const float*)d_in[4];
    const float* b1   = (const float*)d_in[5];
    const float* W2   = (const float*)d_in[6];
    const float* b2   = (const float*)d_in[7];
    const float* Wo   = (const float*)d_in[8];
    const float* bo   = (const float*)d_in[9];
    float* out = (float*)d_out;

    float *q, *k;
    uint16_t *vt, *xs, *qs, *os, *wtb;
    uint32_t *mpd;
    cudaGetSymbolAddress((void**)&q,   g_q);
    cudaGetSymbolAddress((void**)&k,   g_k);
    cudaGetSymbolAddress((void**)&vt,  g_vt);
    cudaGetSymbolAddress((void**)&xs,  g_xs);
    cudaGetSymbolAddress((void**)&qs,  g_qs);
    cudaGetSymbolAddress((void**)&os,  g_os);
    cudaGetSymbolAddress((void**)&wtb, g_wtb);
    cudaGetSymbolAddress((void**)&mpd, g_mp);
    const size_t PLN = (size_t)MTOT * DM;
    const size_t WP  = (size_t)DM * DM;

    cudaFuncSetAttribute(gemm_bf<0>, cudaFuncAttributeMaxDynamicSharedMemorySize, DSMEM);
    cudaFuncSetAttribute(gemm_bf<1>, cudaFuncAttributeMaxDynamicSharedMemorySize, DSMEM);
    cudaFuncSetAttribute(gemm_bf<2>, cudaFuncAttributeMaxDynamicSharedMemorySize, DSMEM);
    cudaFuncSetAttribute(gemm_bf<3>, cudaFuncAttributeMaxDynamicSharedMemorySize, DSMEM);
    cudaFuncSetAttribute(flash_attn, cudaFuncAttributeMaxDynamicSharedMemorySize, FSMEM);

    split_kernel<<<MTOT * DM / 512, 256>>>(x, xs, xs + PLN);
    maskpack<<<(B_ * S_ * 64) / 256, 256>>>(mask, mpd);
    transpose_split<<<dim3(32, 32), 256>>>(W0, wtb + 0 * 2 * WP, wtb + 0 * 2 * WP + WP);
    transpose_split<<<dim3(32, 32), 256>>>(W1, wtb + 1 * 2 * WP, wtb + 1 * 2 * WP + WP);
    transpose_split<<<dim3(32, 32), 256>>>(W2, wtb + 2 * 2 * WP, wtb + 2 * 2 * WP + WP);
    transpose_split<<<dim3(32, 32), 256>>>(Wo, wtb + 3 * 2 * WP, wtb + 3 * 2 * WP + WP);

    gemm_bf<2><<<dim3(8, 32), 256, DSMEM>>>(xs, xs + PLN, wtb + 0 * 2 * WP, wtb + 0 * 2 * WP + WP,
                                            b0, q, qs, qs + PLN);
    gemm_bf<3><<<dim3(8, 32), 256, DSMEM>>>(qs, qs + PLN, wtb + 1 * 2 * WP, wtb + 1 * 2 * WP + WP,
                                            b1, k, nullptr, nullptr);
    gemm_bf<1><<<dim3(8, 32), 256, DSMEM>>>(qs, qs + PLN, wtb + 2 * 2 * WP, wtb + 2 * 2 * WP + WP,
                                            b2, nullptr, vt, nullptr);
    flash_attn<<<dim3(32, 32), 256, FSMEM>>>(q, k, vt, mpd, os, os + PLN);
    gemm_bf<0><<<dim3(8, 32), 256, DSMEM>>>(os, os + PLN, wtb + 3 * 2 * WP, wtb + 3 * 2 * WP + WP,
                                            bo, out, nullptr, nullptr);
}

// round 10
// speedup vs baseline: 3.2645x; 1.1132x over previous
#include <cuda_runtime.h>
#include <cstdint>

#define B_       2
#define S_       2048
#define DM       1024
#define H_       16
#define HD       64
#define BH_      32
#define MTOT     4096
#define L2E      1.4426950408889634f
#define SCALE_   0.125f
#define KP       20                  // fp32 smem row pad (floats), dense
#define KPQ      68                  // q/k smem row pad (floats), flash
#define KPV2     72                  // v smem row pad (halves), flash

// ---------------- scratch (device globals) ----------------
__device__ __align__(128) float    g_xr[MTOT * DM];            // x, tf32-rounded
__device__ __align__(128) float    g_q [MTOT * DM];            // q, tf32-rounded
__device__ __align__(128) float    g_k [MTOT * DM];            // k, tf32-rounded
__device__ __align__(128) float    g_o [MTOT * DM];            // attn out (flat [bh][s][e]), tf32-rounded
__device__ __align__(128) float    g_wt[4][DM * DM];           // W^T fp32 tf32-rounded [n][k]
__device__ __align__(128) uint16_t g_vt[BH_ * HD * S_];        // V^T bf16 per head [bh][e][t]
__device__ __align__(128) uint32_t g_mp[B_ * S_ * (S_ / 32)];  // packed mask bits, 1MB

extern __shared__ char smraw[];

// ---------------- helpers ----------------
__device__ __forceinline__ uint32_t smem_u32(const void* p) {
    uint32_t r;
    asm("{ .reg .u64 t; cvta.to.shared.u64 t, %1; cvt.u32.u64 %0, t; }" : "=r"(r) : "l"(p));
    return r;
}
__device__ __forceinline__ uint32_t tf32r(float x) {
    uint32_t u; asm("cvt.rna.tf32.f32 %0, %1;" : "=r"(u) : "f"(x)); return u;
}
__device__ __forceinline__ uint32_t bfhi(float x) {   // bf16 RNE, as fp32 bits (low16=0)
    uint32_t u = __float_as_uint(x);
    return (u + 0x7fffu + ((u >> 16) & 1u)) & 0xffff0000u;
}
__device__ __forceinline__ float ex2a(float x) {      // MUFU exp2
    float r; asm("ex2.approx.ftz.f32 %0, %1;" : "=f"(r) : "f"(x)); return r;
}
__device__ __forceinline__ uint32_t cvtbf2(float lo, float hi) {
    uint32_t r; asm("cvt.rn.bf16x2.f32 %0, %1, %2;" : "=r"(r) : "f"(hi), "f"(lo)); return r;
}
__device__ __forceinline__ void cp16(uint32_t d, const void* s) {
    asm volatile("cp.async.ca.shared.global [%0], [%1], 16;" :: "r"(d), "l"(s));
}
#define CPC()  asm volatile("cp.async.commit_group;")
#define CPW2() asm volatile("cp.async.wait_group 2;")
#define CPW1() asm volatile("cp.async.wait_group 1;")
#define CPW0() asm volatile("cp.async.wait_group 0;")

#define LDSM4(r, addr) \
    asm volatile("ldmatrix.sync.aligned.m8n8.x4.shared.b16 {%0,%1,%2,%3}, [%4];" \
                 : "=r"((r)[0]), "=r"((r)[1]), "=r"((r)[2]), "=r"((r)[3]) : "r"(addr))

__device__ __forceinline__ void mma_t(float* d, const uint32_t* a, const uint32_t* b) {
    asm volatile("mma.sync.aligned.m16n8k8.row.col.f32.tf32.tf32.f32 "
                 "{%0,%1,%2,%3},{%4,%5,%6,%7},{%8,%9},{%0,%1,%2,%3};"
                 : "+f"(d[0]), "+f"(d[1]), "+f"(d[2]), "+f"(d[3])
                 : "r"(a[0]), "r"(a[1]), "r"(a[2]), "r"(a[3]), "r"(b[0]), "r"(b[1]));
}
__device__ __forceinline__ void mma_bf(float* d, const uint32_t* a, const uint32_t* b) {
    asm volatile("mma.sync.aligned.m16n8k16.row.col.f32.bf16.bf16.f32 "
                 "{%0,%1,%2,%3},{%4,%5,%6,%7},{%8,%9},{%0,%1,%2,%3};"
                 : "+f"(d[0]), "+f"(d[1]), "+f"(d[2]), "+f"(d[3])
                 : "r"(a[0]), "r"(a[1]), "r"(a[2]), "r"(a[3]), "r"(b[0]), "r"(b[1]));
}

// ---------------- dense single-tf32: C = relu(A @ Wt^T + bias), tile 128x128 ----------------
// Operands pre-rounded to tf32. MODE 0: fp32 C (final). MODE 2: tf32-rounded C (q, k).
// MODE 1: bf16 V^T per head into Cvt.
#define DTILE  (128 * KP * 4)          // 10240 B per fp32 tile
#define DSMEM  (4 * DTILE)             // A0 A1 B0 B1
template<int MODE>
__global__ __launch_bounds__(256, 2)
void gemm_t(const float* __restrict__ A, const float* __restrict__ Bt,
            const float* __restrict__ bias, float* __restrict__ C,
            uint16_t* __restrict__ Cvt) {
    const float* sm = (const float*)smraw;
    const int tid = threadIdx.x, lane = tid & 31, wid = tid >> 5;
    const int wm = wid & 1, wn = wid >> 1;
    const int m0 = blockIdx.y * 128, n0 = blockIdx.x * 128;
    const uint32_t sb = smem_u32(sm);
    float acc[4][4][4];
#pragma unroll
    for (int i = 0; i < 4; i++)
#pragma unroll
        for (int j = 0; j < 4; j++)
#pragma unroll
            for (int e = 0; e < 4; e++) acc[i][j][e] = 0.0f;

    const float* Ag = A  + (size_t)m0 * DM;
    const float* Bg = Bt + (size_t)n0 * DM;
    const int NT = DM / 16;   // 64

    auto stg = [&](uint32_t off, const float* g, int k0) {
#pragma unroll
        for (int p = 0; p < 2; p++) {
            int id = tid + p * 256;
            int r = id >> 2, s4 = (id & 3) * 4;
            cp16(sb + off + (uint32_t)(r * KP + s4) * 4u, g + (size_t)r * DM + k0 + s4);
        }
    };
    stg(0 * DTILE, Ag, 0);  stg(2 * DTILE, Bg, 0);  CPC();
    stg(1 * DTILE, Ag, 16); stg(3 * DTILE, Bg, 16); CPC();

    const int ar0 = wm * 64 + (lane >> 2);
    const int bn0 = wn * 32 + (lane >> 2);
    const int c00 = lane & 3;
    for (int i = 0; i < NT; i++) {
        int s = i & 1;
        if (i >= NT - 2) { CPW0(); } else { CPW1(); }
        __syncthreads();
        const float* As = sm + s * (DTILE / 4);
        const float* Bs = sm + (2 + s) * (DTILE / 4);
#pragma unroll
        for (int kh = 0; kh < 2; kh++) {        // two k8 steps per k16 tile
            int c0 = c00 + kh * 8;
            uint32_t a[4][4];
#pragma unroll
            for (int ii = 0; ii < 4; ii++) {
                int r = ar0 + ii * 16;
                a[ii][0] = __float_as_uint(As[r * KP + c0]);
                a[ii][1] = __float_as_uint(As[(r + 8) * KP + c0]);
                a[ii][2] = __float_as_uint(As[r * KP + c0 + 4]);
                a[ii][3] = __float_as_uint(As[(r + 8) * KP + c0 + 4]);
            }
#pragma unroll
            for (int j = 0; j < 4; j++) {
                int rn = bn0 + j * 8;
                uint32_t b2[2] = { __float_as_uint(Bs[rn * KP + c0]),
                                   __float_as_uint(Bs[rn * KP + c0 + 4]) };
#pragma unroll
                for (int ii = 0; ii < 4; ii++) mma_t(acc[ii][j], a[ii], b2);
            }
        }
        __syncthreads();
        if (i + 2 < NT) {
            stg(s * DTILE, Ag, (i + 2) * 16);
            stg((2 + s) * DTILE, Bg, (i + 2) * 16);
            CPC();
        }
    }
#pragma unroll
    for (int i = 0; i < 4; i++)
#pragma unroll
        for (int j = 0; j < 4; j++) {
            int m = m0 + wm * 64 + i * 16 + (lane >> 2);
            int n = n0 + wn * 32 + j * 8 + (lane & 3) * 2;
            float bz0 = bias[n], bz1 = bias[n + 1];
            float v00 = fmaxf(acc[i][j][0] + bz0, 0.0f), v01 = fmaxf(acc[i][j][1] + bz1, 0.0f);
            float v10 = fmaxf(acc[i][j][2] + bz0, 0.0f), v11 = fmaxf(acc[i][j][3] + bz1, 0.0f);
            if (MODE == 0) {
                *(float2*)&C[(size_t)m * DM + n]       = make_float2(v00, v01);
                *(float2*)&C[(size_t)(m + 8) * DM + n] = make_float2(v10, v11);
            }
            if (MODE == 2) {
                *(float2*)&C[(size_t)m * DM + n] =
                    make_float2(__uint_as_float(tf32r(v00)), __uint_as_float(tf32r(v01)));
                *(float2*)&C[(size_t)(m + 8) * DM + n] =
                    make_float2(__uint_as_float(tf32r(v10)), __uint_as_float(tf32r(v11)));
            }
            if (MODE == 1) {
                int bb = m >> 11, t = m & 2047, hh = n >> 6, e = n & 63;
                size_t base = ((size_t)(bb * 16 + hh) * 64 + e) * S_;
                Cvt[base + t]          = (uint16_t)(bfhi(v00) >> 16);
                Cvt[base + S_ + t]     = (uint16_t)(bfhi(v01) >> 16);
                Cvt[base + t + 8]      = (uint16_t)(bfhi(v10) >> 16);
                Cvt[base + S_ + t + 8] = (uint16_t)(bfhi(v11) >> 16);
            }
        }
}

// ---------------- fused flash attention (64-row s-tile, 2 CTAs/SM) ----------
// smem: q[64][KPQ] f32 | k x2 [64][KPQ] f32 | v x2 [64][KPV2] bf16 | srow[64] f32
#define QOFF   0
#define KOFF0  17408
#define KOFF1  34816
#define VOFF0  52224
#define VOFF1  61440
#define SROWO  70656
#define FSMEM  70912
#define TT     64
#define ITERS  (S_ / TT)   // 32
__global__ __launch_bounds__(256, 2)
void flash_attn(const float* __restrict__ q, const float* __restrict__ k,
                const uint16_t* __restrict__ vtb, const uint32_t* __restrict__ mp,
                float* __restrict__ O) {
    char* sm = smraw;
    const int tid = threadIdx.x, lane = tid & 31, wid = tid >> 5;
    const int wn = wid & 1, wm = wid >> 1;          // 2 t-col warps x 4 m-row warps
    const int bh = blockIdx.y, b = bh >> 4, h = bh & 15;
    const int s0 = blockIdx.x * 64;
    const uint32_t sb = smem_u32(sm);
    float* srow = (float*)(sm + SROWO);
    if (tid < 64) srow[tid] = 0.0f;

    const float* qg = q + ((size_t)b * S_ + s0) * DM + h * HD;
    const float* kg = k + (size_t)b * S_ * DM + h * HD;
    const uint16_t* vg = vtb + (size_t)bh * HD * S_;

#pragma unroll
    for (int p = 0; p < 4; p++) {
        int id = tid + p * 256, r = id >> 4, c = id & 15;
        cp16(sb + QOFF + (uint32_t)(r * KPQ + c * 4) * 4u, qg + (size_t)r * DM + c * 4);
    }
    CPC();
    auto stage_k = [&](uint32_t koff, int t0) {
        const float* src = kg + (size_t)t0 * DM;
#pragma unroll
        for (int p = 0; p < 4; p++) {
            int id = tid + p * 256, r = id >> 4, c = id & 15;
            cp16(sb + koff + (uint32_t)(r * KPQ + c * 4) * 4u, src + (size_t)r * DM + c * 4);
        }
    };
    auto stage_v = [&](uint32_t voff, int t0) {
#pragma unroll
        for (int p = 0; p < 2; p++) {
            int id = tid + p * 256, e = id >> 3, c = id & 7;
            cp16(sb + voff + (uint32_t)(e * KPV2 + c * 8) * 2u, vg + (size_t)e * S_ + t0 + c * 8);
        }
    };
    stage_k(KOFF0, 0);  stage_v(VOFF0, 0);  CPC();
    stage_k(KOFF1, TT); stage_v(VOFF1, TT); CPC();

    const int ar0 = wm * 16 + (lane >> 2);
    const int row = s0 + wm * 16 + (lane >> 2);
    const int bpl = (lane & 3) * 2;

    CPW2();
    __syncthreads();
    const float* Qs = (const float*)(sm + QOFF);
    uint32_t Qf[8][4];
#pragma unroll
    for (int kc = 0; kc < 8; kc++) {
        int c0 = kc * 8 + (lane & 3);
        Qf[kc][0] = __float_as_uint(Qs[ar0 * KPQ + c0]);
        Qf[kc][1] = __float_as_uint(Qs[(ar0 + 8) * KPQ + c0]);
        Qf[kc][2] = __float_as_uint(Qs[ar0 * KPQ + c0 + 4]);
        Qf[kc][3] = __float_as_uint(Qs[(ar0 + 8) * KPQ + c0 + 4]);
    }

    float acc2[8][4];
#pragma unroll
    for (int j = 0; j < 8; j++)
#pragma unroll
        for (int e = 0; e < 4; e++) acc2[j][e] = 0.0f;
    float rs2[2] = {0.f, 0.f};

    const int bn0 = wn * 32 + (lane >> 2);
    const float cf = SCALE_ * L2E;
    const uint32_t* mpr0 = mp + ((size_t)(b * S_ + row) << 6) + wn;
    const uint32_t* mpr1 = mpr0 + (8 << 6);
    const uint32_t vln = (uint32_t)(((((lane >> 4) & 1) * 8 + (lane & 7)) * KPV2 + ((lane >> 3) & 1) * 8) * 2);

    for (int it = 0; it < ITERS; it++) {
        const int s = it & 1;
        if (it >= ITERS - 2) { CPW0(); } else { CPW1(); }
        __syncthreads();
        const float* Ks = (const float*)(sm + (s ? KOFF1 : KOFF0));
        const uint32_t vbase = sb + (s ? VOFF1 : VOFF0) + vln;

        float acc[4][4];
#pragma unroll
        for (int j = 0; j < 4; j++)
#pragma unroll
            for (int e = 0; e < 4; e++) acc[j][e] = 0.0f;
#pragma unroll
        for (int kc = 0; kc < 8; kc++) {
            int c0 = kc * 8 + (lane & 3);
#pragma unroll
            for (int j = 0; j < 4; j++) {
                int rn = bn0 + j * 8;
                uint32_t b2[2] = { __float_as_uint(Ks[rn * KPQ + c0]),
                                   __float_as_uint(Ks[rn * KPQ + c0 + 4]) };
                mma_t(acc[j], Qf[kc], b2);
            }
        }

        const uint32_t w0 = mpr0[it * 2], w1 = mpr1[it * 2];
#pragma unroll
        for (int st = 0; st < 2; st++) {
            uint32_t af[4];
#pragma unroll
            for (int jj = 0; jj < 2; jj++) {
                int j = st * 2 + jj;
                int bp = j * 8 + bpl;
                float e00 = ex2a(((w0 >> bp) & 1u)       ? acc[j][0] * cf : -12000.0f);
                float e01 = ex2a(((w0 >> (bp + 1)) & 1u) ? acc[j][1] * cf : -12000.0f);
                float e10 = ex2a(((w1 >> bp) & 1u)       ? acc[j][2] * cf : -12000.0f);
                float e11 = ex2a(((w1 >> (bp + 1)) & 1u) ? acc[j][3] * cf : -12000.0f);
                rs2[0] += e00 + e01;
                rs2[1] += e10 + e11;
                af[jj * 2 + 0] = cvtbf2(e00, e01);
                af[jj * 2 + 1] = cvtbf2(e10, e11);
            }
            const uint32_t va = vbase + (uint32_t)((wn * 32 + st * 16) * 2);
#pragma unroll
            for (int p = 0; p < 4; p++) {
                uint32_t vf[4];
                LDSM4(vf, va + p * (16 * KPV2 * 2));
                uint32_t b2a[2] = { vf[0], vf[1] }, b2b[2] = { vf[2], vf[3] };
                mma_bf(acc2[p * 2 + 0], af, b2a);
                mma_bf(acc2[p * 2 + 1], af, b2b);
            }
        }
        __syncthreads();
        if (it + 2 < ITERS) {
            stage_k(s ? KOFF1 : KOFF0, (it + 2) * TT);
            stage_v(s ? VOFF1 : VOFF0, (it + 2) * TT);
            CPC();
        }
    }

#pragma unroll
    for (int i = 0; i < 2; i++) {
        rs2[i] += __shfl_xor_sync(0xffffffffu, rs2[i], 1);
        rs2[i] += __shfl_xor_sync(0xffffffffu, rs2[i], 2);
    }
    if ((lane & 3) == 0) {
        atomicAdd(&srow[wm * 16 + (lane >> 2)],     rs2[0]);
        atomicAdd(&srow[wm * 16 + (lane >> 2) + 8], rs2[1]);
    }
    __syncthreads();

    float* red = (float*)(sm + KOFF0);   // 64x64 f32 = 16KB, reuse k buffer
    if (wn == 1) {
#pragma unroll
        for (int je = 0; je < 8; je++) {
            int rl = wm * 16 + (lane >> 2);
            int cl = je * 8 + (lane & 3) * 2;
            *(float2*)&red[(size_t)rl * 64 + cl]       = make_float2(acc2[je][0], acc2[je][1]);
            *(float2*)&red[(size_t)(rl + 8) * 64 + cl] = make_float2(acc2[je][2], acc2[je][3]);
        }
    }
    __syncthreads();
    if (wn == 0) {
        int rl0 = wm * 16 + (lane >> 2);
        float inv0 = 1.0f / srow[rl0];
        float inv1 = 1.0f / srow[rl0 + 8];
        int rowg = s0 + rl0;
        float* ob0 = O + ((size_t)bh * S_ + rowg) * HD;
        float* ob1 = O + ((size_t)bh * S_ + rowg + 8) * HD;
#pragma unroll
        for (int je = 0; je < 8; je++) {
            int cl = je * 8 + (lane & 3) * 2;
            float2 o0 = *(float2*)&red[(size_t)rl0 * 64 + cl];
            float2 o1 = *(float2*)&red[(size_t)(rl0 + 8) * 64 + cl];
            *(float2*)&ob0[cl] = make_float2(
                __uint_as_float(tf32r((acc2[je][0] + o0.x) * inv0)),
                __uint_as_float(tf32r((acc2[je][1] + o0.y) * inv0)));
            *(float2*)&ob1[cl] = make_float2(
                __uint_as_float(tf32r((acc2[je][2] + o1.x) * inv1)),
                __uint_as_float(tf32r((acc2[je][3] + o1.y) * inv1)));
        }
    }
}

// ---------------- small utility kernels ----------------
__global__ __launch_bounds__(256)
void round_x(const float* __restrict__ X, float* __restrict__ Y) {
    size_t i = (size_t)blockIdx.x * 256 + threadIdx.x;
    float2 v = ((const float2*)X)[i];
    ((float2*)Y)[i] = make_float2(__uint_as_float(tf32r(v.x)), __uint_as_float(tf32r(v.y)));
}

__global__ __launch_bounds__(256)
void maskpack(const int* __restrict__ mask, uint32_t* __restrict__ mp) {
    int w = blockIdx.x * 256 + threadIdx.x;      // 262144 words
    const int4* src = (const int4*)mask + (size_t)w * 8;
    uint32_t bits = 0;
#pragma unroll
    for (int i = 0; i < 8; i++) {
        int4 v = src[i];
        bits |= (uint32_t)(v.x == 1) << (i * 4 + 0);
        bits |= (uint32_t)(v.y == 1) << (i * 4 + 1);
        bits |= (uint32_t)(v.z == 1) << (i * 4 + 2);
        bits |= (uint32_t)(v.w == 1) << (i * 4 + 3);
    }
    mp[w] = bits;
}

__global__ __launch_bounds__(256)
void transpose_tf32(const float* __restrict__ W, float* __restrict__ Wt) {
    __shared__ float t[32][33];
    const int tx = threadIdx.x & 31, ty = threadIdx.x >> 5;
    const int bx = blockIdx.x * 32, by = blockIdx.y * 32;
#pragma unroll
    for (int j = 0; j < 32; j += 8) t[ty + j][tx] = W[(size_t)(by + ty + j) * DM + bx + tx];
    __syncthreads();
#pragma unroll
    for (int j = 0; j < 32; j += 8)
        Wt[(size_t)(bx + ty + j) * DM + by + tx] = __uint_as_float(tf32r(t[tx][ty + j]));
}

// ---------------- launch ----------------
extern "C" void kernel_launch(void* const* d_in, const int* in_sizes, int n_in,
                              void* d_out, int out_size) {
    (void)in_sizes; (void)n_in; (void)out_size;
    const float* x    = (const float*)d_in[0];
    const int*   mask = (const int*)d_in[1];
    const float* W0   = (const float*)d_in[2];
    const float* b0   = (const float*)d_in[3];
    const float* W1   = (const float*)d_in[4];
    const float* b1   = (const float*)d_in[5];
    const float* W2   = (const float*)d_in[6];
    const float* b2   = (const float*)d_in[7];
    const float* Wo   = (const float*)d_in[8];
    const float* bo   = (const float*)d_in[9];
    float* out = (float*)d_out;

    float *xr, *q, *k, *o, *wt;
    uint16_t *vt;
    uint32_t *mpd;
    cudaGetSymbolAddress((void**)&xr,  g_xr);
    cudaGetSymbolAddress((void**)&q,   g_q);
    cudaGetSymbolAddress((void**)&k,   g_k);
    cudaGetSymbolAddress((void**)&o,   g_o);
    cudaGetSymbolAddress((void**)&wt,  g_wt);
    cudaGetSymbolAddress((void**)&vt,  g_vt);
    cudaGetSymbolAddress((void**)&mpd, g_mp);
    const size_t WP = (size_t)DM * DM;

    cudaFuncSetAttribute(gemm_t<0>, cudaFuncAttributeMaxDynamicSharedMemorySize, DSMEM);
    cudaFuncSetAttribute(gemm_t<1>, cudaFuncAttributeMaxDynamicSharedMemorySize, DSMEM);
    cudaFuncSetAttribute(gemm_t<2>, cudaFuncAttributeMaxDynamicSharedMemorySize, DSMEM);
    cudaFuncSetAttribute(flash_attn, cudaFuncAttributeMaxDynamicSharedMemorySize, FSMEM);

    round_x<<<MTOT * DM / 512, 256>>>(x, xr);
    maskpack<<<(B_ * S_ * 64) / 256, 256>>>(mask, mpd);
    transpose_tf32<<<dim3(32, 32), 256>>>(W0, wt + 0 * WP);
    transpose_tf32<<<dim3(32, 32), 256>>>(W1, wt + 1 * WP);
    transpose_tf32<<<dim3(32, 32), 256>>>(W2, wt + 2 * WP);
    transpose_tf32<<<dim3(32, 32), 256>>>(Wo, wt + 3 * WP);

    gemm_t<2><<<dim3(8, 32), 256, DSMEM>>>(xr, wt + 0 * WP, b0, q, nullptr);
    gemm_t<2><<<dim3(8, 32), 256, DSMEM>>>(q,  wt + 1 * WP, b1, k, nullptr);
    gemm_t<1><<<dim3(8, 32), 256, DSMEM>>>(q,  wt + 2 * WP, b2, nullptr, vt);
    flash_attn<<<dim3(32, 32), 256, FSMEM>>>(q, k, vt, mpd, o);
    gemm_t<0><<<dim3(8, 32), 256, DSMEM>>>(o,  wt + 3 * WP, bo, out, nullptr);
}

// round 11
// speedup vs baseline: 3.4737x; 1.0641x over previous
#include <cuda_runtime.h>
#include <cstdint>

#define B_       2
#define S_       2048
#define DM       1024
#define H_       16
#define HD       64
#define BH_      32
#define MTOT     4096
#define L2E      1.4426950408889634f
#define SCALE_   0.125f
#define KP       20                  // fp32 smem row pad (floats), dense
#define KPQ      68                  // q/k smem row pad (floats), flash
#define KPV2     72                  // v smem row pad (halves), flash

// ---------------- scratch (device globals) ----------------
__device__ __align__(128) float    g_xr[MTOT * DM];            // x, tf32-rounded
__device__ __align__(128) float    g_q [MTOT * DM];            // q, tf32-rounded
__device__ __align__(128) float    g_k [MTOT * DM];            // k, tf32-rounded
__device__ __align__(128) float    g_o [MTOT * DM];            // attn out, tf32-rounded
__device__ __align__(128) float    g_wt[4][DM * DM];           // W^T fp32 tf32-rounded [n][k]; [1],[2] contiguous for kv
__device__ __align__(128) uint16_t g_vt[BH_ * HD * S_];        // V^T bf16 per head [bh][e][t]
__device__ __align__(128) uint32_t g_mp[B_ * S_ * (S_ / 32)];  // packed mask bits, 1MB

extern __shared__ char smraw[];

// ---------------- helpers ----------------
__device__ __forceinline__ uint32_t smem_u32(const void* p) {
    uint32_t r;
    asm("{ .reg .u64 t; cvta.to.shared.u64 t, %1; cvt.u32.u64 %0, t; }" : "=r"(r) : "l"(p));
    return r;
}
__device__ __forceinline__ uint32_t tf32r(float x) {
    uint32_t u; asm("cvt.rna.tf32.f32 %0, %1;" : "=r"(u) : "f"(x)); return u;
}
__device__ __forceinline__ uint32_t bfhi(float x) {   // bf16 RNE, as fp32 bits (low16=0)
    uint32_t u = __float_as_uint(x);
    return (u + 0x7fffu + ((u >> 16) & 1u)) & 0xffff0000u;
}
__device__ __forceinline__ float ex2a(float x) {      // MUFU exp2
    float r; asm("ex2.approx.ftz.f32 %0, %1;" : "=f"(r) : "f"(x)); return r;
}
__device__ __forceinline__ uint32_t cvtbf2(float lo, float hi) {
    uint32_t r; asm("cvt.rn.bf16x2.f32 %0, %1, %2;" : "=r"(r) : "f"(hi), "f"(lo)); return r;
}
__device__ __forceinline__ void cp16(uint32_t d, const void* s) {
    asm volatile("cp.async.ca.shared.global [%0], [%1], 16;" :: "r"(d), "l"(s));
}
#define CPC()  asm volatile("cp.async.commit_group;")
#define CPW2() asm volatile("cp.async.wait_group 2;")
#define CPW1() asm volatile("cp.async.wait_group 1;")
#define CPW0() asm volatile("cp.async.wait_group 0;")

#define LDSM4(r, addr) \
    asm volatile("ldmatrix.sync.aligned.m8n8.x4.shared.b16 {%0,%1,%2,%3}, [%4];" \
                 : "=r"((r)[0]), "=r"((r)[1]), "=r"((r)[2]), "=r"((r)[3]) : "r"(addr))

__device__ __forceinline__ void mma_t(float* d, const uint32_t* a, const uint32_t* b) {
    asm volatile("mma.sync.aligned.m16n8k8.row.col.f32.tf32.tf32.f32 "
                 "{%0,%1,%2,%3},{%4,%5,%6,%7},{%8,%9},{%0,%1,%2,%3};"
                 : "+f"(d[0]), "+f"(d[1]), "+f"(d[2]), "+f"(d[3])
                 : "r"(a[0]), "r"(a[1]), "r"(a[2]), "r"(a[3]), "r"(b[0]), "r"(b[1]));
}
__device__ __forceinline__ void mma_bf(float* d, const uint32_t* a, const uint32_t* b) {
    asm volatile("mma.sync.aligned.m16n8k16.row.col.f32.bf16.bf16.f32 "
                 "{%0,%1,%2,%3},{%4,%5,%6,%7},{%8,%9},{%0,%1,%2,%3};"
                 : "+f"(d[0]), "+f"(d[1]), "+f"(d[2]), "+f"(d[3])
                 : "r"(a[0]), "r"(a[1]), "r"(a[2]), "r"(a[3]), "r"(b[0]), "r"(b[1]));
}

// ---------------- dense single-tf32 mainloop (shared by both dense kernels) ----------------
// 3-stage cp.async pipeline, ONE __syncthreads per iter.
#define DTILE  (128 * KP * 4)          // 10240 B per fp32 tile
#define DSMEM  (6 * DTILE)             // A0 A1 A2 B0 B1 B2 = 61440
__device__ __forceinline__ void dense_mainloop(const float* Ag, const float* Bg,
                                               int tid, int lane, int wm, int wn,
                                               float (*acc)[4][4]) {
    const float* sm = (const float*)smraw;
    const uint32_t sb = smem_u32(sm);
    auto stg = [&](uint32_t off, const float* g, int k0) {
#pragma unroll
        for (int p = 0; p < 2; p++) {
            int id = tid + p * 256;
            int r = id >> 2, s4 = (id & 3) * 4;
            cp16(sb + off + (uint32_t)(r * KP + s4) * 4u, g + (size_t)r * DM + k0 + s4);
        }
    };
    const int NT = DM / 16;   // 64
    stg(0 * DTILE, Ag, 0);  stg(3 * DTILE, Bg, 0);  CPC();
    stg(1 * DTILE, Ag, 16); stg(4 * DTILE, Bg, 16); CPC();

    const int ar0 = wm * 64 + (lane >> 2);
    const int bn0 = wn * 32 + (lane >> 2);
    const int c00 = lane & 3;
    for (int i = 0; i < NT; i++) {
        int s = i % 3;
        if (i >= NT - 2) { CPW0(); } else { CPW1(); }
        __syncthreads();
        const float* As = sm + s * (DTILE / 4);
        const float* Bs = sm + (3 + s) * (DTILE / 4);
#pragma unroll
        for (int kh = 0; kh < 2; kh++) {
            int c0 = c00 + kh * 8;
            uint32_t a[4][4];
#pragma unroll
            for (int ii = 0; ii < 4; ii++) {
                int r = ar0 + ii * 16;
                a[ii][0] = __float_as_uint(As[r * KP + c0]);
                a[ii][1] = __float_as_uint(As[(r + 8) * KP + c0]);
                a[ii][2] = __float_as_uint(As[r * KP + c0 + 4]);
                a[ii][3] = __float_as_uint(As[(r + 8) * KP + c0 + 4]);
            }
#pragma unroll
            for (int j = 0; j < 4; j++) {
                int rn = bn0 + j * 8;
                uint32_t b2[2] = { __float_as_uint(Bs[rn * KP + c0]),
                                   __float_as_uint(Bs[rn * KP + c0 + 4]) };
#pragma unroll
                for (int ii = 0; ii < 4; ii++) mma_t(acc[ii][j], a[ii], b2);
            }
        }
        if (i + 2 < NT) {
            int sp = (i + 2) % 3;
            stg(sp * DTILE, Ag, (i + 2) * 16);
            stg((3 + sp) * DTILE, Bg, (i + 2) * 16);
            CPC();
        }
    }
}

// MODE 0: fp32 C (final).  MODE 2: tf32-rounded C (q).
template<int MODE>
__global__ __launch_bounds__(256, 2)
void gemm_t(const float* __restrict__ A, const float* __restrict__ Bt,
            const float* __restrict__ bias, float* __restrict__ C) {
    const int tid = threadIdx.x, lane = tid & 31, wid = tid >> 5;
    const int wm = wid & 1, wn = wid >> 1;
    const int m0 = blockIdx.y * 128, n0 = blockIdx.x * 128;
    float acc[4][4][4];
#pragma unroll
    for (int i = 0; i < 4; i++)
#pragma unroll
        for (int j = 0; j < 4; j++)
#pragma unroll
            for (int e = 0; e < 4; e++) acc[i][j][e] = 0.0f;
    dense_mainloop(A + (size_t)m0 * DM, Bt + (size_t)n0 * DM, tid, lane, wm, wn, acc);
#pragma unroll
    for (int i = 0; i < 4; i++)
#pragma unroll
        for (int j = 0; j < 4; j++) {
            int m = m0 + wm * 64 + i * 16 + (lane >> 2);
            int n = n0 + wn * 32 + j * 8 + (lane & 3) * 2;
            float bz0 = bias[n], bz1 = bias[n + 1];
            float v00 = fmaxf(acc[i][j][0] + bz0, 0.0f), v01 = fmaxf(acc[i][j][1] + bz1, 0.0f);
            float v10 = fmaxf(acc[i][j][2] + bz0, 0.0f), v11 = fmaxf(acc[i][j][3] + bz1, 0.0f);
            if (MODE == 0) {
                *(float2*)&C[(size_t)m * DM + n]       = make_float2(v00, v01);
                *(float2*)&C[(size_t)(m + 8) * DM + n] = make_float2(v10, v11);
            } else {
                *(float2*)&C[(size_t)m * DM + n] =
                    make_float2(__uint_as_float(tf32r(v00)), __uint_as_float(tf32r(v01)));
                *(float2*)&C[(size_t)(m + 8) * DM + n] =
                    make_float2(__uint_as_float(tf32r(v10)), __uint_as_float(tf32r(v11)));
            }
        }
}

// merged K+V GEMM: B = [W1^T ; W2^T] (2048 rows), n<1024 -> k (tf32), n>=1024 -> vt (bf16 per head)
__global__ __launch_bounds__(256, 2)
void gemm_kv(const float* __restrict__ A, const float* __restrict__ Bt,
             const float* __restrict__ b1, const float* __restrict__ b2,
             float* __restrict__ K, uint16_t* __restrict__ VT) {
    const int tid = threadIdx.x, lane = tid & 31, wid = tid >> 5;
    const int wm = wid & 1, wn = wid >> 1;
    const int m0 = blockIdx.y * 128, n0 = blockIdx.x * 128;   // n0 in [0,2048)
    float acc[4][4][4];
#pragma unroll
    for (int i = 0; i < 4; i++)
#pragma unroll
        for (int j = 0; j < 4; j++)
#pragma unroll
            for (int e = 0; e < 4; e++) acc[i][j][e] = 0.0f;
    dense_mainloop(A + (size_t)m0 * DM, Bt + (size_t)n0 * DM, tid, lane, wm, wn, acc);
    const bool isK = (n0 < DM);
    const float* bias = isK ? b1 : b2;
    const int nb = isK ? n0 : (n0 - DM);
#pragma unroll
    for (int i = 0; i < 4; i++)
#pragma unroll
        for (int j = 0; j < 4; j++) {
            int m = m0 + wm * 64 + i * 16 + (lane >> 2);
            int n = nb + wn * 32 + j * 8 + (lane & 3) * 2;
            float bz0 = bias[n], bz1 = bias[n + 1];
            float v00 = fmaxf(acc[i][j][0] + bz0, 0.0f), v01 = fmaxf(acc[i][j][1] + bz1, 0.0f);
            float v10 = fmaxf(acc[i][j][2] + bz0, 0.0f), v11 = fmaxf(acc[i][j][3] + bz1, 0.0f);
            if (isK) {
                *(float2*)&K[(size_t)m * DM + n] =
                    make_float2(__uint_as_float(tf32r(v00)), __uint_as_float(tf32r(v01)));
                *(float2*)&K[(size_t)(m + 8) * DM + n] =
                    make_float2(__uint_as_float(tf32r(v10)), __uint_as_float(tf32r(v11)));
            } else {
                int bb = m >> 11, t = m & 2047, hh = n >> 6, e = n & 63;
                size_t base = ((size_t)(bb * 16 + hh) * 64 + e) * S_;
                VT[base + t]          = (uint16_t)(bfhi(v00) >> 16);
                VT[base + S_ + t]     = (uint16_t)(bfhi(v01) >> 16);
                VT[base + t + 8]      = (uint16_t)(bfhi(v10) >> 16);
                VT[base + S_ + t + 8] = (uint16_t)(bfhi(v11) >> 16);
            }
        }
}

// ---------------- fused flash attention (64-row s-tile, 3-stage k/v, 2 CTAs/SM) ----------
// smem: q[64][KPQ] f32 | k x3 | v x3 | srow[64]
#define QOFF   0
#define KST    17408
#define VOFF   (QOFF + 4 * KST)        // 69632
#define VST    9216
#define SROWO  (VOFF + 3 * VST)        // 97280
#define FSMEM  (SROWO + 256)           // 97536
#define TT     64
#define ITERS  (S_ / TT)   // 32
__global__ __launch_bounds__(256, 2)
void flash_attn(const float* __restrict__ q, const float* __restrict__ k,
                const uint16_t* __restrict__ vtb, const uint32_t* __restrict__ mp,
                float* __restrict__ O) {
    char* sm = smraw;
    const int tid = threadIdx.x, lane = tid & 31, wid = tid >> 5;
    const int wn = wid & 1, wm = wid >> 1;          // 2 t-col warps x 4 m-row warps
    const int bh = blockIdx.y, b = bh >> 4, h = bh & 15;
    const int s0 = blockIdx.x * 64;
    const uint32_t sb = smem_u32(sm);
    float* srow = (float*)(sm + SROWO);
    if (tid < 64) srow[tid] = 0.0f;

    const float* qg = q + ((size_t)b * S_ + s0) * DM + h * HD;
    const float* kg = k + (size_t)b * S_ * DM + h * HD;
    const uint16_t* vg = vtb + (size_t)bh * HD * S_;

#pragma unroll
    for (int p = 0; p < 4; p++) {
        int id = tid + p * 256, r = id >> 4, c = id & 15;
        cp16(sb + QOFF + (uint32_t)(r * KPQ + c * 4) * 4u, qg + (size_t)r * DM + c * 4);
    }
    CPC();
    auto stage_k = [&](int s, int t0) {
        const float* src = kg + (size_t)t0 * DM;
        uint32_t koff = KST + (uint32_t)s * KST;
#pragma unroll
        for (int p = 0; p < 4; p++) {
            int id = tid + p * 256, r = id >> 4, c = id & 15;
            cp16(sb + koff + (uint32_t)(r * KPQ + c * 4) * 4u, src + (size_t)r * DM + c * 4);
        }
    };
    auto stage_v = [&](int s, int t0) {
        uint32_t voff = VOFF + (uint32_t)s * VST;
#pragma unroll
        for (int p = 0; p < 2; p++) {
            int id = tid + p * 256, e = id >> 3, c = id & 7;
            cp16(sb + voff + (uint32_t)(e * KPV2 + c * 8) * 2u, vg + (size_t)e * S_ + t0 + c * 8);
        }
    };
    stage_k(0, 0);  stage_v(0, 0);  CPC();
    stage_k(1, TT); stage_v(1, TT); CPC();

    const int ar0 = wm * 16 + (lane >> 2);
    const int row = s0 + wm * 16 + (lane >> 2);
    const int bpl = (lane & 3) * 2;

    CPW2();             // q group complete
    __syncthreads();
    const float* Qs = (const float*)(sm + QOFF);
    uint32_t Qf[8][4];
#pragma unroll
    for (int kc = 0; kc < 8; kc++) {
        int c0 = kc * 8 + (lane & 3);
        Qf[kc][0] = __float_as_uint(Qs[ar0 * KPQ + c0]);
        Qf[kc][1] = __float_as_uint(Qs[(ar0 + 8) * KPQ + c0]);
        Qf[kc][2] = __float_as_uint(Qs[ar0 * KPQ + c0 + 4]);
        Qf[kc][3] = __float_as_uint(Qs[(ar0 + 8) * KPQ + c0 + 4]);
    }

    float acc2[8][4];
#pragma unroll
    for (int j = 0; j < 8; j++)
#pragma unroll
        for (int e = 0; e < 4; e++) acc2[j][e] = 0.0f;
    float rs2[2] = {0.f, 0.f};

    const int bn0 = wn * 32 + (lane >> 2);
    const float cf = SCALE_ * L2E;
    const uint32_t* mpr0 = mp + ((size_t)(b * S_ + row) << 6) + wn;
    const uint32_t* mpr1 = mpr0 + (8 << 6);
    const uint32_t vln = (uint32_t)(((((lane >> 4) & 1) * 8 + (lane & 7)) * KPV2 + ((lane >> 3) & 1) * 8) * 2);

    for (int it = 0; it < ITERS; it++) {
        const int s = it % 3;
        if (it >= ITERS - 2) { CPW0(); } else { CPW1(); }
        __syncthreads();
        const float* Ks = (const float*)(sm + KST + s * KST);
        const uint32_t vbase = sb + VOFF + (uint32_t)s * VST + vln;

        float acc[4][4];
#pragma unroll
        for (int j = 0; j < 4; j++)
#pragma unroll
            for (int e = 0; e < 4; e++) acc[j][e] = 0.0f;
#pragma unroll
        for (int kc = 0; kc < 8; kc++) {
            int c0 = kc * 8 + (lane & 3);
#pragma unroll
            for (int j = 0; j < 4; j++) {
                int rn = bn0 + j * 8;
                uint32_t b2[2] = { __float_as_uint(Ks[rn * KPQ + c0]),
                                   __float_as_uint(Ks[rn * KPQ + c0 + 4]) };
                mma_t(acc[j], Qf[kc], b2);
            }
        }

        const uint32_t w0 = mpr0[it * 2], w1 = mpr1[it * 2];
#pragma unroll
        for (int st = 0; st < 2; st++) {
            uint32_t af[4];
#pragma unroll
            for (int jj = 0; jj < 2; jj++) {
                int j = st * 2 + jj;
                int bp = j * 8 + bpl;
                float e00 = ex2a(((w0 >> bp) & 1u)       ? acc[j][0] * cf : -12000.0f);
                float e01 = ex2a(((w0 >> (bp + 1)) & 1u) ? acc[j][1] * cf : -12000.0f);
                float e10 = ex2a(((w1 >> bp) & 1u)       ? acc[j][2] * cf : -12000.0f);
                float e11 = ex2a(((w1 >> (bp + 1)) & 1u) ? acc[j][3] * cf : -12000.0f);
                rs2[0] += e00 + e01;
                rs2[1] += e10 + e11;
                af[jj * 2 + 0] = cvtbf2(e00, e01);
                af[jj * 2 + 1] = cvtbf2(e10, e11);
            }
            const uint32_t va = vbase + (uint32_t)((wn * 32 + st * 16) * 2);
#pragma unroll
            for (int p = 0; p < 4; p++) {
                uint32_t vf[4];
                LDSM4(vf, va + p * (16 * KPV2 * 2));
                uint32_t b2a[2] = { vf[0], vf[1] }, b2b[2] = { vf[2], vf[3] };
                mma_bf(acc2[p * 2 + 0], af, b2a);
                mma_bf(acc2[p * 2 + 1], af, b2b);
            }
        }
        if (it + 2 < ITERS) {
            int sp = (it + 2) % 3;
            stage_k(sp, (it + 2) * TT);
            stage_v(sp, (it + 2) * TT);
            CPC();
        }
    }

#pragma unroll
    for (int i = 0; i < 2; i++) {
        rs2[i] += __shfl_xor_sync(0xffffffffu, rs2[i], 1);
        rs2[i] += __shfl_xor_sync(0xffffffffu, rs2[i], 2);
    }
    __syncthreads();    // all compute done before reusing k-stage smem / srow atomics
    if ((lane & 3) == 0) {
        atomicAdd(&srow[wm * 16 + (lane >> 2)],     rs2[0]);
        atomicAdd(&srow[wm * 16 + (lane >> 2) + 8], rs2[1]);
    }
    __syncthreads();

    float* red = (float*)(sm + KST);   // reuse k stage 0: 16KB needed
    if (wn == 1) {
#pragma unroll
        for (int je = 0; je < 8; je++) {
            int rl = wm * 16 + (lane >> 2);
            int cl = je * 8 + (lane & 3) * 2;
            *(float2*)&red[(size_t)rl * 64 + cl]       = make_float2(acc2[je][0], acc2[je][1]);
            *(float2*)&red[(size_t)(rl + 8) * 64 + cl] = make_float2(acc2[je][2], acc2[je][3]);
        }
    }
    __syncthreads();
    if (wn == 0) {
        int rl0 = wm * 16 + (lane >> 2);
        float inv0 = 1.0f / srow[rl0];
        float inv1 = 1.0f / srow[rl0 + 8];
        int rowg = s0 + rl0;
        float* ob0 = O + ((size_t)bh * S_ + rowg) * HD;
        float* ob1 = O + ((size_t)bh * S_ + rowg + 8) * HD;
#pragma unroll
        for (int je = 0; je < 8; je++) {
            int cl = je * 8 + (lane & 3) * 2;
            float2 o0 = *(float2*)&red[(size_t)rl0 * 64 + cl];
            float2 o1 = *(float2*)&red[(size_t)(rl0 + 8) * 64 + cl];
            *(float2*)&ob0[cl] = make_float2(
                __uint_as_float(tf32r((acc2[je][0] + o0.x) * inv0)),
                __uint_as_float(tf32r((acc2[je][1] + o0.y) * inv0)));
            *(float2*)&ob1[cl] = make_float2(
                __uint_as_float(tf32r((acc2[je][2] + o1.x) * inv1)),
                __uint_as_float(tf32r((acc2[je][3] + o1.y) * inv1)));
        }
    }
}

// ---------------- small utility kernels ----------------
__global__ __launch_bounds__(256)
void round_x(const float* __restrict__ X, float* __restrict__ Y) {
    size_t i = (size_t)blockIdx.x * 256 + threadIdx.x;
    float2 v = ((const float2*)X)[i];
    ((float2*)Y)[i] = make_float2(__uint_as_float(tf32r(v.x)), __uint_as_float(tf32r(v.y)));
}

__global__ __launch_bounds__(256)
void maskpack(const int* __restrict__ mask, uint32_t* __restrict__ mp) {
    int w = blockIdx.x * 256 + threadIdx.x;
    const int4* src = (const int4*)mask + (size_t)w * 8;
    uint32_t bits = 0;
#pragma unroll
    for (int i = 0; i < 8; i++) {
        int4 v = src[i];
        bits |= (uint32_t)(v.x == 1) << (i * 4 + 0);
        bits |= (uint32_t)(v.y == 1) << (i * 4 + 1);
        bits |= (uint32_t)(v.z == 1) << (i * 4 + 2);
        bits |= (uint32_t)(v.w == 1) << (i * 4 + 3);
    }
    mp[w] = bits;
}

__global__ __launch_bounds__(256)
void transpose_tf32(const float* __restrict__ Wa, const float* __restrict__ Wb,
                    const float* __restrict__ Wc, const float* __restrict__ Wd,
                    float* __restrict__ Wt) {
    __shared__ float t[32][33];
    const int z = blockIdx.z;
    const float* W = (z == 0) ? Wa : (z == 1) ? Wb : (z == 2) ? Wc : Wd;
    float* Wo = Wt + (size_t)z * DM * DM;
    const int tx = threadIdx.x & 31, ty = threadIdx.x >> 5;
    const int bx = blockIdx.x * 32, by = blockIdx.y * 32;
#pragma unroll
    for (int j = 0; j < 32; j += 8) t[ty + j][tx] = W[(size_t)(by + ty + j) * DM + bx + tx];
    __syncthreads();
#pragma unroll
    for (int j = 0; j < 32; j += 8)
        Wo[(size_t)(bx + ty + j) * DM + by + tx] = __uint_as_float(tf32r(t[tx][ty + j]));
}

// ---------------- launch ----------------
extern "C" void kernel_launch(void* const* d_in, const int* in_sizes, int n_in,
                              void* d_out, int out_size) {
    (void)in_sizes; (void)n_in; (void)out_size;
    const float* x    = (const float*)d_in[0];
    const int*   mask = (const int*)d_in[1];
    const float* W0   = (const float*)d_in[2];
    const float* b0   = (const float*)d_in[3];
    const float* W1   = (const float*)d_in[4];
    const float* b1   = (const float*)d_in[5];
    const float* W2   = (const float*)d_in[6];
    const float* b2   = (const float*)d_in[7];
    const float* Wo   = (const float*)d_in[8];
    const float* bo   = (const float*)d_in[9];
    float* out = (float*)d_out;

    float *xr, *q, *k, *o, *wt;
    uint16_t *vt;
    uint32_t *mpd;
    cudaGetSymbolAddress((void**)&xr,  g_xr);
    cudaGetSymbolAddress((void**)&q,   g_q);
    cudaGetSymbolAddress((void**)&k,   g_k);
    cudaGetSymbolAddress((void**)&o,   g_o);
    cudaGetSymbolAddress((void**)&wt,  g_wt);
    cudaGetSymbolAddress((void**)&vt,  g_vt);
    cudaGetSymbolAddress((void**)&mpd, g_mp);
    const size_t WP = (size_t)DM * DM;

    cudaFuncSetAttribute(gemm_t<0>, cudaFuncAttributeMaxDynamicSharedMemorySize, DSMEM);
    cudaFuncSetAttribute(gemm_t<2>, cudaFuncAttributeMaxDynamicSharedMemorySize, DSMEM);
    cudaFuncSetAttribute(gemm_kv,   cudaFuncAttributeMaxDynamicSharedMemorySize, DSMEM);
    cudaFuncSetAttribute(flash_attn, cudaFuncAttributeMaxDynamicSharedMemorySize, FSMEM);

    round_x<<<MTOT * DM / 512, 256>>>(x, xr);
    maskpack<<<(B_ * S_ * 64) / 256, 256>>>(mask, mpd);
    transpose_tf32<<<dim3(32, 32, 4), 256>>>(W0, W1, W2, Wo, wt);

    gemm_t<2><<<dim3(8, 32), 256, DSMEM>>>(xr, wt + 0 * WP, b0, q);
    gemm_kv<<<dim3(16, 32), 256, DSMEM>>>(q, wt + 1 * WP, b1, b2, k, vt);
    flash_attn<<<dim3(32, 32), 256, FSMEM>>>(q, k, vt, mpd, o);
    gemm_t<0><<<dim3(8, 32), 256, DSMEM>>>(o, wt + 3 * WP, bo, out);
}

// round 12
// speedup vs baseline: 4.0717x; 1.1721x over previous
#include <cuda_runtime.h>
#include <cstdint>

#define B_       2
#define S_       2048
#define DM       1024
#define H_       16
#define HD       64
#define BH_      32
#define MTOT     4096
#define L2E      1.4426950408889634f
#define SCALE_   0.125f
#define DKP      36                  // dense fp32 smem row pad (floats) -> ldsm conflict-free
#define KPQ      68                  // q/k smem row pad (floats), flash (68%32=4, ldsm-safe)
#define KPV2     72                  // v smem row pad (halves), flash

// ---------------- scratch (device globals) ----------------
__device__ __align__(128) float    g_xr[MTOT * DM];            // x, tf32-rounded
__device__ __align__(128) float    g_q [MTOT * DM];            // q, tf32-rounded
__device__ __align__(128) float    g_k [MTOT * DM];            // k, tf32-rounded
__device__ __align__(128) float    g_o [MTOT * DM];            // attn out, tf32-rounded
__device__ __align__(128) float    g_wt[4][DM * DM];           // W^T tf32-rounded [n][k]; [1],[2] contiguous
__device__ __align__(128) uint16_t g_vt[BH_ * HD * S_];        // V^T bf16 per head [bh][e][t]
__device__ __align__(128) uint32_t g_mp[B_ * S_ * (S_ / 32)];  // packed mask bits, 1MB

extern __shared__ char smraw[];

// ---------------- helpers ----------------
__device__ __forceinline__ uint32_t smem_u32(const void* p) {
    uint32_t r;
    asm("{ .reg .u64 t; cvta.to.shared.u64 t, %1; cvt.u32.u64 %0, t; }" : "=r"(r) : "l"(p));
    return r;
}
__device__ __forceinline__ uint32_t tf32r(float x) {
    uint32_t u; asm("cvt.rna.tf32.f32 %0, %1;" : "=r"(u) : "f"(x)); return u;
}
__device__ __forceinline__ uint32_t bfhi(float x) {   // bf16 RNE, as fp32 bits (low16=0)
    uint32_t u = __float_as_uint(x);
    return (u + 0x7fffu + ((u >> 16) & 1u)) & 0xffff0000u;
}
__device__ __forceinline__ float ex2a(float x) {      // MUFU exp2
    float r; asm("ex2.approx.ftz.f32 %0, %1;" : "=f"(r) : "f"(x)); return r;
}
__device__ __forceinline__ uint32_t cvtbf2(float lo, float hi) {
    uint32_t r; asm("cvt.rn.bf16x2.f32 %0, %1, %2;" : "=r"(r) : "f"(hi), "f"(lo)); return r;
}
__device__ __forceinline__ void cp16(uint32_t d, const void* s) {
    asm volatile("cp.async.ca.shared.global [%0], [%1], 16;" :: "r"(d), "l"(s));
}
#define CPC()  asm volatile("cp.async.commit_group;")
#define CPW2() asm volatile("cp.async.wait_group 2;")
#define CPW1() asm volatile("cp.async.wait_group 1;")
#define CPW0() asm volatile("cp.async.wait_group 0;")

#define LDSM4(r, addr) \
    asm volatile("ldmatrix.sync.aligned.m8n8.x4.shared.b16 {%0,%1,%2,%3}, [%4];" \
                 : "=r"((r)[0]), "=r"((r)[1]), "=r"((r)[2]), "=r"((r)[3]) : "r"(addr))

__device__ __forceinline__ void mma_t(float* d, const uint32_t* a, const uint32_t* b) {
    asm volatile("mma.sync.aligned.m16n8k8.row.col.f32.tf32.tf32.f32 "
                 "{%0,%1,%2,%3},{%4,%5,%6,%7},{%8,%9},{%0,%1,%2,%3};"
                 : "+f"(d[0]), "+f"(d[1]), "+f"(d[2]), "+f"(d[3])
                 : "r"(a[0]), "r"(a[1]), "r"(a[2]), "r"(a[3]), "r"(b[0]), "r"(b[1]));
}
__device__ __forceinline__ void mma_bf(float* d, const uint32_t* a, const uint32_t* b) {
    asm volatile("mma.sync.aligned.m16n8k16.row.col.f32.bf16.bf16.f32 "
                 "{%0,%1,%2,%3},{%4,%5,%6,%7},{%8,%9},{%0,%1,%2,%3};"
                 : "+f"(d[0]), "+f"(d[1]), "+f"(d[2]), "+f"(d[3])
                 : "r"(a[0]), "r"(a[1]), "r"(a[2]), "r"(a[3]), "r"(b[0]), "r"(b[1]));
}

// ---------------- dense single-tf32 mainloop: k32 iters, 3-stage, ldmatrix fragments ------
#define DTILEA (128 * DKP * 4)         // 18432 B per 128x32 fp32 tile
#define DSTG   (2 * DTILEA)            // A + B per stage
#define DSMEM  (3 * DSTG)              // 110592
__device__ __forceinline__ void dense_mainloop(const float* Ag, const float* Bg,
                                               int tid, int lane, int wm, int wn,
                                               float (*acc)[4][4]) {
    const uint32_t sb = smem_u32(smraw);
    auto stg = [&](int s, int k0) {
        uint32_t off = sb + (uint32_t)s * DSTG;
#pragma unroll
        for (int p = 0; p < 4; p++) {
            int id = tid + p * 256;
            int r = id >> 3, c = (id & 7) * 4;
            cp16(off + (uint32_t)(r * DKP + c) * 4u, Ag + (size_t)r * DM + k0 + c);
            cp16(off + DTILEA + (uint32_t)(r * DKP + c) * 4u, Bg + (size_t)r * DM + k0 + c);
        }
    };
    stg(0, 0);  CPC();
    stg(1, 32); CPC();

    // ldmatrix lane bases (tf32-as-b16 trick):
    // A frag: rows sel bit3, col sel bit4.  B frag: rows sel bit4, col sel bit3.
    const uint32_t la = (uint32_t)((wm * 64 + ((lane >> 3) & 1) * 8 + (lane & 7)) * DKP * 4
                                   + ((lane >> 4) & 1) * 16);
    const uint32_t lb = (uint32_t)(DTILEA
                                   + (wn * 32 + ((lane >> 4) & 1) * 8 + (lane & 7)) * DKP * 4
                                   + ((lane >> 3) & 1) * 16);
    const int NT = DM / 32;   // 32
    for (int i = 0; i < NT; i++) {
        int s = i % 3;
        if (i >= NT - 2) { CPW0(); } else { CPW1(); }
        __syncthreads();
        const uint32_t abase = sb + (uint32_t)s * DSTG + la;
        const uint32_t bbase = sb + (uint32_t)s * DSTG + lb;
#pragma unroll
        for (int kh = 0; kh < 4; kh++) {            // 4 x k8 per k32 iter
            uint32_t bf0[4], bf1[4];
            LDSM4(bf0, bbase + kh * 32);                       // j0,j1
            LDSM4(bf1, bbase + kh * 32 + 16 * DKP * 4);        // j2,j3
#pragma unroll
            for (int ii = 0; ii < 4; ii++) {
                uint32_t af[4];
                LDSM4(af, abase + kh * 32 + ii * (16 * DKP * 4));
                mma_t(acc[ii][0], af, &bf0[0]);
                mma_t(acc[ii][1], af, &bf0[2]);
                mma_t(acc[ii][2], af, &bf1[0]);
                mma_t(acc[ii][3], af, &bf1[2]);
            }
        }
        if (i + 2 < NT) { stg((i + 2) % 3, (i + 2) * 32); CPC(); }
    }
}

// MODE 0: fp32 C (final).  MODE 2: tf32-rounded C (q).
template<int MODE>
__global__ __launch_bounds__(256, 2)
void gemm_t(const float* __restrict__ A, const float* __restrict__ Bt,
            const float* __restrict__ bias, float* __restrict__ C) {
    const int tid = threadIdx.x, lane = tid & 31, wid = tid >> 5;
    const int wm = wid & 1, wn = wid >> 1;
    const int m0 = blockIdx.y * 128, n0 = blockIdx.x * 128;
    float acc[4][4][4];
#pragma unroll
    for (int i = 0; i < 4; i++)
#pragma unroll
        for (int j = 0; j < 4; j++)
#pragma unroll
            for (int e = 0; e < 4; e++) acc[i][j][e] = 0.0f;
    dense_mainloop(A + (size_t)m0 * DM, Bt + (size_t)n0 * DM, tid, lane, wm, wn, acc);
#pragma unroll
    for (int i = 0; i < 4; i++)
#pragma unroll
        for (int j = 0; j < 4; j++) {
            int m = m0 + wm * 64 + i * 16 + (lane >> 2);
            int n = n0 + wn * 32 + j * 8 + (lane & 3) * 2;
            float bz0 = bias[n], bz1 = bias[n + 1];
            float v00 = fmaxf(acc[i][j][0] + bz0, 0.0f), v01 = fmaxf(acc[i][j][1] + bz1, 0.0f);
            float v10 = fmaxf(acc[i][j][2] + bz0, 0.0f), v11 = fmaxf(acc[i][j][3] + bz1, 0.0f);
            if (MODE == 0) {
                *(float2*)&C[(size_t)m * DM + n]       = make_float2(v00, v01);
                *(float2*)&C[(size_t)(m + 8) * DM + n] = make_float2(v10, v11);
            } else {
                *(float2*)&C[(size_t)m * DM + n] =
                    make_float2(__uint_as_float(tf32r(v00)), __uint_as_float(tf32r(v01)));
                *(float2*)&C[(size_t)(m + 8) * DM + n] =
                    make_float2(__uint_as_float(tf32r(v10)), __uint_as_float(tf32r(v11)));
            }
        }
}

// merged K+V GEMM: B = [W1^T ; W2^T] (2048 rows), n<1024 -> k (tf32), n>=1024 -> vt (bf16)
__global__ __launch_bounds__(256, 2)
void gemm_kv(const float* __restrict__ A, const float* __restrict__ Bt,
             const float* __restrict__ b1, const float* __restrict__ b2,
             float* __restrict__ K, uint16_t* __restrict__ VT) {
    const int tid = threadIdx.x, lane = tid & 31, wid = tid >> 5;
    const int wm = wid & 1, wn = wid >> 1;
    const int m0 = blockIdx.y * 128, n0 = blockIdx.x * 128;   // n0 in [0,2048)
    float acc[4][4][4];
#pragma unroll
    for (int i = 0; i < 4; i++)
#pragma unroll
        for (int j = 0; j < 4; j++)
#pragma unroll
            for (int e = 0; e < 4; e++) acc[i][j][e] = 0.0f;
    dense_mainloop(A + (size_t)m0 * DM, Bt + (size_t)n0 * DM, tid, lane, wm, wn, acc);
    const bool isK = (n0 < DM);
    const float* bias = isK ? b1 : b2;
    const int nb = isK ? n0 : (n0 - DM);
#pragma unroll
    for (int i = 0; i < 4; i++)
#pragma unroll
        for (int j = 0; j < 4; j++) {
            int m = m0 + wm * 64 + i * 16 + (lane >> 2);
            int n = nb + wn * 32 + j * 8 + (lane & 3) * 2;
            float bz0 = bias[n], bz1 = bias[n + 1];
            float v00 = fmaxf(acc[i][j][0] + bz0, 0.0f), v01 = fmaxf(acc[i][j][1] + bz1, 0.0f);
            float v10 = fmaxf(acc[i][j][2] + bz0, 0.0f), v11 = fmaxf(acc[i][j][3] + bz1, 0.0f);
            if (isK) {
                *(float2*)&K[(size_t)m * DM + n] =
                    make_float2(__uint_as_float(tf32r(v00)), __uint_as_float(tf32r(v01)));
                *(float2*)&K[(size_t)(m + 8) * DM + n] =
                    make_float2(__uint_as_float(tf32r(v10)), __uint_as_float(tf32r(v11)));
            } else {
                int bb = m >> 11, t = m & 2047, hh = n >> 6, e = n & 63;
                size_t base = ((size_t)(bb * 16 + hh) * 64 + e) * S_;
                VT[base + t]          = (uint16_t)(bfhi(v00) >> 16);
                VT[base + S_ + t]     = (uint16_t)(bfhi(v01) >> 16);
                VT[base + t + 8]      = (uint16_t)(bfhi(v10) >> 16);
                VT[base + S_ + t + 8] = (uint16_t)(bfhi(v11) >> 16);
            }
        }
}

// ---------------- fused flash attention (64-row s-tile, 3-stage k/v, 2 CTAs/SM) ----------
// smem: q[64][KPQ] f32 | k x3 | v x3 | srow[64]
#define QOFF   0
#define KST    17408
#define VOFF   (QOFF + 4 * KST)        // 69632
#define VST    9216
#define SROWO  (VOFF + 3 * VST)        // 97280
#define FSMEM  (SROWO + 256)           // 97536
#define TT     64
#define ITERS  (S_ / TT)   // 32
__global__ __launch_bounds__(256, 2)
void flash_attn(const float* __restrict__ q, const float* __restrict__ k,
                const uint16_t* __restrict__ vtb, const uint32_t* __restrict__ mp,
                float* __restrict__ O) {
    char* sm = smraw;
    const int tid = threadIdx.x, lane = tid & 31, wid = tid >> 5;
    const int wn = wid & 1, wm = wid >> 1;          // 2 t-col warps x 4 m-row warps
    const int bh = blockIdx.y, b = bh >> 4, h = bh & 15;
    const int s0 = blockIdx.x * 64;
    const uint32_t sb = smem_u32(sm);
    float* srow = (float*)(sm + SROWO);
    if (tid < 64) srow[tid] = 0.0f;

    const float* qg = q + ((size_t)b * S_ + s0) * DM + h * HD;
    const float* kg = k + (size_t)b * S_ * DM + h * HD;
    const uint16_t* vg = vtb + (size_t)bh * HD * S_;

#pragma unroll
    for (int p = 0; p < 4; p++) {
        int id = tid + p * 256, r = id >> 4, c = id & 15;
        cp16(sb + QOFF + (uint32_t)(r * KPQ + c * 4) * 4u, qg + (size_t)r * DM + c * 4);
    }
    CPC();
    auto stage_k = [&](int s, int t0) {
        const float* src = kg + (size_t)t0 * DM;
        uint32_t koff = KST + (uint32_t)s * KST;
#pragma unroll
        for (int p = 0; p < 4; p++) {
            int id = tid + p * 256, r = id >> 4, c = id & 15;
            cp16(sb + koff + (uint32_t)(r * KPQ + c * 4) * 4u, src + (size_t)r * DM + c * 4);
        }
    };
    auto stage_v = [&](int s, int t0) {
        uint32_t voff = VOFF + (uint32_t)s * VST;
#pragma unroll
        for (int p = 0; p < 2; p++) {
            int id = tid + p * 256, e = id >> 3, c = id & 7;
            cp16(sb + voff + (uint32_t)(e * KPV2 + c * 8) * 2u, vg + (size_t)e * S_ + t0 + c * 8);
        }
    };
    stage_k(0, 0);  stage_v(0, 0);  CPC();
    stage_k(1, TT); stage_v(1, TT); CPC();

    const int ar0 = wm * 16 + (lane >> 2);
    const int row = s0 + wm * 16 + (lane >> 2);
    const int bpl = (lane & 3) * 2;

    CPW2();             // q group complete
    __syncthreads();
    const float* Qs = (const float*)(sm + QOFF);
    uint32_t Qf[8][4];
#pragma unroll
    for (int kc = 0; kc < 8; kc++) {
        int c0 = kc * 8 + (lane & 3);
        Qf[kc][0] = __float_as_uint(Qs[ar0 * KPQ + c0]);
        Qf[kc][1] = __float_as_uint(Qs[(ar0 + 8) * KPQ + c0]);
        Qf[kc][2] = __float_as_uint(Qs[ar0 * KPQ + c0 + 4]);
        Qf[kc][3] = __float_as_uint(Qs[(ar0 + 8) * KPQ + c0 + 4]);
    }

    float acc2[8][4];
#pragma unroll
    for (int j = 0; j < 8; j++)
#pragma unroll
        for (int e = 0; e < 4; e++) acc2[j][e] = 0.0f;
    float rs2[2] = {0.f, 0.f};

    const float cf = SCALE_ * L2E;
    const uint32_t* mpr0 = mp + ((size_t)(b * S_ + row) << 6) + wn;
    const uint32_t* mpr1 = mpr0 + (8 << 6);
    // K-fragment ldmatrix lane base (B-frag pattern: row sel bit4, col sel bit3)
    const uint32_t lk = (uint32_t)((wn * 32 + ((lane >> 4) & 1) * 8 + (lane & 7)) * KPQ * 4
                                   + ((lane >> 3) & 1) * 16);
    const uint32_t vln = (uint32_t)(((((lane >> 4) & 1) * 8 + (lane & 7)) * KPV2 + ((lane >> 3) & 1) * 8) * 2);

    for (int it = 0; it < ITERS; it++) {
        const int s = it % 3;
        if (it >= ITERS - 2) { CPW0(); } else { CPW1(); }
        __syncthreads();
        const uint32_t kbase = sb + KST + (uint32_t)s * KST + lk;
        const uint32_t vbase = sb + VOFF + (uint32_t)s * VST + vln;

        float acc[4][4];
#pragma unroll
        for (int j = 0; j < 4; j++)
#pragma unroll
            for (int e = 0; e < 4; e++) acc[j][e] = 0.0f;
#pragma unroll
        for (int kc = 0; kc < 8; kc++) {
            uint32_t kf0[4], kf1[4];
            LDSM4(kf0, kbase + kc * 32);                       // j0,j1
            LDSM4(kf1, kbase + kc * 32 + 16 * KPQ * 4);        // j2,j3
            mma_t(acc[0], Qf[kc], &kf0[0]);
            mma_t(acc[1], Qf[kc], &kf0[2]);
            mma_t(acc[2], Qf[kc], &kf1[0]);
            mma_t(acc[3], Qf[kc], &kf1[2]);
        }

        const uint32_t w0 = mpr0[it * 2], w1 = mpr1[it * 2];
#pragma unroll
        for (int st = 0; st < 2; st++) {
            uint32_t af[4];
#pragma unroll
            for (int jj = 0; jj < 2; jj++) {
                int j = st * 2 + jj;
                int bp = j * 8 + bpl;
                float e00 = ex2a(((w0 >> bp) & 1u)       ? acc[j][0] * cf : -12000.0f);
                float e01 = ex2a(((w0 >> (bp + 1)) & 1u) ? acc[j][1] * cf : -12000.0f);
                float e10 = ex2a(((w1 >> bp) & 1u)       ? acc[j][2] * cf : -12000.0f);
                float e11 = ex2a(((w1 >> (bp + 1)) & 1u) ? acc[j][3] * cf : -12000.0f);
                rs2[0] += e00 + e01;
                rs2[1] += e10 + e11;
                af[jj * 2 + 0] = cvtbf2(e00, e01);
                af[jj * 2 + 1] = cvtbf2(e10, e11);
            }
            const uint32_t va = vbase + (uint32_t)((wn * 32 + st * 16) * 2);
#pragma unroll
            for (int p = 0; p < 4; p++) {
                uint32_t vf[4];
                LDSM4(vf, va + p * (16 * KPV2 * 2));
                mma_bf(acc2[p * 2 + 0], af, &vf[0]);
                mma_bf(acc2[p * 2 + 1], af, &vf[2]);
            }
        }
        if (it + 2 < ITERS) {
            int sp = (it + 2) % 3;
            stage_k(sp, (it + 2) * TT);
            stage_v(sp, (it + 2) * TT);
            CPC();
        }
    }

#pragma unroll
    for (int i = 0; i < 2; i++) {
        rs2[i] += __shfl_xor_sync(0xffffffffu, rs2[i], 1);
        rs2[i] += __shfl_xor_sync(0xffffffffu, rs2[i], 2);
    }
    __syncthreads();
    if ((lane & 3) == 0) {
        atomicAdd(&srow[wm * 16 + (lane >> 2)],     rs2[0]);
        atomicAdd(&srow[wm * 16 + (lane >> 2) + 8], rs2[1]);
    }
    __syncthreads();

    float* red = (float*)(sm + KST);   // reuse k stage 0: 16KB
    if (wn == 1) {
#pragma unroll
        for (int je = 0; je < 8; je++) {
            int rl = wm * 16 + (lane >> 2);
            int cl = je * 8 + (lane & 3) * 2;
            *(float2*)&red[(size_t)rl * 64 + cl]       = make_float2(acc2[je][0], acc2[je][1]);
            *(float2*)&red[(size_t)(rl + 8) * 64 + cl] = make_float2(acc2[je][2], acc2[je][3]);
        }
    }
    __syncthreads();
    if (wn == 0) {
        int rl0 = wm * 16 + (lane >> 2);
        float inv0 = 1.0f / srow[rl0];
        float inv1 = 1.0f / srow[rl0 + 8];
        int rowg = s0 + rl0;
        float* ob0 = O + ((size_t)bh * S_ + rowg) * HD;
        float* ob1 = O + ((size_t)bh * S_ + rowg + 8) * HD;
#pragma unroll
        for (int je = 0; je < 8; je++) {
            int cl = je * 8 + (lane & 3) * 2;
            float2 o0 = *(float2*)&red[(size_t)rl0 * 64 + cl];
            float2 o1 = *(float2*)&red[(size_t)(rl0 + 8) * 64 + cl];
            *(float2*)&ob0[cl] = make_float2(
                __uint_as_float(tf32r((acc2[je][0] + o0.x) * inv0)),
                __uint_as_float(tf32r((acc2[je][1] + o0.y) * inv0)));
            *(float2*)&ob1[cl] = make_float2(
                __uint_as_float(tf32r((acc2[je][2] + o1.x) * inv1)),
                __uint_as_float(tf32r((acc2[je][3] + o1.y) * inv1)));
        }
    }
}

// ---------------- small utility kernels ----------------
__global__ __launch_bounds__(256)
void round_x(const float* __restrict__ X, float* __restrict__ Y) {
    size_t i = (size_t)blockIdx.x * 256 + threadIdx.x;
    float2 v = ((const float2*)X)[i];
    ((float2*)Y)[i] = make_float2(__uint_as_float(tf32r(v.x)), __uint_as_float(tf32r(v.y)));
}

__global__ __launch_bounds__(256)
void maskpack(const int* __restrict__ mask, uint32_t* __restrict__ mp) {
    int w = blockIdx.x * 256 + threadIdx.x;
    const int4* src = (const int4*)mask + (size_t)w * 8;
    uint32_t bits = 0;
#pragma unroll
    for (int i = 0; i < 8; i++) {
        int4 v = src[i];
        bits |= (uint32_t)(v.x == 1) << (i * 4 + 0);
        bits |= (uint32_t)(v.y == 1) << (i * 4 + 1);
        bits |= (uint32_t)(v.z == 1) << (i * 4 + 2);
        bits |= (uint32_t)(v.w == 1) << (i * 4 + 3);
    }
    mp[w] = bits;
}

__global__ __launch_bounds__(256)
void transpose_tf32(const float* __restrict__ Wa, const float* __restrict__ Wb,
                    const float* __restrict__ Wc, const float* __restrict__ Wd,
                    float* __restrict__ Wt) {
    __shared__ float t[32][33];
    const int z = blockIdx.z;
    const float* W = (z == 0) ? Wa : (z == 1) ? Wb : (z == 2) ? Wc : Wd;
    float* Wo = Wt + (size_t)z * DM * DM;
    const int tx = threadIdx.x & 31, ty = threadIdx.x >> 5;
    const int bx = blockIdx.x * 32, by = blockIdx.y * 32;
#pragma unroll
    for (int j = 0; j < 32; j += 8) t[ty + j][tx] = W[(size_t)(by + ty + j) * DM + bx + tx];
    __syncthreads();
#pragma unroll
    for (int j = 0; j < 32; j += 8)
        Wo[(size_t)(bx + ty + j) * DM + by + tx] = __uint_as_float(tf32r(t[tx][ty + j]));
}

// ---------------- launch ----------------
extern "C" void kernel_launch(void* const* d_in, const int* in_sizes, int n_in,
                              void* d_out, int out_size) {
    (void)in_sizes; (void)n_in; (void)out_size;
    const float* x    = (const float*)d_in[0];
    const int*   mask = (const int*)d_in[1];
    const float* W0   = (const float*)d_in[2];
    const float* b0   = (const float*)d_in[3];
    const float* W1   = (const float*)d_in[4];
    const float* b1   = (const float*)d_in[5];
    const float* W2   = (const float*)d_in[6];
    const float* b2   = (const float*)d_in[7];
    const float* Wo   = (const float*)d_in[8];
    const float* bo   = (const float*)d_in[9];
    float* out = (float*)d_out;

    float *xr, *q, *k, *o, *wt;
    uint16_t *vt;
    uint32_t *mpd;
    cudaGetSymbolAddress((void**)&xr,  g_xr);
    cudaGetSymbolAddress((void**)&q,   g_q);
    cudaGetSymbolAddress((void**)&k,   g_k);
    cudaGetSymbolAddress((void**)&o,   g_o);
    cudaGetSymbolAddress((void**)&wt,  g_wt);
    cudaGetSymbolAddress((void**)&vt,  g_vt);
    cudaGetSymbolAddress((void**)&mpd, g_mp);
    const size_t WP = (size_t)DM * DM;

    cudaFuncSetAttribute(gemm_t<0>, cudaFuncAttributeMaxDynamicSharedMemorySize, DSMEM);
    cudaFuncSetAttribute(gemm_t<2>, cudaFuncAttributeMaxDynamicSharedMemorySize, DSMEM);
    cudaFuncSetAttribute(gemm_kv,   cudaFuncAttributeMaxDynamicSharedMemorySize, DSMEM);
    cudaFuncSetAttribute(flash_attn, cudaFuncAttributeMaxDynamicSharedMemorySize, FSMEM);

    round_x<<<MTOT * DM / 512, 256>>>(x, xr);
    maskpack<<<(B_ * S_ * 64) / 256, 256>>>(mask, mpd);
    transpose_tf32<<<dim3(32, 32, 4), 256>>>(W0, W1, W2, Wo, wt);

    gemm_t<2><<<dim3(8, 32), 256, DSMEM>>>(xr, wt + 0 * WP, b0, q);
    gemm_kv<<<dim3(16, 32), 256, DSMEM>>>(q, wt + 1 * WP, b1, b2, k, vt);
    flash_attn<<<dim3(32, 32), 256, FSMEM>>>(q, k, vt, mpd, o);
    gemm_t<0><<<dim3(8, 32), 256, DSMEM>>>(o, wt + 3 * WP, bo, out);
}

// round 13
// speedup vs baseline: 5.9928x; 1.4718x over previous
#include <cuda_runtime.h>
#include <cstdint>

#define B_       2
#define S_       2048
#define DM       1024
#define H_       16
#define HD       64
#define BH_      32
#define MTOT     4096
#define L2E      1.4426950408889634f
#define SCALE_   0.125f
#define KPH      40                  // dense fp16 smem row pad (halves) -> 80B pitch, ldsm conflict-free
#define KPQ2     72                  // flash q/k fp16 pad (halves) -> 144B pitch
#define KPV2     72                  // flash v fp16 pad (halves)

// ---------------- scratch (device globals) ----------------
__device__ __align__(128) uint16_t g_xh[MTOT * DM];            // x fp16
__device__ __align__(128) uint16_t g_qh[MTOT * DM];            // q fp16
__device__ __align__(128) uint16_t g_kh[MTOT * DM];            // k fp16
__device__ __align__(128) uint16_t g_oh[MTOT * DM];            // attn out fp16 (flat)
__device__ __align__(128) uint16_t g_wt[4][DM * DM];           // W^T fp16 [n][k]; [1],[2] contiguous
__device__ __align__(128) uint16_t g_vt[BH_ * HD * S_];        // V^T fp16 per head [bh][e][t]
__device__ __align__(128) uint32_t g_mp[B_ * S_ * (S_ / 32)];  // packed mask bits, 1MB

extern __shared__ char smraw[];

// ---------------- helpers ----------------
__device__ __forceinline__ uint32_t smem_u32(const void* p) {
    uint32_t r;
    asm("{ .reg .u64 t; cvta.to.shared.u64 t, %1; cvt.u32.u64 %0, t; }" : "=r"(r) : "l"(p));
    return r;
}
__device__ __forceinline__ uint16_t f2h(float x) {
    uint16_t h; asm("cvt.rn.f16.f32 %0, %1;" : "=h"(h) : "f"(x)); return h;
}
__device__ __forceinline__ uint32_t cvth2(float lo, float hi) {  // pack {lo,hi} -> f16x2
    uint32_t r; asm("cvt.rn.f16x2.f32 %0, %1, %2;" : "=r"(r) : "f"(hi), "f"(lo)); return r;
}
__device__ __forceinline__ float ex2a(float x) {      // MUFU exp2
    float r; asm("ex2.approx.ftz.f32 %0, %1;" : "=f"(r) : "f"(x)); return r;
}
__device__ __forceinline__ void cp16(uint32_t d, const void* s) {
    asm volatile("cp.async.ca.shared.global [%0], [%1], 16;" :: "r"(d), "l"(s));
}
#define CPC()  asm volatile("cp.async.commit_group;")
#define CPW2() asm volatile("cp.async.wait_group 2;")
#define CPW1() asm volatile("cp.async.wait_group 1;")
#define CPW0() asm volatile("cp.async.wait_group 0;")

#define LDSM4(r, addr) \
    asm volatile("ldmatrix.sync.aligned.m8n8.x4.shared.b16 {%0,%1,%2,%3}, [%4];" \
                 : "=r"((r)[0]), "=r"((r)[1]), "=r"((r)[2]), "=r"((r)[3]) : "r"(addr))

__device__ __forceinline__ void mma_h(float* d, const uint32_t* a, const uint32_t* b) {
    asm volatile("mma.sync.aligned.m16n8k16.row.col.f32.f16.f16.f32 "
                 "{%0,%1,%2,%3},{%4,%5,%6,%7},{%8,%9},{%0,%1,%2,%3};"
                 : "+f"(d[0]), "+f"(d[1]), "+f"(d[2]), "+f"(d[3])
                 : "r"(a[0]), "r"(a[1]), "r"(a[2]), "r"(a[3]), "r"(b[0]), "r"(b[1]));
}

// ---------------- dense fp16 mainloop: k32 iters, 3-stage, ldmatrix fragments ------
#define DTILEH (128 * KPH * 2)         // 10240 B per 128x32 fp16 tile
#define DSTG   (2 * DTILEH)            // 20480
#define DSMEM  (3 * DSTG)              // 61440
__device__ __forceinline__ void dense_mainloop(const uint16_t* Ag, const uint16_t* Bg,
                                               int tid, int lane, int wm, int wn,
                                               float (*acc)[4][4]) {
    const uint32_t sb = smem_u32(smraw);
    auto stg = [&](int s, int k0) {
        uint32_t off = sb + (uint32_t)s * DSTG;
#pragma unroll
        for (int p = 0; p < 2; p++) {
            int id = tid + p * 256;
            int r = id >> 2, c = (id & 3) * 8;       // 8 halves = 16B
            cp16(off + (uint32_t)(r * KPH + c) * 2u, Ag + (size_t)r * DM + k0 + c);
            cp16(off + DTILEH + (uint32_t)(r * KPH + c) * 2u, Bg + (size_t)r * DM + k0 + c);
        }
    };
    stg(0, 0);  CPC();
    stg(1, 32); CPC();

    // ldsm lane bases (bytes; pitch 80B). A: row sel bit3, col sel bit4. B: row sel bit4, col sel bit3.
    const uint32_t la = (uint32_t)((wm * 64 + ((lane >> 3) & 1) * 8 + (lane & 7)) * 80
                                   + ((lane >> 4) & 1) * 16);
    const uint32_t lb = (uint32_t)(DTILEH
                                   + (wn * 32 + ((lane >> 4) & 1) * 8 + (lane & 7)) * 80
                                   + ((lane >> 3) & 1) * 16);
    const int NT = DM / 32;   // 32
    for (int i = 0; i < NT; i++) {
        int s = i % 3;
        if (i >= NT - 2) { CPW0(); } else { CPW1(); }
        __syncthreads();
        const uint32_t abase = sb + (uint32_t)s * DSTG + la;
        const uint32_t bbase = sb + (uint32_t)s * DSTG + lb;
#pragma unroll
        for (int kh = 0; kh < 2; kh++) {            // 2 x k16 per k32 iter
            uint32_t bf0[4], bf1[4];
            LDSM4(bf0, bbase + kh * 32);                   // n0-15: j0,j1
            LDSM4(bf1, bbase + kh * 32 + 16 * 80);         // n16-31: j2,j3
#pragma unroll
            for (int ii = 0; ii < 4; ii++) {
                uint32_t af[4];
                LDSM4(af, abase + kh * 32 + ii * (16 * 80));
                mma_h(acc[ii][0], af, &bf0[0]);
                mma_h(acc[ii][1], af, &bf0[2]);
                mma_h(acc[ii][2], af, &bf1[0]);
                mma_h(acc[ii][3], af, &bf1[2]);
            }
        }
        if (i + 2 < NT) { stg((i + 2) % 3, (i + 2) * 32); CPC(); }
    }
}

// MODE 0: fp32 C (final).  MODE 2: fp16 Ch (q / k inputs to attention).
template<int MODE>
__global__ __launch_bounds__(256, 2)
void gemm_h(const uint16_t* __restrict__ A, const uint16_t* __restrict__ Bt,
            const float* __restrict__ bias, float* __restrict__ C,
            uint16_t* __restrict__ Ch) {
    const int tid = threadIdx.x, lane = tid & 31, wid = tid >> 5;
    const int wm = wid & 1, wn = wid >> 1;
    const int m0 = blockIdx.y * 128, n0 = blockIdx.x * 128;
    float acc[4][4][4];
#pragma unroll
    for (int i = 0; i < 4; i++)
#pragma unroll
        for (int j = 0; j < 4; j++)
#pragma unroll
            for (int e = 0; e < 4; e++) acc[i][j][e] = 0.0f;
    dense_mainloop(A + (size_t)m0 * DM, Bt + (size_t)n0 * DM, tid, lane, wm, wn, acc);
#pragma unroll
    for (int i = 0; i < 4; i++)
#pragma unroll
        for (int j = 0; j < 4; j++) {
            int m = m0 + wm * 64 + i * 16 + (lane >> 2);
            int n = n0 + wn * 32 + j * 8 + (lane & 3) * 2;
            float bz0 = bias[n], bz1 = bias[n + 1];
            float v00 = fmaxf(acc[i][j][0] + bz0, 0.0f), v01 = fmaxf(acc[i][j][1] + bz1, 0.0f);
            float v10 = fmaxf(acc[i][j][2] + bz0, 0.0f), v11 = fmaxf(acc[i][j][3] + bz1, 0.0f);
            if (MODE == 0) {
                *(float2*)&C[(size_t)m * DM + n]       = make_float2(v00, v01);
                *(float2*)&C[(size_t)(m + 8) * DM + n] = make_float2(v10, v11);
            } else {
                ((uint32_t*)Ch)[((size_t)m * DM + n) >> 1]       = cvth2(v00, v01);
                ((uint32_t*)Ch)[((size_t)(m + 8) * DM + n) >> 1] = cvth2(v10, v11);
            }
        }
}

// merged K+V GEMM: B = [W1^T ; W2^T] (2048 rows), n<1024 -> kh (fp16), n>=1024 -> vt (fp16 per head)
__global__ __launch_bounds__(256, 2)
void gemm_kv(const uint16_t* __restrict__ A, const uint16_t* __restrict__ Bt,
             const float* __restrict__ b1, const float* __restrict__ b2,
             uint16_t* __restrict__ K, uint16_t* __restrict__ VT) {
    const int tid = threadIdx.x, lane = tid & 31, wid = tid >> 5;
    const int wm = wid & 1, wn = wid >> 1;
    const int m0 = blockIdx.y * 128, n0 = blockIdx.x * 128;   // n0 in [0,2048)
    float acc[4][4][4];
#pragma unroll
    for (int i = 0; i < 4; i++)
#pragma unroll
        for (int j = 0; j < 4; j++)
#pragma unroll
            for (int e = 0; e < 4; e++) acc[i][j][e] = 0.0f;
    dense_mainloop(A + (size_t)m0 * DM, Bt + (size_t)n0 * DM, tid, lane, wm, wn, acc);
    const bool isK = (n0 < DM);
    const float* bias = isK ? b1 : b2;
    const int nb = isK ? n0 : (n0 - DM);
#pragma unroll
    for (int i = 0; i < 4; i++)
#pragma unroll
        for (int j = 0; j < 4; j++) {
            int m = m0 + wm * 64 + i * 16 + (lane >> 2);
            int n = nb + wn * 32 + j * 8 + (lane & 3) * 2;
            float bz0 = bias[n], bz1 = bias[n + 1];
            float v00 = fmaxf(acc[i][j][0] + bz0, 0.0f), v01 = fmaxf(acc[i][j][1] + bz1, 0.0f);
            float v10 = fmaxf(acc[i][j][2] + bz0, 0.0f), v11 = fmaxf(acc[i][j][3] + bz1, 0.0f);
            if (isK) {
                ((uint32_t*)K)[((size_t)m * DM + n) >> 1]       = cvth2(v00, v01);
                ((uint32_t*)K)[((size_t)(m + 8) * DM + n) >> 1] = cvth2(v10, v11);
            } else {
                int bb = m >> 11, t = m & 2047, hh = n >> 6, e = n & 63;
                size_t base = ((size_t)(bb * 16 + hh) * 64 + e) * S_;
                VT[base + t]          = f2h(v00);
                VT[base + S_ + t]     = f2h(v01);
                VT[base + t + 8]      = f2h(v10);
                VT[base + S_ + t + 8] = f2h(v11);
            }
        }
}

// ---------------- fused flash attention (64-row s-tile, 3-stage k/v, fp16, 2 CTAs/SM) ----------
// smem: q[64][72]h | k x3 [64][72]h | v x3 [64][72]h | srow[64] f32
#define QSZ    (64 * KPQ2 * 2)         // 9216
#define KOFF   QSZ
#define VOFF   (QSZ + 3 * QSZ)         // 36864
#define SROWO  (VOFF + 3 * QSZ)        // 64512
#define FSMEM  (SROWO + 256)           // 64768
#define TT     64
#define ITERS  (S_ / TT)   // 32
__global__ __launch_bounds__(256, 2)
void flash_attn(const uint16_t* __restrict__ q, const uint16_t* __restrict__ k,
                const uint16_t* __restrict__ vtb, const uint32_t* __restrict__ mp,
                uint16_t* __restrict__ O) {
    char* sm = smraw;
    const int tid = threadIdx.x, lane = tid & 31, wid = tid >> 5;
    const int wn = wid & 1, wm = wid >> 1;          // 2 t-col warps x 4 m-row warps
    const int bh = blockIdx.y, b = bh >> 4, h = bh & 15;
    const int s0 = blockIdx.x * 64;
    const uint32_t sb = smem_u32(sm);
    float* srow = (float*)(sm + SROWO);
    if (tid < 64) srow[tid] = 0.0f;

    const uint16_t* qg = q + ((size_t)b * S_ + s0) * DM + h * HD;
    const uint16_t* kg = k + (size_t)b * S_ * DM + h * HD;
    const uint16_t* vg = vtb + (size_t)bh * HD * S_;

#pragma unroll
    for (int p = 0; p < 2; p++) {        // q: 64 rows x 8 chunks
        int id = tid + p * 256, r = id >> 3, c = (id & 7) * 8;
        cp16(sb + (uint32_t)(r * KPQ2 + c) * 2u, qg + (size_t)r * DM + c);
    }
    CPC();
    auto stage_k = [&](int s, int t0) {
        const uint16_t* src = kg + (size_t)t0 * DM;
        uint32_t koff = KOFF + (uint32_t)s * QSZ;
#pragma unroll
        for (int p = 0; p < 2; p++) {
            int id = tid + p * 256, r = id >> 3, c = (id & 7) * 8;
            cp16(sb + koff + (uint32_t)(r * KPQ2 + c) * 2u, src + (size_t)r * DM + c);
        }
    };
    auto stage_v = [&](int s, int t0) {
        uint32_t voff = VOFF + (uint32_t)s * QSZ;
#pragma unroll
        for (int p = 0; p < 2; p++) {
            int id = tid + p * 256, e = id >> 3, c = (id & 7) * 8;
            cp16(sb + voff + (uint32_t)(e * KPV2 + c) * 2u, vg + (size_t)e * S_ + t0 + c);
        }
    };
    stage_k(0, 0);  stage_v(0, 0);  CPC();
    stage_k(1, TT); stage_v(1, TT); CPC();

    const int row = s0 + wm * 16 + (lane >> 2);
    const int bpl = (lane & 3) * 2;

    CPW2();             // q group complete
    __syncthreads();
    // hoist Q A-fragments: 4 k16 chunks x 4 regs (ldsm; row sel bit3, col sel bit4)
    const uint32_t qb = sb + (uint32_t)((wm * 16 + ((lane >> 3) & 1) * 8 + (lane & 7)) * 144
                                        + ((lane >> 4) & 1) * 16);
    uint32_t Qf[4][4];
#pragma unroll
    for (int kc = 0; kc < 4; kc++) LDSM4(Qf[kc], qb + kc * 32);

    float acc2[8][4];
#pragma unroll
    for (int j = 0; j < 8; j++)
#pragma unroll
        for (int e = 0; e < 4; e++) acc2[j][e] = 0.0f;
    float rs2[2] = {0.f, 0.f};

    const float cf = SCALE_ * L2E;
    const uint32_t* mpr0 = mp + ((size_t)(b * S_ + row) << 6) + wn;
    const uint32_t* mpr1 = mpr0 + (8 << 6);
    // K B-fragments (row sel bit4, col sel bit3), V likewise
    const uint32_t lk = (uint32_t)((wn * 32 + ((lane >> 4) & 1) * 8 + (lane & 7)) * 144
                                   + ((lane >> 3) & 1) * 16);
    const uint32_t vln = (uint32_t)((((lane >> 4) & 1) * 8 + (lane & 7)) * 144
                                    + ((lane >> 3) & 1) * 16);

    for (int it = 0; it < ITERS; it++) {
        const int s = it % 3;
        if (it >= ITERS - 2) { CPW0(); } else { CPW1(); }
        __syncthreads();
        const uint32_t kbase = sb + KOFF + (uint32_t)s * QSZ + lk;
        const uint32_t vbase = sb + VOFF + (uint32_t)s * QSZ + vln;

        float acc[4][4];
#pragma unroll
        for (int j = 0; j < 4; j++)
#pragma unroll
            for (int e = 0; e < 4; e++) acc[j][e] = 0.0f;
#pragma unroll
        for (int kc = 0; kc < 4; kc++) {             // 4 x k16
            uint32_t kf0[4], kf1[4];
            LDSM4(kf0, kbase + kc * 32);                   // t0-15: j0,j1
            LDSM4(kf1, kbase + kc * 32 + 16 * 144);        // t16-31: j2,j3
            mma_h(acc[0], Qf[kc], &kf0[0]);
            mma_h(acc[1], Qf[kc], &kf0[2]);
            mma_h(acc[2], Qf[kc], &kf1[0]);
            mma_h(acc[3], Qf[kc], &kf1[2]);
        }

        const uint32_t w0 = mpr0[it * 2], w1 = mpr1[it * 2];
#pragma unroll
        for (int st = 0; st < 2; st++) {
            uint32_t af[4];
#pragma unroll
            for (int jj = 0; jj < 2; jj++) {
                int j = st * 2 + jj;
                int bp = j * 8 + bpl;
                float e00 = ex2a(((w0 >> bp) & 1u)       ? acc[j][0] * cf : -12000.0f);
                float e01 = ex2a(((w0 >> (bp + 1)) & 1u) ? acc[j][1] * cf : -12000.0f);
                float e10 = ex2a(((w1 >> bp) & 1u)       ? acc[j][2] * cf : -12000.0f);
                float e11 = ex2a(((w1 >> (bp + 1)) & 1u) ? acc[j][3] * cf : -12000.0f);
                rs2[0] += e00 + e01;
                rs2[1] += e10 + e11;
                af[jj * 2 + 0] = cvth2(e00, e01);
                af[jj * 2 + 1] = cvth2(e10, e11);
            }
            const uint32_t va = vbase + (uint32_t)((wn * 32 + st * 16) * 2);
#pragma unroll
            for (int p = 0; p < 4; p++) {
                uint32_t vf[4];
                LDSM4(vf, va + p * (16 * 144));
                mma_h(acc2[p * 2 + 0], af, &vf[0]);
                mma_h(acc2[p * 2 + 1], af, &vf[2]);
            }
        }
        if (it + 2 < ITERS) {
            int sp = (it + 2) % 3;
            stage_k(sp, (it + 2) * TT);
            stage_v(sp, (it + 2) * TT);
            CPC();
        }
    }

#pragma unroll
    for (int i = 0; i < 2; i++) {
        rs2[i] += __shfl_xor_sync(0xffffffffu, rs2[i], 1);
        rs2[i] += __shfl_xor_sync(0xffffffffu, rs2[i], 2);
    }
    __syncthreads();
    if ((lane & 3) == 0) {
        atomicAdd(&srow[wm * 16 + (lane >> 2)],     rs2[0]);
        atomicAdd(&srow[wm * 16 + (lane >> 2) + 8], rs2[1]);
    }
    __syncthreads();

    float* red = (float*)(sm + KOFF);   // reuse k stages: 16KB needed, 27KB available
    if (wn == 1) {
#pragma unroll
        for (int je = 0; je < 8; je++) {
            int rl = wm * 16 + (lane >> 2);
            int cl = je * 8 + (lane & 3) * 2;
            *(float2*)&red[(size_t)rl * 64 + cl]       = make_float2(acc2[je][0], acc2[je][1]);
            *(float2*)&red[(size_t)(rl + 8) * 64 + cl] = make_float2(acc2[je][2], acc2[je][3]);
        }
    }
    __syncthreads();
    if (wn == 0) {
        int rl0 = wm * 16 + (lane >> 2);
        float inv0 = 1.0f / srow[rl0];
        float inv1 = 1.0f / srow[rl0 + 8];
        int rowg = s0 + rl0;
#pragma unroll
        for (int je = 0; je < 8; je++) {
            int cl = je * 8 + (lane & 3) * 2;
            float2 o0 = *(float2*)&red[(size_t)rl0 * 64 + cl];
            float2 o1 = *(float2*)&red[(size_t)(rl0 + 8) * 64 + cl];
            ((uint32_t*)O)[(((size_t)bh * S_ + rowg) * HD + cl) >> 1] =
                cvth2((acc2[je][0] + o0.x) * inv0, (acc2[je][1] + o0.y) * inv0);
            ((uint32_t*)O)[(((size_t)bh * S_ + rowg + 8) * HD + cl) >> 1] =
                cvth2((acc2[je][2] + o1.x) * inv1, (acc2[je][3] + o1.y) * inv1);
        }
    }
}

// ---------------- small utility kernels ----------------
__global__ __launch_bounds__(256)
void conv_x(const float* __restrict__ X, uint16_t* __restrict__ Xh) {
    size_t i = (size_t)blockIdx.x * 256 + threadIdx.x;
    float2 v = ((const float2*)X)[i];
    ((uint32_t*)Xh)[i] = cvth2(v.x, v.y);
}

__global__ __launch_bounds__(256)
void maskpack(const int* __restrict__ mask, uint32_t* __restrict__ mp) {
    int w = blockIdx.x * 256 + threadIdx.x;
    const int4* src = (const int4*)mask + (size_t)w * 8;
    uint32_t bits = 0;
#pragma unroll
    for (int i = 0; i < 8; i++) {
        int4 v = src[i];
        bits |= (uint32_t)(v.x == 1) << (i * 4 + 0);
        bits |= (uint32_t)(v.y == 1) << (i * 4 + 1);
        bits |= (uint32_t)(v.z == 1) << (i * 4 + 2);
        bits |= (uint32_t)(v.w == 1) << (i * 4 + 3);
    }
    mp[w] = bits;
}

__global__ __launch_bounds__(256)
void transpose_h(const float* __restrict__ Wa, const float* __restrict__ Wb,
                 const float* __restrict__ Wc, const float* __restrict__ Wd,
                 uint16_t* __restrict__ Wt) {
    __shared__ float t[32][33];
    const int z = blockIdx.z;
    const float* W = (z == 0) ? Wa : (z == 1) ? Wb : (z == 2) ? Wc : Wd;
    uint16_t* Wo = Wt + (size_t)z * DM * DM;
    const int tx = threadIdx.x & 31, ty = threadIdx.x >> 5;
    const int bx = blockIdx.x * 32, by = blockIdx.y * 32;
#pragma unroll
    for (int j = 0; j < 32; j += 8) t[ty + j][tx] = W[(size_t)(by + ty + j) * DM + bx + tx];
    __syncthreads();
#pragma unroll
    for (int j = 0; j < 32; j += 8)
        Wo[(size_t)(bx + ty + j) * DM + by + tx] = f2h(t[tx][ty + j]);
}

// ---------------- launch ----------------
extern "C" void kernel_launch(void* const* d_in, const int* in_sizes, int n_in,
                              void* d_out, int out_size) {
    (void)in_sizes; (void)n_in; (void)out_size;
    const float* x    = (const float*)d_in[0];
    const int*   mask = (const int*)d_in[1];
    const float* W0   = (const float*)d_in[2];
    const float* b0   = (const float*)d_in[3];
    const float* W1   = (const float*)d_in[4];
    const float* b1   = (const float*)d_in[5];
    const float* W2   = (const float*)d_in[6];
    const float* b2   = (const float*)d_in[7];
    const float* Wo   = (const float*)d_in[8];
    const float* bo   = (const float*)d_in[9];
    float* out = (float*)d_out;

    uint16_t *xh, *qh, *kh, *oh, *wt, *vt;
    uint32_t *mpd;
    cudaGetSymbolAddress((void**)&xh,  g_xh);
    cudaGetSymbolAddress((void**)&qh,  g_qh);
    cudaGetSymbolAddress((void**)&kh,  g_kh);
    cudaGetSymbolAddress((void**)&oh,  g_oh);
    cudaGetSymbolAddress((void**)&wt,  g_wt);
    cudaGetSymbolAddress((void**)&vt,  g_vt);
    cudaGetSymbolAddress((void**)&mpd, g_mp);
    const size_t WP = (size_t)DM * DM;

    cudaFuncSetAttribute(gemm_h<0>, cudaFuncAttributeMaxDynamicSharedMemorySize, DSMEM);
    cudaFuncSetAttribute(gemm_h<2>, cudaFuncAttributeMaxDynamicSharedMemorySize, DSMEM);
    cudaFuncSetAttribute(gemm_kv,   cudaFuncAttributeMaxDynamicSharedMemorySize, DSMEM);
    cudaFuncSetAttribute(flash_attn, cudaFuncAttributeMaxDynamicSharedMemorySize, FSMEM);

    conv_x<<<MTOT * DM / 512, 256>>>(x, xh);
    maskpack<<<(B_ * S_ * 64) / 256, 256>>>(mask, mpd);
    transpose_h<<<dim3(32, 32, 4), 256>>>(W0, W1, W2, Wo, wt);

    gemm_h<2><<<dim3(8, 32), 256, DSMEM>>>(xh, wt + 0 * WP, b0, nullptr, qh);
    gemm_kv<<<dim3(16, 32), 256, DSMEM>>>(qh, wt + 1 * WP, b1, b2, kh, vt);
    flash_attn<<<dim3(32, 32), 256, FSMEM>>>(qh, kh, vt, mpd, oh);
    gemm_h<0><<<dim3(8, 32), 256, DSMEM>>>(oh, wt + 3 * WP, bo, out, nullptr);
}

// round 14
// speedup vs baseline: 6.7941x; 1.1337x over previous
#include <cuda_runtime.h>
#include <cstdint>

#define B_       2
#define S_       2048
#define DM       1024
#define H_       16
#define HD       64
#define BH_      32
#define MTOT     4096
#define L2E      1.4426950408889634f
#define SCALE_   0.125f
#define KPH      40                  // dense fp16 smem row pad (halves) -> 80B pitch
#define KPQ2     72                  // flash q/k/v fp16 pad (halves) -> 144B pitch

// ---------------- scratch (device globals) ----------------
__device__ __align__(128) uint16_t g_xh[MTOT * DM];            // x fp16
__device__ __align__(128) uint16_t g_qh[MTOT * DM];            // q fp16
__device__ __align__(128) uint16_t g_kh[MTOT * DM];            // k fp16
__device__ __align__(128) uint16_t g_oh[MTOT * DM];            // attn out fp16 (flat)
__device__ __align__(128) uint16_t g_wt[4][DM * DM];           // W^T fp16 [n][k]; [1],[2] contiguous
__device__ __align__(128) uint16_t g_vt[BH_ * HD * S_];        // V^T fp16 per head [bh][e][t]
__device__ __align__(128) uint32_t g_mp[B_ * S_ * (S_ / 32)];  // packed mask bits, 1MB

extern __shared__ char smraw[];

// ---------------- helpers ----------------
__device__ __forceinline__ uint32_t smem_u32(const void* p) {
    uint32_t r;
    asm("{ .reg .u64 t; cvta.to.shared.u64 t, %1; cvt.u32.u64 %0, t; }" : "=r"(r) : "l"(p));
    return r;
}
__device__ __forceinline__ uint16_t f2h(float x) {
    uint16_t h; asm("cvt.rn.f16.f32 %0, %1;" : "=h"(h) : "f"(x)); return h;
}
__device__ __forceinline__ uint32_t cvth2(float lo, float hi) {  // pack {lo,hi} -> f16x2
    uint32_t r; asm("cvt.rn.f16x2.f32 %0, %1, %2;" : "=r"(r) : "f"(hi), "f"(lo)); return r;
}
__device__ __forceinline__ float ex2a(float x) {      // MUFU exp2
    float r; asm("ex2.approx.ftz.f32 %0, %1;" : "=f"(r) : "f"(x)); return r;
}
__device__ __forceinline__ void cp16(uint32_t d, const void* s) {
    asm volatile("cp.async.ca.shared.global [%0], [%1], 16;" :: "r"(d), "l"(s));
}
#define CPC()  asm volatile("cp.async.commit_group;")
#define CPW2() asm volatile("cp.async.wait_group 2;")
#define CPW1() asm volatile("cp.async.wait_group 1;")
#define CPW0() asm volatile("cp.async.wait_group 0;")

#define LDSM4(r, addr) \
    asm volatile("ldmatrix.sync.aligned.m8n8.x4.shared.b16 {%0,%1,%2,%3}, [%4];" \
                 : "=r"((r)[0]), "=r"((r)[1]), "=r"((r)[2]), "=r"((r)[3]) : "r"(addr))

__device__ __forceinline__ void mma_h(float* d, const uint32_t* a, const uint32_t* b) {
    asm volatile("mma.sync.aligned.m16n8k16.row.col.f32.f16.f16.f32 "
                 "{%0,%1,%2,%3},{%4,%5,%6,%7},{%8,%9},{%0,%1,%2,%3};"
                 : "+f"(d[0]), "+f"(d[1]), "+f"(d[2]), "+f"(d[3])
                 : "r"(a[0]), "r"(a[1]), "r"(a[2]), "r"(a[3]), "r"(b[0]), "r"(b[1]));
}

// ---------------- dense fp16 mainloop: 4 warps x (64m x 64n), k32 iters, 3-stage ------
#define DTILEH (128 * KPH * 2)         // 10240 B per 128x32 fp16 tile
#define DSTG   (2 * DTILEH)            // 20480
#define DSMEM  (3 * DSTG)              // 61440
__device__ __forceinline__ void dense_mainloop(const uint16_t* Ag, const uint16_t* Bg,
                                               int tid, int lane, int wm, int wn,
                                               float (*acc)[8][4]) {
    const uint32_t sb = smem_u32(smraw);
    auto stg = [&](int s, int k0) {
        uint32_t off = sb + (uint32_t)s * DSTG;
#pragma unroll
        for (int p = 0; p < 4; p++) {
            int id = tid + p * 128;
            int r = id >> 2, c = (id & 3) * 8;       // 8 halves = 16B
            cp16(off + (uint32_t)(r * KPH + c) * 2u, Ag + (size_t)r * DM + k0 + c);
            cp16(off + DTILEH + (uint32_t)(r * KPH + c) * 2u, Bg + (size_t)r * DM + k0 + c);
        }
    };
    stg(0, 0);  CPC();
    stg(1, 32); CPC();

    // ldsm lane bases (bytes; pitch 80B). A: row sel bit3, col sel bit4. B: row sel bit4, col sel bit3.
    const uint32_t la = (uint32_t)((wm * 64 + ((lane >> 3) & 1) * 8 + (lane & 7)) * 80
                                   + ((lane >> 4) & 1) * 16);
    const uint32_t lb = (uint32_t)(DTILEH
                                   + (wn * 64 + ((lane >> 4) & 1) * 8 + (lane & 7)) * 80
                                   + ((lane >> 3) & 1) * 16);
    const int NT = DM / 32;   // 32
    for (int i = 0; i < NT; i++) {
        int s = i % 3;
        if (i >= NT - 2) { CPW0(); } else { CPW1(); }
        __syncthreads();
        const uint32_t abase = sb + (uint32_t)s * DSTG + la;
        const uint32_t bbase = sb + (uint32_t)s * DSTG + lb;
#pragma unroll
        for (int kh = 0; kh < 2; kh++) {            // 2 x k16 per k32 iter
            uint32_t bf[4][4];
#pragma unroll
            for (int jj = 0; jj < 4; jj++) LDSM4(bf[jj], bbase + kh * 32 + jj * (16 * 80));
#pragma unroll
            for (int ii = 0; ii < 4; ii++) {
                uint32_t af[4];
                LDSM4(af, abase + kh * 32 + ii * (16 * 80));
#pragma unroll
                for (int j = 0; j < 8; j++)
                    mma_h(acc[ii][j], af, &bf[j >> 1][(j & 1) * 2]);
            }
        }
        if (i + 2 < NT) { stg((i + 2) % 3, (i + 2) * 32); CPC(); }
    }
}

// MODE 0: fp32 C (final).  MODE 2: fp16 Ch (q / k inputs to attention).
template<int MODE>
__global__ __launch_bounds__(128, 2)
void gemm_h(const uint16_t* __restrict__ A, const uint16_t* __restrict__ Bt,
            const float* __restrict__ bias, float* __restrict__ C,
            uint16_t* __restrict__ Ch) {
    const int tid = threadIdx.x, lane = tid & 31, wid = tid >> 5;
    const int wm = wid & 1, wn = wid >> 1;
    const int m0 = blockIdx.y * 128, n0 = blockIdx.x * 128;
    float acc[4][8][4];
#pragma unroll
    for (int i = 0; i < 4; i++)
#pragma unroll
        for (int j = 0; j < 8; j++)
#pragma unroll
            for (int e = 0; e < 4; e++) acc[i][j][e] = 0.0f;
    dense_mainloop(A + (size_t)m0 * DM, Bt + (size_t)n0 * DM, tid, lane, wm, wn, acc);
#pragma unroll
    for (int i = 0; i < 4; i++)
#pragma unroll
        for (int j = 0; j < 8; j++) {
            int m = m0 + wm * 64 + i * 16 + (lane >> 2);
            int n = n0 + wn * 64 + j * 8 + (lane & 3) * 2;
            float bz0 = bias[n], bz1 = bias[n + 1];
            float v00 = fmaxf(acc[i][j][0] + bz0, 0.0f), v01 = fmaxf(acc[i][j][1] + bz1, 0.0f);
            float v10 = fmaxf(acc[i][j][2] + bz0, 0.0f), v11 = fmaxf(acc[i][j][3] + bz1, 0.0f);
            if (MODE == 0) {
                *(float2*)&C[(size_t)m * DM + n]       = make_float2(v00, v01);
                *(float2*)&C[(size_t)(m + 8) * DM + n] = make_float2(v10, v11);
            } else {
                ((uint32_t*)Ch)[((size_t)m * DM + n) >> 1]       = cvth2(v00, v01);
                ((uint32_t*)Ch)[((size_t)(m + 8) * DM + n) >> 1] = cvth2(v10, v11);
            }
        }
}

// merged K+V GEMM: B = [W1^T ; W2^T] (2048 rows), n<1024 -> kh (fp16), n>=1024 -> vt (fp16 per head)
__global__ __launch_bounds__(128, 2)
void gemm_kv(const uint16_t* __restrict__ A, const uint16_t* __restrict__ Bt,
             const float* __restrict__ b1, const float* __restrict__ b2,
             uint16_t* __restrict__ K, uint16_t* __restrict__ VT) {
    const int tid = threadIdx.x, lane = tid & 31, wid = tid >> 5;
    const int wm = wid & 1, wn = wid >> 1;
    const int m0 = blockIdx.y * 128, n0 = blockIdx.x * 128;   // n0 in [0,2048)
    float acc[4][8][4];
#pragma unroll
    for (int i = 0; i < 4; i++)
#pragma unroll
        for (int j = 0; j < 8; j++)
#pragma unroll
            for (int e = 0; e < 4; e++) acc[i][j][e] = 0.0f;
    dense_mainloop(A + (size_t)m0 * DM, Bt + (size_t)n0 * DM, tid, lane, wm, wn, acc);
    const bool isK = (n0 < DM);
    const float* bias = isK ? b1 : b2;
    const int nb = isK ? n0 : (n0 - DM);
#pragma unroll
    for (int i = 0; i < 4; i++)
#pragma unroll
        for (int j = 0; j < 8; j++) {
            int m = m0 + wm * 64 + i * 16 + (lane >> 2);
            int n = nb + wn * 64 + j * 8 + (lane & 3) * 2;
            float bz0 = bias[n], bz1 = bias[n + 1];
            float v00 = fmaxf(acc[i][j][0] + bz0, 0.0f), v01 = fmaxf(acc[i][j][1] + bz1, 0.0f);
            float v10 = fmaxf(acc[i][j][2] + bz0, 0.0f), v11 = fmaxf(acc[i][j][3] + bz1, 0.0f);
            if (isK) {
                ((uint32_t*)K)[((size_t)m * DM + n) >> 1]       = cvth2(v00, v01);
                ((uint32_t*)K)[((size_t)(m + 8) * DM + n) >> 1] = cvth2(v10, v11);
            } else {
                int bb = m >> 11, t = m & 2047, hh = n >> 6, e = n & 63;
                size_t base = ((size_t)(bb * 16 + hh) * 64 + e) * S_;
                VT[base + t]          = f2h(v00);
                VT[base + S_ + t]     = f2h(v01);
                VT[base + t + 8]      = f2h(v10);
                VT[base + S_ + t + 8] = f2h(v11);
            }
        }
}

// ---------------- fused flash attention: 128-row s-tile, 4 warps x (32m x 64t) ----------
// smem: q[128][72]h | k x3 [64][72]h | v x3 [64][72]h
#define QSZ    (128 * KPQ2 * 2)        // 18432
#define KST    (64 * KPQ2 * 2)         // 9216
#define KOFF   QSZ                     // 18432
#define VOFF   (KOFF + 3 * KST)        // 46080
#define FSMEM  (VOFF + 3 * KST)        // 73728
#define TT     64
#define ITERS  (S_ / TT)   // 32
__global__ __launch_bounds__(128, 2)
void flash_attn(const uint16_t* __restrict__ q, const uint16_t* __restrict__ k,
                const uint16_t* __restrict__ vtb, const uint32_t* __restrict__ mp,
                uint16_t* __restrict__ O) {
    char* sm = smraw;
    const int tid = threadIdx.x, lane = tid & 31, wm = tid >> 5;   // 4 warps, 32 m-rows each
    const int bh = blockIdx.y, b = bh >> 4, h = bh & 15;
    const int s0 = blockIdx.x * 128;
    const uint32_t sb = smem_u32(sm);

    const uint16_t* qg = q + ((size_t)b * S_ + s0) * DM + h * HD;
    const uint16_t* kg = k + (size_t)b * S_ * DM + h * HD;
    const uint16_t* vg = vtb + (size_t)bh * HD * S_;

#pragma unroll
    for (int p = 0; p < 8; p++) {        // q: 128 rows x 8 chunks
        int id = tid + p * 128, r = id >> 3, c = (id & 7) * 8;
        cp16(sb + (uint32_t)(r * KPQ2 + c) * 2u, qg + (size_t)r * DM + c);
    }
    CPC();
    auto stage_k = [&](int s, int t0) {
        const uint16_t* src = kg + (size_t)t0 * DM;
        uint32_t koff = KOFF + (uint32_t)s * KST;
#pragma unroll
        for (int p = 0; p < 4; p++) {
            int id = tid + p * 128, r = id >> 3, c = (id & 7) * 8;
            cp16(sb + koff + (uint32_t)(r * KPQ2 + c) * 2u, src + (size_t)r * DM + c);
        }
    };
    auto stage_v = [&](int s, int t0) {
        uint32_t voff = VOFF + (uint32_t)s * KST;
#pragma unroll
        for (int p = 0; p < 4; p++) {
            int id = tid + p * 128, e = id >> 3, c = (id & 7) * 8;
            cp16(sb + voff + (uint32_t)(e * KPQ2 + c) * 2u, vg + (size_t)e * S_ + t0 + c);
        }
    };
    stage_k(0, 0);  stage_v(0, 0);  CPC();
    stage_k(1, TT); stage_v(1, TT); CPC();

    const int bpl = (lane & 3) * 2;

    CPW2();             // q group complete
    __syncthreads();
    // hoist Q A-fragments: 2 m16 tiles x 4 k16 chunks (ldsm; row sel bit3, col sel bit4)
    uint32_t Qf[2][4][4];
#pragma unroll
    for (int im = 0; im < 2; im++) {
        uint32_t qb = sb + (uint32_t)((wm * 32 + im * 16 + ((lane >> 3) & 1) * 8 + (lane & 7)) * 144
                                      + ((lane >> 4) & 1) * 16);
#pragma unroll
        for (int kc = 0; kc < 4; kc++) LDSM4(Qf[im][kc], qb + kc * 32);
    }

    float acc2[2][8][4];
#pragma unroll
    for (int im = 0; im < 2; im++)
#pragma unroll
        for (int j = 0; j < 8; j++)
#pragma unroll
            for (int e = 0; e < 4; e++) acc2[im][j][e] = 0.0f;
    float rs[2][2] = {{0.f, 0.f}, {0.f, 0.f}};

    const float cf = SCALE_ * L2E;
    const uint32_t* mpr[2];
#pragma unroll
    for (int im = 0; im < 2; im++) {
        int row = s0 + wm * 32 + im * 16 + (lane >> 2);
        mpr[im] = mp + ((size_t)(b * S_ + row) << 6);
    }
    // K/V B-fragment lane base (row sel bit4, col sel bit3); pitch 144B
    const uint32_t lkv = (uint32_t)((((lane >> 4) & 1) * 8 + (lane & 7)) * 144
                                    + ((lane >> 3) & 1) * 16);

    for (int it = 0; it < ITERS; it++) {
        const int s = it % 3;
        if (it >= ITERS - 2) { CPW0(); } else { CPW1(); }
        __syncthreads();
        const uint32_t kbase = sb + KOFF + (uint32_t)s * KST + lkv;
        const uint32_t vbase = sb + VOFF + (uint32_t)s * KST + lkv;

        float acc[2][8][4];
#pragma unroll
        for (int im = 0; im < 2; im++)
#pragma unroll
            for (int j = 0; j < 8; j++)
#pragma unroll
                for (int e = 0; e < 4; e++) acc[im][j][e] = 0.0f;
#pragma unroll
        for (int kc = 0; kc < 4; kc++) {             // 4 x k16 over head dim
            uint32_t kf[4][4];
#pragma unroll
            for (int tg = 0; tg < 4; tg++) LDSM4(kf[tg], kbase + kc * 32 + tg * (16 * 144));
#pragma unroll
            for (int im = 0; im < 2; im++)
#pragma unroll
                for (int j = 0; j < 8; j++)
                    mma_h(acc[im][j], Qf[im][kc], &kf[j >> 1][(j & 1) * 2]);
        }

        uint32_t w[2][2], w8[2][2];
#pragma unroll
        for (int im = 0; im < 2; im++) {
            w[im][0]  = mpr[im][it * 2];       w[im][1]  = mpr[im][it * 2 + 1];
            w8[im][0] = mpr[im][512 + it * 2]; w8[im][1] = mpr[im][512 + it * 2 + 1];
        }
#pragma unroll
        for (int st = 0; st < 4; st++) {
            uint32_t af[2][4];
#pragma unroll
            for (int im = 0; im < 2; im++)
#pragma unroll
                for (int jj = 0; jj < 2; jj++) {
                    const int j = st * 2 + jj;
                    const int bp = (j * 8) & 31;
                    const int wsel = (j >> 2);
                    const uint32_t wl = w[im][wsel], wh = w8[im][wsel];
                    float e00 = ex2a(((wl >> (bp + bpl)) & 1u)     ? acc[im][j][0] * cf : -12000.0f);
                    float e01 = ex2a(((wl >> (bp + bpl + 1)) & 1u) ? acc[im][j][1] * cf : -12000.0f);
                    float e10 = ex2a(((wh >> (bp + bpl)) & 1u)     ? acc[im][j][2] * cf : -12000.0f);
                    float e11 = ex2a(((wh >> (bp + bpl + 1)) & 1u) ? acc[im][j][3] * cf : -12000.0f);
                    rs[im][0] += e00 + e01;
                    rs[im][1] += e10 + e11;
                    af[im][jj * 2 + 0] = cvth2(e00, e01);
                    af[im][jj * 2 + 1] = cvth2(e10, e11);
                }
            uint32_t vf[4][4];
#pragma unroll
            for (int eg = 0; eg < 4; eg++) LDSM4(vf[eg], vbase + st * 32 + eg * (16 * 144));
#pragma unroll
            for (int im = 0; im < 2; im++)
#pragma unroll
                for (int eg = 0; eg < 4; eg++) {
                    mma_h(acc2[im][eg * 2 + 0], af[im], &vf[eg][0]);
                    mma_h(acc2[im][eg * 2 + 1], af[im], &vf[eg][2]);
                }
        }
        if (it + 2 < ITERS) {
            int sp = (it + 2) % 3;
            stage_k(sp, (it + 2) * TT);
            stage_v(sp, (it + 2) * TT);
            CPC();
        }
    }

    // row sums: quad shuffle (lanes in a quad share the same row)
#pragma unroll
    for (int im = 0; im < 2; im++)
#pragma unroll
        for (int r = 0; r < 2; r++) {
            rs[im][r] += __shfl_xor_sync(0xffffffffu, rs[im][r], 1);
            rs[im][r] += __shfl_xor_sync(0xffffffffu, rs[im][r], 2);
        }

    // epilogue: each warp owns its rows fully -> direct write, no smem
#pragma unroll
    for (int im = 0; im < 2; im++) {
        int row = s0 + wm * 32 + im * 16 + (lane >> 2);
        float inv0 = 1.0f / rs[im][0];
        float inv1 = 1.0f / rs[im][1];
#pragma unroll
        for (int je = 0; je < 8; je++) {
            int cl = je * 8 + (lane & 3) * 2;
            ((uint32_t*)O)[(((size_t)bh * S_ + row) * HD + cl) >> 1] =
                cvth2(acc2[im][je][0] * inv0, acc2[im][je][1] * inv0);
            ((uint32_t*)O)[(((size_t)bh * S_ + row + 8) * HD + cl) >> 1] =
                cvth2(acc2[im][je][2] * inv1, acc2[im][je][3] * inv1);
        }
    }
}

// ---------------- small utility kernels ----------------
__global__ __launch_bounds__(256)
void conv_x(const float* __restrict__ X, uint16_t* __restrict__ Xh) {
    size_t i = (size_t)blockIdx.x * 256 + threadIdx.x;
    float2 v = ((const float2*)X)[i];
    ((uint32_t*)Xh)[i] = cvth2(v.x, v.y);
}

__global__ __launch_bounds__(256)
void maskpack(const int* __restrict__ mask, uint32_t* __restrict__ mp) {
    int w = blockIdx.x * 256 + threadIdx.x;
    const int4* src = (const int4*)mask + (size_t)w * 8;
    uint32_t bits = 0;
#pragma unroll
    for (int i = 0; i < 8; i++) {
        int4 v = src[i];
        bits |= (uint32_t)(v.x == 1) << (i * 4 + 0);
        bits |= (uint32_t)(v.y == 1) << (i * 4 + 1);
        bits |= (uint32_t)(v.z == 1) << (i * 4 + 2);
        bits |= (uint32_t)(v.w == 1) << (i * 4 + 3);
    }
    mp[w] = bits;
}

__global__ __launch_bounds__(256)
void transpose_h(const float* __restrict__ Wa, const float* __restrict__ Wb,
                 const float* __restrict__ Wc, const float* __restrict__ Wd,
                 uint16_t* __restrict__ Wt) {
    __shared__ float t[32][33];
    const int z = blockIdx.z;
    const float* W = (z == 0) ? Wa : (z == 1) ? Wb : (z == 2) ? Wc : Wd;
    uint16_t* Wo = Wt + (size_t)z * DM * DM;
    const int tx = threadIdx.x & 31, ty = threadIdx.x >> 5;
    const int bx = blockIdx.x * 32, by = blockIdx.y * 32;
#pragma unroll
    for (int j = 0; j < 32; j += 8) t[ty + j][tx] = W[(size_t)(by + ty + j) * DM + bx + tx];
    __syncthreads();
#pragma unroll
    for (int j = 0; j < 32; j += 8)
        Wo[(size_t)(bx + ty + j) * DM + by + tx] = f2h(t[tx][ty + j]);
}

// ---------------- launch ----------------
extern "C" void kernel_launch(void* const* d_in, const int* in_sizes, int n_in,
                              void* d_out, int out_size) {
    (void)in_sizes; (void)n_in; (void)out_size;
    const float* x    = (const float*)d_in[0];
    const int*   mask = (const int*)d_in[1];
    const float* W0   = (const float*)d_in[2];
    const float* b0   = (const float*)d_in[3];
    const float* W1   = (const float*)d_in[4];
    const float* b1   = (const float*)d_in[5];
    const float* W2   = (const float*)d_in[6];
    const float* b2   = (const float*)d_in[7];
    const float* Wo   = (const float*)d_in[8];
    const float* bo   = (const float*)d_in[9];
    float* out = (float*)d_out;

    uint16_t *xh, *qh, *kh, *oh, *wt, *vt;
    uint32_t *mpd;
    cudaGetSymbolAddress((void**)&xh,  g_xh);
    cudaGetSymbolAddress((void**)&qh,  g_qh);
    cudaGetSymbolAddress((void**)&kh,  g_kh);
    cudaGetSymbolAddress((void**)&oh,  g_oh);
    cudaGetSymbolAddress((void**)&wt,  g_wt);
    cudaGetSymbolAddress((void**)&vt,  g_vt);
    cudaGetSymbolAddress((void**)&mpd, g_mp);
    const size_t WP = (size_t)DM * DM;

    cudaFuncSetAttribute(gemm_h<0>, cudaFuncAttributeMaxDynamicSharedMemorySize, DSMEM);
    cudaFuncSetAttribute(gemm_h<2>, cudaFuncAttributeMaxDynamicSharedMemorySize, DSMEM);
    cudaFuncSetAttribute(gemm_kv,   cudaFuncAttributeMaxDynamicSharedMemorySize, DSMEM);
    cudaFuncSetAttribute(flash_attn, cudaFuncAttributeMaxDynamicSharedMemorySize, FSMEM);

    conv_x<<<MTOT * DM / 512, 256>>>(x, xh);
    maskpack<<<(B_ * S_ * 64) / 256, 256>>>(mask, mpd);
    transpose_h<<<dim3(32, 32, 4), 256>>>(W0, W1, W2, Wo, wt);

    gemm_h<2><<<dim3(8, 32), 128, DSMEM>>>(xh, wt + 0 * WP, b0, nullptr, qh);
    gemm_kv<<<dim3(16, 32), 128, DSMEM>>>(qh, wt + 1 * WP, b1, b2, kh, vt);
    flash_attn<<<dim3(16, 32), 128, FSMEM>>>(qh, kh, vt, mpd, oh);
    gemm_h<0><<<dim3(8, 32), 128, DSMEM>>>(oh, wt + 3 * WP, bo, out, nullptr);
}